// round 10
// baseline (speedup 1.0000x reference)
#include <cuda_runtime.h>

namespace {

constexpr int NN  = 50000;   // nodes
constexpr int NE  = 800000;  // edges
constexpr int KIN = 256;     // in_dim
constexpr int NB  = (NN + 1023) / 1024;  // scan blocks = 49

// ---------------- scratch (static device memory; no allocations) ----------------
__device__ float g_xr[NN * 256];     // tf32-rounded x
__device__ float g_win[256 * 128];   // tf32-rounded W_in
__device__ float g_w1p[128 * 128];   // tf32-rounded diag(sc1)*W1
__device__ float g_w2[128 * 128];    // tf32-rounded W2
__device__ float g_wskip[128 * 128]; // tf32-rounded W_skip
__device__ float g_t1bias[128];      // sh1^T @ W1
__device__ float g_h1[NN * 128];     // leaky(x@W_in+b_in), tf32-rounded
__device__ float g_t1[NN * 128];     // BN1(h1) @ W1
__device__ float g_skip[NN * 128];   // leaky(gat1 + bias1), tf32-rounded
__device__ float g_t2[NN * 128];     // skip @ W2
__device__ float g_out2[NN * 128];   // gat2 + bias2
__device__ float g_as1[NN * 8];
__device__ float g_ad1[NN * 8];
__device__ float g_as2[NN];
__device__ float g_ad2[NN];
__device__ int   g_src[NE];
__device__ int   g_dst[NE];
__device__ int   g_sby[NE];          // src ids sorted by dst (CSR order)
__device__ int   g_deg[NN];
__device__ int   g_cur[NN];
__device__ int   g_rs[NN + 1];       // CSR row starts (disjoint regions)
__device__ int   g_ctr;
__device__ float g_stats1[256];
__device__ float g_stats2[256];
__device__ float g_sc2[128], g_sh2[128];
__device__ int   g_is64;

__device__ __forceinline__ float lrelu(float v) { return v >= 0.f ? v : 0.2f * v; }

__device__ __forceinline__ float tf32r(float f) {
  unsigned u;
  asm("cvt.rna.tf32.f32 %0, %1;" : "=r"(u) : "f"(f));
  return __uint_as_float(u);
}
__device__ __forceinline__ float4 tf32r4(float4 v) {
  return make_float4(tf32r(v.x), tf32r(v.y), tf32r(v.z), tf32r(v.w));
}

// ---------------- setup: zero + dtype detect ----------------
__global__ void k_zero(const void* __restrict__ ei) {
  int i = blockIdx.x * 256 + threadIdx.x;
  if (i < NN) { g_deg[i] = 0; g_cur[i] = 0; }
  if (i < 256) { g_stats1[i] = 0.f; g_stats2[i] = 0.f; }
  if (blockIdx.x == 0 && threadIdx.x == 0) {
    g_ctr = 0;
    const long long* p = (const long long*)ei;
    int ok = 1;
    for (int j = 0; j < 64; j++) {
      long long v = p[j];
      if (v < 0 || v >= NN) { ok = 0; break; }
    }
    g_is64 = ok;
  }
}

__global__ void k_edges(const void* __restrict__ ei) {
  int i = blockIdx.x * 256 + threadIdx.x;
  if (i < NE) {
    int s, d;
    if (g_is64) {
      const long long* p = (const long long*)ei;
      s = (int)p[i];
      d = (int)p[NE + i];
    } else {
      const int* p = (const int*)ei;
      s = p[i];
      d = p[NE + i];
    }
    if ((unsigned)s >= NN) s = 0;
    if ((unsigned)d >= NN) d = 0;
    g_src[i] = s;
    g_dst[i] = d;
    atomicAdd(&g_deg[d], 1);
  }
}

__global__ void k_scan() {
  int t = threadIdx.x;
  int i = blockIdx.x * 1024 + t;
  int v = (i < NN) ? g_deg[i] : 0;
  __shared__ int sb[1024];
  __shared__ int sbase;
  sb[t] = v;
  __syncthreads();
  for (int o = 1; o < 1024; o <<= 1) {
    int x = (t >= o) ? sb[t - o] : 0;
    __syncthreads();
    sb[t] += x;
    __syncthreads();
  }
  if (t == 1023) sbase = atomicAdd(&g_ctr, sb[1023]);
  __syncthreads();
  if (i < NN) g_rs[i] = sbase + sb[t] - v;
}

__global__ void k_scatter() {
  int i = blockIdx.x * 256 + threadIdx.x;
  if (i < NE) {
    int d = g_dst[i];
    int p = atomicAdd(&g_cur[d], 1);
    g_sby[g_rs[d] + p] = g_src[i];
  }
}

// ---------------- pre-round all GEMM operands to tf32 ----------------
__global__ __launch_bounds__(256) void k_roundall(const float* __restrict__ x,
                                                  const float* __restrict__ W_in,
                                                  const float* __restrict__ W2,
                                                  const float* __restrict__ Wsk) {
  int i = blockIdx.x * 256 + threadIdx.x;   // float4 index
  if (i < NN * 64)
    *(float4*)(g_xr + i * 4) = tf32r4(*(const float4*)(x + i * 4));
  if (i < 8192)
    *(float4*)(g_win + i * 4) = tf32r4(*(const float4*)(W_in + i * 4));
  if (i < 4096) {
    *(float4*)(g_w2 + i * 4)    = tf32r4(*(const float4*)(W2 + i * 4));
    *(float4*)(g_wskip + i * 4) = tf32r4(*(const float4*)(Wsk + i * 4));
  }
}

// ---------------- TF32 tensor-core GEMM, cp.async double-buffered ----------------
constexpr int M_LEAKY = 2, M_ADDC = 4, M_BIAS = 16, M_CVT = 32, M_TB = 64;
constexpr int ASZ = 128 * 36;    // floats per A stage
constexpr int WSZ = 32 * 136;    // floats per W stage
constexpr int TSZ = ASZ + WSZ;   // 8448 floats = 33792 B per stage
constexpr int GEMM_SMEM = TSZ * 2 * 4;  // 67584 B

__device__ __forceinline__ void mma_tf32(float4& c, const unsigned a[4], const unsigned b[2]) {
  asm volatile(
      "mma.sync.aligned.m16n8k8.row.col.f32.tf32.tf32.f32 "
      "{%0,%1,%2,%3}, {%4,%5,%6,%7}, {%8,%9}, {%0,%1,%2,%3};"
      : "+f"(c.x), "+f"(c.y), "+f"(c.z), "+f"(c.w)
      : "r"(a[0]), "r"(a[1]), "r"(a[2]), "r"(a[3]), "r"(b[0]), "r"(b[1]));
}

// SEL: 0 -> A=g_xr  (K=256), out=g_h1 (bias+leaky+cvt)
//      1 -> A=g_h1,  W=g_w1p, out=g_t1 (+t1bias)
//      2 -> A=g_skip,W=g_w2,  out=g_t2
//      3 -> A=g_skip,W=g_wskip,out=outp (bias + addC)
template <int K, int MODE, int SEL>
__global__ __launch_bounds__(256, 2) void k_gemm_tc(const float* __restrict__ bias,
                                                    float* __restrict__ outp) {
  extern __shared__ float sm[];
  const float* A  = (SEL == 0) ? g_xr : (SEL == 1) ? g_h1 : g_skip;
  const float* Wm = (SEL == 0) ? g_win : (SEL == 1) ? g_w1p : (SEL == 2) ? g_w2 : g_wskip;
  float* out      = (SEL == 0) ? g_h1 : (SEL == 1) ? g_t1 : (SEL == 2) ? g_t2 : outp;

  int tid = threadIdx.x;
  int lane = tid & 31, wid = tid >> 5;
  int gr = lane >> 2, gc = lane & 3;
  int warp_m = wid & 3, warp_n = wid >> 2;
  int row0 = blockIdx.x * 128;

  float4 acc[2][8];
#pragma unroll
  for (int mt = 0; mt < 2; mt++)
#pragma unroll
    for (int nt = 0; nt < 8; nt++) acc[mt][nt] = make_float4(0.f, 0.f, 0.f, 0.f);

  auto issue = [&](int kc, int buf) {
    float* As = sm + buf * TSZ;
    float* Ws = As + ASZ;
#pragma unroll
    for (int i = 0; i < 4; i++) {
      int idx = tid * 4 + i * 1024;
      int r = idx >> 5, c = idx & 31;
      int grow = row0 + r;
      int ok = (grow < NN);
      const float* src = A + (size_t)(ok ? grow : 0) * K + kc + c;
      unsigned dst = (unsigned)__cvta_generic_to_shared(As + r * 36 + c);
      int sz = ok ? 16 : 0;
      asm volatile("cp.async.cg.shared.global [%0], [%1], 16, %2;"
                   :: "r"(dst), "l"(src), "r"(sz));
    }
#pragma unroll
    for (int i = 0; i < 4; i++) {
      int idx = tid * 4 + i * 1024;
      int k = idx >> 7, n = idx & 127;
      const float* src = Wm + (size_t)(kc + k) * 128 + n;
      unsigned dst = (unsigned)__cvta_generic_to_shared(Ws + k * 136 + n);
      asm volatile("cp.async.cg.shared.global [%0], [%1], 16;"
                   :: "r"(dst), "l"(src));
    }
    asm volatile("cp.async.commit_group;");
  };

  issue(0, 0);
  constexpr int NCH = K / 32;
  for (int ch = 0; ch < NCH; ch++) {
    asm volatile("cp.async.wait_group 0;" ::: "memory");
    __syncthreads();
    if (ch + 1 < NCH) issue((ch + 1) * 32, (ch + 1) & 1);

    const float* As = sm + (ch & 1) * TSZ;
    const float* Ws = As + ASZ;
#pragma unroll
    for (int kk = 0; kk < 32; kk += 8) {
      unsigned a[2][4];
#pragma unroll
      for (int mt = 0; mt < 2; mt++) {
        int rb = warp_m * 32 + mt * 16;
        a[mt][0] = __float_as_uint(As[(rb + gr)     * 36 + kk + gc]);
        a[mt][1] = __float_as_uint(As[(rb + gr + 8) * 36 + kk + gc]);
        a[mt][2] = __float_as_uint(As[(rb + gr)     * 36 + kk + gc + 4]);
        a[mt][3] = __float_as_uint(As[(rb + gr + 8) * 36 + kk + gc + 4]);
      }
      unsigned b[8][2];
#pragma unroll
      for (int nt = 0; nt < 8; nt++) {
        int n = warp_n * 64 + nt * 8 + gr;
        b[nt][0] = __float_as_uint(Ws[(kk + gc)     * 136 + n]);
        b[nt][1] = __float_as_uint(Ws[(kk + gc + 4) * 136 + n]);
      }
#pragma unroll
      for (int mt = 0; mt < 2; mt++)
#pragma unroll
        for (int nt = 0; nt < 8; nt++) mma_tf32(acc[mt][nt], a[mt], b[nt]);
    }
    __syncthreads();
  }

#pragma unroll
  for (int nt = 0; nt < 8; nt++) {
    int col = warp_n * 64 + nt * 8 + gc * 2;
    float2 bv = make_float2(0.f, 0.f);
    if (MODE & M_BIAS) bv = *(const float2*)(bias + col);
    if (MODE & M_TB)   bv = *(const float2*)(g_t1bias + col);
#pragma unroll
    for (int mt = 0; mt < 2; mt++) {
      int r0 = row0 + warp_m * 32 + mt * 16 + gr;
#pragma unroll
      for (int hh = 0; hh < 2; hh++) {
        int r = r0 + hh * 8;
        if (r < NN) {
          float2 v = hh ? make_float2(acc[mt][nt].z, acc[mt][nt].w)
                        : make_float2(acc[mt][nt].x, acc[mt][nt].y);
          if (MODE & (M_BIAS | M_TB)) { v.x += bv.x; v.y += bv.y; }
          if (MODE & M_ADDC) {
            float2 cv = *(const float2*)(g_out2 + (size_t)r * 128 + col);
            v.x += cv.x; v.y += cv.y;
          }
          if (MODE & M_LEAKY) { v.x = lrelu(v.x); v.y = lrelu(v.y); }
          if (MODE & M_CVT)   { v.x = tf32r(v.x); v.y = tf32r(v.y); }
          *(float2*)(out + (size_t)r * 128 + col) = v;
        }
      }
    }
  }
}

// ---------------- column stats (sum, sumsq) for BN ----------------
template <int L>
__global__ __launch_bounds__(256) void k_colstats(const float* __restrict__ srcp) {
  const float* src = (L == 1) ? g_h1 : srcp;
  int col = threadIdx.x & 127;
  int half = threadIdx.x >> 7;
  float s = 0.f, q = 0.f;
  for (int i = 0; i < 256; i++) {
    int r = blockIdx.x * 512 + i * 2 + half;
    if (r < NN) {
      float v = src[(size_t)r * 128 + col];
      s += v;
      q += v * v;
    }
  }
  __shared__ float red[512];
  red[threadIdx.x] = s;
  red[256 + threadIdx.x] = q;
  __syncthreads();
  float* stats = (L == 1) ? g_stats1 : g_stats2;
  if (threadIdx.x < 128) {
    atomicAdd(&stats[threadIdx.x], red[threadIdx.x] + red[threadIdx.x + 128]);
    atomicAdd(&stats[128 + threadIdx.x], red[256 + threadIdx.x] + red[384 + threadIdx.x]);
  }
}

// ---------------- BN1 finalize + fold into W1: W1'=sc*W1, t1bias=sh^T W1 ----------------
__global__ __launch_bounds__(128) void k_bnprep(const float* __restrict__ gamma,
                                                const float* __restrict__ beta,
                                                const float* __restrict__ W1) {
  __shared__ float ssc[128], ssh[128];
  int t = threadIdx.x;
  float mean = g_stats1[t] * (1.f / NN);
  float var = g_stats1[128 + t] * (1.f / NN) - mean * mean;
  float sc = rsqrtf(var + 1e-5f) * gamma[t];
  float sh = beta[t] - mean * sc;
  ssc[t] = sc; ssh[t] = sh;
  __syncthreads();
  float tb = 0.f;
  for (int k = 0; k < 128; k++) {
    float w = W1[k * 128 + t];
    g_w1p[k * 128 + t] = tf32r(ssc[k] * w);
    tb = fmaf(ssh[k], w, tb);
  }
  g_t1bias[t] = tb;
}

// ---------------- BN2 finalize ----------------
__global__ void k_bnfin2(const float* __restrict__ gamma, const float* __restrict__ beta) {
  int i = threadIdx.x;
  float mean = g_stats2[i] * (1.f / NN);
  float var = g_stats2[128 + i] * (1.f / NN) - mean * mean;
  float sc = rsqrtf(var + 1e-5f) * gamma[i];
  g_sc2[i] = sc;
  g_sh2[i] = beta[i] - mean * sc;
}

// ---------------- attention per-node dot products ----------------
template <int H>
__global__ __launch_bounds__(256) void k_att(const float* __restrict__ avs,
                                             const float* __restrict__ avd) {
  int tid = threadIdx.x;
  int node = blockIdx.x * 2 + (tid >> 7);
  int j = tid & 127;
  const float* t = (H == 8) ? g_t1 : g_t2;
  float tv = t[(size_t)node * 128 + j];
  float ps = tv * avs[j];
  float pd = tv * avd[j];
#pragma unroll
  for (int o = 8; o; o >>= 1) {
    ps += __shfl_xor_sync(0xffffffffu, ps, o);
    pd += __shfl_xor_sync(0xffffffffu, pd, o);
  }
  if (H == 8) {
    if ((j & 15) == 0) {
      g_as1[node * 8 + (j >> 4)] = ps;
      g_ad1[node * 8 + (j >> 4)] = pd;
    }
  } else {
    __shared__ float sb[2][8][2];
    if ((j & 15) == 0) { sb[tid >> 7][j >> 4][0] = ps; sb[tid >> 7][j >> 4][1] = pd; }
    __syncthreads();
    if (j == 0) {
      float a = 0.f, b = 0.f;
#pragma unroll
      for (int s = 0; s < 8; s++) { a += sb[tid >> 7][s][0]; b += sb[tid >> 7][s][1]; }
      g_as2[node] = a;
      g_ad2[node] = b;
    }
  }
}

template <int H>
__device__ __forceinline__ void load_as(float* dst, const float* __restrict__ p, int s) {
  if constexpr (H == 8) {
    float4 a = __ldg((const float4*)(p + (size_t)s * 8));
    float4 b = __ldg((const float4*)(p + (size_t)s * 8 + 4));
    dst[0] = a.x; dst[1] = a.y; dst[2] = a.z; dst[3] = a.w;
    dst[4] = b.x; dst[5] = b.y; dst[6] = b.z; dst[7] = b.w;
  } else {
    dst[0] = __ldg(p + s);
  }
}

// ---------------- GAT aggregation: WARP per node, online softmax ----------------
// CVT: round output to tf32 (when it feeds later GEMMs)
template <int H, bool LK, bool CVT>
__global__ __launch_bounds__(256) void k_gat(const float* __restrict__ bias) {
  const float* t   = (H == 8) ? g_t1  : g_t2;
  const float* asv = (H == 8) ? g_as1 : g_as2;
  const float* adv = (H == 8) ? g_ad1 : g_ad2;
  float* out       = (H == 8) ? g_skip : g_out2;

  int lane = threadIdx.x & 31, warp = threadIdx.x >> 5;
  int node = blockIdx.x * 8 + warp;
  if (node >= NN) return;
  int beg = g_rs[node];
  int cnt = g_deg[node];
  int myh = (H == 8) ? (lane >> 2) : 0;

  __shared__ float salpha[8][H * 33];

  float ad[H];
  load_as<H>(ad, adv, node);

  float m[H], den[H];
#pragma unroll
  for (int h = 0; h < H; h++) { m[h] = -1e30f; den[h] = 0.f; }
  float4 acc = make_float4(0.f, 0.f, 0.f, 0.f);

  for (int base = 0; base < cnt; base += 32) {
    int c = min(32, cnt - base);

    int s = 0;
    float e[H];
    if (lane < c) {
      s = __ldg(&g_sby[beg + base + lane]);
      float av[H];
      load_as<H>(av, asv, s);
#pragma unroll
      for (int h = 0; h < H; h++) e[h] = lrelu(av[h] + ad[h]);
    } else {
#pragma unroll
      for (int h = 0; h < H; h++) e[h] = -1e30f;
    }

    float cm[H];
#pragma unroll
    for (int h = 0; h < H; h++) {
      cm[h] = e[h];
#pragma unroll
      for (int o = 16; o; o >>= 1) cm[h] = fmaxf(cm[h], __shfl_xor_sync(0xffffffffu, cm[h], o));
    }

    float a_[H];
#pragma unroll
    for (int h = 0; h < H; h++) {
      float mn = fmaxf(m[h], cm[h]);
      float f = __expf(m[h] - mn);
      m[h] = mn;
      den[h] *= f;
      if (h == myh) { acc.x *= f; acc.y *= f; acc.z *= f; acc.w *= f; }
      a_[h] = (lane < c) ? __expf(e[h] - mn) : 0.f;
      salpha[warp][h * 33 + lane] = a_[h];
    }

#pragma unroll
    for (int h = 0; h < H; h++) {
      float sum = a_[h];
#pragma unroll
      for (int o = 16; o; o >>= 1) sum += __shfl_xor_sync(0xffffffffu, sum, o);
      den[h] += sum;
    }
    __syncwarp();

    const float* sa = &salpha[warp][myh * 33];
#pragma unroll 4
    for (int j = 0; j < c; j++) {
      int sj = __shfl_sync(0xffffffffu, s, j);
      float w = sa[j];
      float4 tv = __ldg((const float4*)(t + (size_t)sj * 128 + lane * 4));
      acc.x = fmaf(w, tv.x, acc.x);
      acc.y = fmaf(w, tv.y, acc.y);
      acc.z = fmaf(w, tv.z, acc.z);
      acc.w = fmaf(w, tv.w, acc.w);
    }
    __syncwarp();
  }

  float inv = 1.f / fmaxf(den[myh], 1e-16f);
  float4 bv = *(const float4*)(bias + lane * 4);
  float4 v;
  v.x = acc.x * inv + bv.x;
  v.y = acc.y * inv + bv.y;
  v.z = acc.z * inv + bv.z;
  v.w = acc.w * inv + bv.w;
  if (LK) { v.x = lrelu(v.x); v.y = lrelu(v.y); v.z = lrelu(v.z); v.w = lrelu(v.w); }
  if (CVT) v = tf32r4(v);
  *(float4*)(out + (size_t)node * 128 + lane * 4) = v;
}

// ---------------- final: BN2 affine + L2 row normalize (2 nodes/block) ----------------
__global__ __launch_bounds__(256) void k_final(float* __restrict__ out) {
  int node = blockIdx.x * 2 + (threadIdx.x >> 7);
  int tid = threadIdx.x & 127;
  if (node >= NN) return;
  float v = out[(size_t)node * 128 + tid] * g_sc2[tid] + g_sh2[tid];
  float q = v * v;
#pragma unroll
  for (int o = 16; o; o >>= 1) q += __shfl_xor_sync(0xffffffffu, q, o);
  __shared__ float sq[2][4];
  int half = threadIdx.x >> 7;
  if ((tid & 31) == 0) sq[half][tid >> 5] = q;
  __syncthreads();
  float tot = sq[half][0] + sq[half][1] + sq[half][2] + sq[half][3];
  float r = 1.f / fmaxf(sqrtf(tot), 1e-12f);
  out[(size_t)node * 128 + tid] = v * r;
}

}  // namespace

extern "C" void kernel_launch(void* const* d_in, const int* in_sizes, int n_in,
                              void* d_out, int out_size) {
  const float* x        = (const float*)d_in[0];
  const float* b_in     = (const float*)d_in[2];
  const float* gamma1   = (const float*)d_in[3];
  const float* beta1    = (const float*)d_in[4];
  const float* W1       = (const float*)d_in[5];
  const float* att_src1 = (const float*)d_in[6];
  const float* att_dst1 = (const float*)d_in[7];
  const float* bias1    = (const float*)d_in[8];
  const float* att_src2 = (const float*)d_in[10];
  const float* att_dst2 = (const float*)d_in[11];
  const float* bias2    = (const float*)d_in[12];
  const float* b_skip   = (const float*)d_in[14];
  const float* gamma2   = (const float*)d_in[15];
  const float* beta2    = (const float*)d_in[16];
  const void*  eidx     = d_in[17];
  float* out = (float*)d_out;

  cudaFuncSetAttribute(k_gemm_tc<KIN, M_BIAS | M_LEAKY | M_CVT, 0>,
                       cudaFuncAttributeMaxDynamicSharedMemorySize, GEMM_SMEM);
  cudaFuncSetAttribute(k_gemm_tc<128, M_TB, 1>,
                       cudaFuncAttributeMaxDynamicSharedMemorySize, GEMM_SMEM);
  cudaFuncSetAttribute(k_gemm_tc<128, 0, 2>,
                       cudaFuncAttributeMaxDynamicSharedMemorySize, GEMM_SMEM);
  cudaFuncSetAttribute(k_gemm_tc<128, M_BIAS | M_ADDC, 3>,
                       cudaFuncAttributeMaxDynamicSharedMemorySize, GEMM_SMEM);

  const int GB = (NN + 127) / 128;   // 391
  const int SB = (NN + 511) / 512;   // 98
  const int AB = (NN + 7) / 8;       // 6250

  // --- CSR build first; launch idx 3 = k_scatter (profiled) ---
  k_zero<<<(NN + 255) / 256, 256>>>(eidx);                  // 0
  k_edges<<<(NE + 255) / 256, 256>>>(eidx);                 // 1
  k_scan<<<NB, 1024>>>();                                   // 2
  k_scatter<<<(NE + 255) / 256, 256>>>();                   // 3 (profiled)

  // --- pre-round GEMM operands ---
  k_roundall<<<(NN * 64 + 255) / 256, 256>>>(x, (const float*)d_in[1],
                                             (const float*)d_in[9], (const float*)d_in[13]);

  // --- GEMM chain ---
  k_gemm_tc<KIN, M_BIAS | M_LEAKY | M_CVT, 0><<<GB, 256, GEMM_SMEM>>>(b_in, nullptr);
  k_colstats<1><<<SB, 256>>>(nullptr);
  k_bnprep<<<1, 128>>>(gamma1, beta1, W1);
  k_gemm_tc<128, M_TB, 1><<<GB, 256, GEMM_SMEM>>>(nullptr, nullptr);
  k_att<8><<<NN / 2, 256>>>(att_src1, att_dst1);
  k_gat<8, true, true><<<AB, 256>>>(bias1);
  k_gemm_tc<128, 0, 2><<<GB, 256, GEMM_SMEM>>>(nullptr, nullptr);
  k_att<1><<<NN / 2, 256>>>(att_src2, att_dst2);
  k_gat<1, false, false><<<AB, 256>>>(bias2);
  k_gemm_tc<128, M_BIAS | M_ADDC, 3><<<GB, 256, GEMM_SMEM>>>(b_skip, out);
  k_colstats<2><<<SB, 256>>>(out);
  k_bnfin2<<<1, 128>>>(gamma2, beta2);
  k_final<<<(NN + 1) / 2, 256>>>(out);
}

// round 11
// speedup vs baseline: 1.0019x; 1.0019x over previous
#include <cuda_runtime.h>

namespace {

constexpr int NN  = 50000;   // nodes
constexpr int NE  = 800000;  // edges
constexpr int KIN = 256;     // in_dim
constexpr int NB  = (NN + 1023) / 1024;  // scan blocks = 49

// ---------------- scratch (static device memory; no allocations) ----------------
__device__ float g_w1p[128 * 128];   // tf32-rounded diag(sc1)*W1
__device__ float g_w2[128 * 128];    // tf32-rounded W2
__device__ float g_wskip[128 * 128]; // tf32-rounded W_skip
__device__ float g_t1bias[128];      // sh1^T @ W1
__device__ float g_h1[NN * 128];     // leaky(x@W_in+b_in), tf32-rounded
__device__ float g_t1[NN * 128];     // BN1(h1) @ W1
__device__ float g_skip[NN * 128];   // leaky(gat1 + bias1), tf32-rounded
__device__ float g_t2[NN * 128];     // skip @ W2
__device__ float g_out2[NN * 128];   // gat2 + bias2
__device__ float g_as1[NN * 8];
__device__ float g_ad1[NN * 8];
__device__ float g_as2[NN];
__device__ float g_ad2[NN];
__device__ int   g_src[NE];
__device__ int   g_dst[NE];
__device__ int   g_sby[NE];          // src ids sorted by dst (CSR order)
__device__ int   g_deg[NN];
__device__ int   g_cur[NN];
__device__ int   g_rs[NN + 1];       // CSR row starts (disjoint regions)
__device__ int   g_ctr;
__device__ float g_stats1[256];
__device__ float g_stats2[256];
__device__ float g_sc2[128], g_sh2[128];
__device__ int   g_is64;

__device__ __forceinline__ float lrelu(float v) { return v >= 0.f ? v : 0.2f * v; }

__device__ __forceinline__ float tf32r(float f) {
  unsigned u;
  asm("cvt.rna.tf32.f32 %0, %1;" : "=r"(u) : "f"(f));
  return __uint_as_float(u);
}
__device__ __forceinline__ float4 tf32r4(float4 v) {
  return make_float4(tf32r(v.x), tf32r(v.y), tf32r(v.z), tf32r(v.w));
}

// ---------------- setup: zero + dtype detect ----------------
__global__ void k_zero(const void* __restrict__ ei) {
  int i = blockIdx.x * 256 + threadIdx.x;
  if (i < NN) { g_deg[i] = 0; g_cur[i] = 0; g_as2[i] = 0.f; g_ad2[i] = 0.f; }
  if (i < 256) { g_stats1[i] = 0.f; g_stats2[i] = 0.f; }
  if (blockIdx.x == 0 && threadIdx.x == 0) {
    g_ctr = 0;
    const long long* p = (const long long*)ei;
    int ok = 1;
    for (int j = 0; j < 64; j++) {
      long long v = p[j];
      if (v < 0 || v >= NN) { ok = 0; break; }
    }
    g_is64 = ok;
  }
}

__global__ void k_edges(const void* __restrict__ ei) {
  int i = blockIdx.x * 256 + threadIdx.x;
  if (i < NE) {
    int s, d;
    if (g_is64) {
      const long long* p = (const long long*)ei;
      s = (int)p[i];
      d = (int)p[NE + i];
    } else {
      const int* p = (const int*)ei;
      s = p[i];
      d = p[NE + i];
    }
    if ((unsigned)s >= NN) s = 0;
    if ((unsigned)d >= NN) d = 0;
    g_src[i] = s;
    g_dst[i] = d;
    atomicAdd(&g_deg[d], 1);
  }
}

__global__ void k_scan() {
  int t = threadIdx.x;
  int i = blockIdx.x * 1024 + t;
  int v = (i < NN) ? g_deg[i] : 0;
  __shared__ int sb[1024];
  __shared__ int sbase;
  sb[t] = v;
  __syncthreads();
  for (int o = 1; o < 1024; o <<= 1) {
    int x = (t >= o) ? sb[t - o] : 0;
    __syncthreads();
    sb[t] += x;
    __syncthreads();
  }
  if (t == 1023) sbase = atomicAdd(&g_ctr, sb[1023]);
  __syncthreads();
  if (i < NN) g_rs[i] = sbase + sb[t] - v;
}

__global__ void k_scatter() {
  int i = blockIdx.x * 256 + threadIdx.x;
  if (i < NE) {
    int d = g_dst[i];
    int p = atomicAdd(&g_cur[d], 1);
    g_sby[g_rs[d] + p] = g_src[i];
  }
}

// ---------------- round W2 / W_skip to tf32 (tiny) ----------------
__global__ __launch_bounds__(256) void k_roundw(const float* __restrict__ W2,
                                                const float* __restrict__ Wsk) {
  int i = blockIdx.x * 256 + threadIdx.x;   // float4 index
  if (i < 4096) {
    *(float4*)(g_w2 + i * 4)    = tf32r4(*(const float4*)(W2 + i * 4));
    *(float4*)(g_wskip + i * 4) = tf32r4(*(const float4*)(Wsk + i * 4));
  }
}

// ---------------- TF32 tensor-core GEMM ----------------
constexpr int M_LEAKY = 2, M_ADDC = 4, M_BIAS = 16, M_CVT = 32, M_TB = 64;
constexpr int M_ST1 = 128, M_ST2 = 256, M_ATT8 = 512, M_ATT1 = 1024;
constexpr int ASZ = 128 * 36;
constexpr int WSZ = 32 * 136;
constexpr int TSZ = ASZ + WSZ;            // 8448 floats per stage
constexpr int GEMM_SMEM_1 = TSZ * 4;      // 33792 B (non-async, 1 stage)
constexpr int GEMM_SMEM_2 = TSZ * 2 * 4;  // 67584 B (async, 2 stages)

__device__ __forceinline__ void mma_tf32(float4& c, const unsigned a[4], const unsigned b[2]) {
  asm volatile(
      "mma.sync.aligned.m16n8k8.row.col.f32.tf32.tf32.f32 "
      "{%0,%1,%2,%3}, {%4,%5,%6,%7}, {%8,%9}, {%0,%1,%2,%3};"
      : "+f"(c.x), "+f"(c.y), "+f"(c.z), "+f"(c.w)
      : "r"(a[0]), "r"(a[1]), "r"(a[2]), "r"(a[3]), "r"(b[0]), "r"(b[1]));
}

// SEL: 0 -> A=Araw (x, K=256), W=Wraw (W_in), out=g_h1    [non-async, inline cvt]
//      1 -> A=g_h1,  W=g_w1p,  out=g_t1
//      2 -> A=g_skip,W=g_w2,   out=g_t2
//      3 -> A=g_skip,W=g_wskip,out=outp
template <int K, int MODE, int SEL, bool ASYNC>
__global__ __launch_bounds__(256, 2) void k_gemm_tc(const float* __restrict__ bias,
                                                    const float* __restrict__ atts,
                                                    const float* __restrict__ attd,
                                                    const float* __restrict__ Araw,
                                                    const float* __restrict__ Wraw,
                                                    float* __restrict__ outp) {
  extern __shared__ float sm[];
  __shared__ float satt[256];
  __shared__ float sstat[256];

  const float* A  = (SEL == 0) ? Araw : (SEL == 1) ? g_h1 : g_skip;
  const float* Wm = (SEL == 0) ? Wraw : (SEL == 1) ? g_w1p : (SEL == 2) ? g_w2 : g_wskip;
  float* out      = (SEL == 0) ? g_h1 : (SEL == 1) ? g_t1 : (SEL == 2) ? g_t2 : outp;

  int tid = threadIdx.x;
  int lane = tid & 31, wid = tid >> 5;
  int gr = lane >> 2, gc = lane & 3;
  int warp_m = wid & 3, warp_n = wid >> 2;
  int row0 = blockIdx.x * 128;

  // stage att vectors / zero stats (consumed after main-loop syncs)
  if (MODE & (M_ATT8 | M_ATT1)) {
    if (tid < 128) { satt[tid] = __ldg(atts + tid); satt[128 + tid] = __ldg(attd + tid); }
  }
  if (MODE & (M_ST1 | M_ST2)) sstat[tid] = 0.f;

  float4 acc[2][8];
#pragma unroll
  for (int mt = 0; mt < 2; mt++)
#pragma unroll
    for (int nt = 0; nt < 8; nt++) acc[mt][nt] = make_float4(0.f, 0.f, 0.f, 0.f);

  if constexpr (ASYNC) {
    auto issue = [&](int kc, int buf) {
      float* As = sm + buf * TSZ;
      float* Ws = As + ASZ;
#pragma unroll
      for (int i = 0; i < 4; i++) {
        int idx = tid * 4 + i * 1024;
        int r = idx >> 5, c = idx & 31;
        int grow = row0 + r;
        int ok = (grow < NN);
        const float* src = A + (size_t)(ok ? grow : 0) * K + kc + c;
        unsigned dst = (unsigned)__cvta_generic_to_shared(As + r * 36 + c);
        int sz = ok ? 16 : 0;
        asm volatile("cp.async.cg.shared.global [%0], [%1], 16, %2;"
                     :: "r"(dst), "l"(src), "r"(sz));
      }
#pragma unroll
      for (int i = 0; i < 4; i++) {
        int idx = tid * 4 + i * 1024;
        int k = idx >> 7, n = idx & 127;
        const float* src = Wm + (size_t)(kc + k) * 128 + n;
        unsigned dst = (unsigned)__cvta_generic_to_shared(Ws + k * 136 + n);
        asm volatile("cp.async.cg.shared.global [%0], [%1], 16;"
                     :: "r"(dst), "l"(src));
      }
      asm volatile("cp.async.commit_group;");
    };

    issue(0, 0);
    constexpr int NCH = K / 32;
    for (int ch = 0; ch < NCH; ch++) {
      asm volatile("cp.async.wait_group 0;" ::: "memory");
      __syncthreads();
      if (ch + 1 < NCH) issue((ch + 1) * 32, (ch + 1) & 1);

      const float* As = sm + (ch & 1) * TSZ;
      const float* Ws = As + ASZ;
#pragma unroll
      for (int kk = 0; kk < 32; kk += 8) {
        unsigned a[2][4];
#pragma unroll
        for (int mt = 0; mt < 2; mt++) {
          int rb = warp_m * 32 + mt * 16;
          a[mt][0] = __float_as_uint(As[(rb + gr)     * 36 + kk + gc]);
          a[mt][1] = __float_as_uint(As[(rb + gr + 8) * 36 + kk + gc]);
          a[mt][2] = __float_as_uint(As[(rb + gr)     * 36 + kk + gc + 4]);
          a[mt][3] = __float_as_uint(As[(rb + gr + 8) * 36 + kk + gc + 4]);
        }
        unsigned b[8][2];
#pragma unroll
        for (int nt = 0; nt < 8; nt++) {
          int n = warp_n * 64 + nt * 8 + gr;
          b[nt][0] = __float_as_uint(Ws[(kk + gc)     * 136 + n]);
          b[nt][1] = __float_as_uint(Ws[(kk + gc + 4) * 136 + n]);
        }
#pragma unroll
        for (int mt = 0; mt < 2; mt++)
#pragma unroll
          for (int nt = 0; nt < 8; nt++) mma_tf32(acc[mt][nt], a[mt], b[nt]);
      }
      __syncthreads();
    }
  } else {
    float* As = sm;
    float* Ws = sm + ASZ;
    for (int kc = 0; kc < K; kc += 32) {
#pragma unroll
      for (int i = 0; i < 4; i++) {
        int idx = tid * 4 + i * 1024;
        int r = idx >> 5, c = idx & 31;
        int grow = row0 + r;
        float4 v = make_float4(0.f, 0.f, 0.f, 0.f);
        if (grow < NN) v = *(const float4*)(A + (size_t)grow * K + kc + c);
        float* p = &As[r * 36 + c];
        p[0] = tf32r(v.x); p[1] = tf32r(v.y); p[2] = tf32r(v.z); p[3] = tf32r(v.w);
      }
#pragma unroll
      for (int i = 0; i < 4; i++) {
        int idx = tid * 4 + i * 1024;
        int k = idx >> 7, n = idx & 127;
        float4 v = *(const float4*)(Wm + (size_t)(kc + k) * 128 + n);
        float* p = &Ws[k * 136 + n];
        p[0] = tf32r(v.x); p[1] = tf32r(v.y); p[2] = tf32r(v.z); p[3] = tf32r(v.w);
      }
      __syncthreads();
#pragma unroll
      for (int kk = 0; kk < 32; kk += 8) {
        unsigned a[2][4];
#pragma unroll
        for (int mt = 0; mt < 2; mt++) {
          int rb = warp_m * 32 + mt * 16;
          a[mt][0] = __float_as_uint(As[(rb + gr)     * 36 + kk + gc]);
          a[mt][1] = __float_as_uint(As[(rb + gr + 8) * 36 + kk + gc]);
          a[mt][2] = __float_as_uint(As[(rb + gr)     * 36 + kk + gc + 4]);
          a[mt][3] = __float_as_uint(As[(rb + gr + 8) * 36 + kk + gc + 4]);
        }
        unsigned b[8][2];
#pragma unroll
        for (int nt = 0; nt < 8; nt++) {
          int n = warp_n * 64 + nt * 8 + gr;
          b[nt][0] = __float_as_uint(Ws[(kk + gc)     * 136 + n]);
          b[nt][1] = __float_as_uint(Ws[(kk + gc + 4) * 136 + n]);
        }
#pragma unroll
        for (int mt = 0; mt < 2; mt++)
#pragma unroll
          for (int nt = 0; nt < 8; nt++) mma_tf32(acc[mt][nt], a[mt], b[nt]);
      }
      __syncthreads();
    }
  }

  // ---------------- fused epilogue: store + bias/addC/leaky/cvt + stats + att ----------------
  float pa_s[2][2] = {{0.f, 0.f}, {0.f, 0.f}};
  float pa_d[2][2] = {{0.f, 0.f}, {0.f, 0.f}};

#pragma unroll
  for (int nt = 0; nt < 8; nt++) {
    int col = warp_n * 64 + nt * 8 + gc * 2;
    float2 bv = make_float2(0.f, 0.f);
    if (MODE & M_BIAS) bv = *(const float2*)(bias + col);
    if (MODE & M_TB)   bv = *(const float2*)(g_t1bias + col);
    float2 av_s = make_float2(0.f, 0.f), av_d = make_float2(0.f, 0.f);
    if (MODE & (M_ATT8 | M_ATT1)) {
      av_s = *(const float2*)&satt[col];
      av_d = *(const float2*)&satt[128 + col];
    }
    float2 csum = make_float2(0.f, 0.f), csq = make_float2(0.f, 0.f);

#pragma unroll
    for (int mt = 0; mt < 2; mt++) {
#pragma unroll
      for (int hh = 0; hh < 2; hh++) {
        int r = row0 + warp_m * 32 + mt * 16 + gr + hh * 8;
        if (r < NN) {
          float2 v = hh ? make_float2(acc[mt][nt].z, acc[mt][nt].w)
                        : make_float2(acc[mt][nt].x, acc[mt][nt].y);
          if (MODE & (M_BIAS | M_TB)) { v.x += bv.x; v.y += bv.y; }
          if (MODE & M_ADDC) {
            float2 cv = *(const float2*)(g_out2 + (size_t)r * 128 + col);
            v.x += cv.x; v.y += cv.y;
          }
          if (MODE & M_LEAKY) { v.x = lrelu(v.x); v.y = lrelu(v.y); }
          if (MODE & M_CVT)   { v.x = tf32r(v.x); v.y = tf32r(v.y); }
          *(float2*)(out + (size_t)r * 128 + col) = v;
          if (MODE & (M_ST1 | M_ST2)) {
            csum.x += v.x; csum.y += v.y;
            csq.x += v.x * v.x; csq.y += v.y * v.y;
          }
          if (MODE & (M_ATT8 | M_ATT1)) {
            pa_s[mt][hh] = fmaf(v.x, av_s.x, fmaf(v.y, av_s.y, pa_s[mt][hh]));
            pa_d[mt][hh] = fmaf(v.x, av_d.x, fmaf(v.y, av_d.y, pa_d[mt][hh]));
          }
        }
      }
    }

    if (MODE & (M_ST1 | M_ST2)) {
      atomicAdd(&sstat[col], csum.x);
      atomicAdd(&sstat[col + 1], csum.y);
      atomicAdd(&sstat[128 + col], csq.x);
      atomicAdd(&sstat[128 + col + 1], csq.y);
    }

    if ((MODE & M_ATT8) && (nt & 1)) {
      int head = warp_n * 4 + (nt >> 1);
#pragma unroll
      for (int mt = 0; mt < 2; mt++) {
#pragma unroll
        for (int hh = 0; hh < 2; hh++) {
          float ps = pa_s[mt][hh], pd = pa_d[mt][hh];
          ps += __shfl_xor_sync(0xffffffffu, ps, 1);
          ps += __shfl_xor_sync(0xffffffffu, ps, 2);
          pd += __shfl_xor_sync(0xffffffffu, pd, 1);
          pd += __shfl_xor_sync(0xffffffffu, pd, 2);
          int r = row0 + warp_m * 32 + mt * 16 + gr + hh * 8;
          if (gc == 0 && r < NN) {
            g_as1[(size_t)r * 8 + head] = ps;
            g_ad1[(size_t)r * 8 + head] = pd;
          }
          pa_s[mt][hh] = 0.f;
          pa_d[mt][hh] = 0.f;
        }
      }
    }
  }

  if (MODE & M_ATT1) {
#pragma unroll
    for (int mt = 0; mt < 2; mt++) {
#pragma unroll
      for (int hh = 0; hh < 2; hh++) {
        float ps = pa_s[mt][hh], pd = pa_d[mt][hh];
        ps += __shfl_xor_sync(0xffffffffu, ps, 1);
        ps += __shfl_xor_sync(0xffffffffu, ps, 2);
        pd += __shfl_xor_sync(0xffffffffu, pd, 1);
        pd += __shfl_xor_sync(0xffffffffu, pd, 2);
        int r = row0 + warp_m * 32 + mt * 16 + gr + hh * 8;
        if (gc == 0 && r < NN) {
          atomicAdd(&g_as2[r], ps);
          atomicAdd(&g_ad2[r], pd);
        }
      }
    }
  }

  if (MODE & (M_ST1 | M_ST2)) {
    __syncthreads();
    float* gst = (MODE & M_ST1) ? g_stats1 : g_stats2;
    atomicAdd(&gst[tid & 255], sstat[tid & 255] * 0.f + sstat[tid]);  // tid<256 always
  }
}

// ---------------- BN1 finalize + fold into W1 ----------------
__global__ __launch_bounds__(128) void k_bnprep(const float* __restrict__ gamma,
                                                const float* __restrict__ beta,
                                                const float* __restrict__ W1) {
  __shared__ float ssc[128], ssh[128];
  int t = threadIdx.x;
  float mean = g_stats1[t] * (1.f / NN);
  float var = g_stats1[128 + t] * (1.f / NN) - mean * mean;
  float sc = rsqrtf(var + 1e-5f) * gamma[t];
  float sh = beta[t] - mean * sc;
  ssc[t] = sc; ssh[t] = sh;
  __syncthreads();
  float tb = 0.f;
  for (int k = 0; k < 128; k++) {
    float w = W1[k * 128 + t];
    g_w1p[k * 128 + t] = tf32r(ssc[k] * w);
    tb = fmaf(ssh[k], w, tb);
  }
  g_t1bias[t] = tb;
}

// ---------------- BN2 finalize ----------------
__global__ void k_bnfin2(const float* __restrict__ gamma, const float* __restrict__ beta) {
  int i = threadIdx.x;
  float mean = g_stats2[i] * (1.f / NN);
  float var = g_stats2[128 + i] * (1.f / NN) - mean * mean;
  float sc = rsqrtf(var + 1e-5f) * gamma[i];
  g_sc2[i] = sc;
  g_sh2[i] = beta[i] - mean * sc;
}

template <int H>
__device__ __forceinline__ void load_as(float* dst, const float* __restrict__ p, int s) {
  if constexpr (H == 8) {
    float4 a = __ldg((const float4*)(p + (size_t)s * 8));
    float4 b = __ldg((const float4*)(p + (size_t)s * 8 + 4));
    dst[0] = a.x; dst[1] = a.y; dst[2] = a.z; dst[3] = a.w;
    dst[4] = b.x; dst[5] = b.y; dst[6] = b.z; dst[7] = b.w;
  } else {
    dst[0] = __ldg(p + s);
  }
}

// ---------------- GAT aggregation: WARP per node, online softmax ----------------
template <int H, bool LK, bool CVT>
__global__ __launch_bounds__(256) void k_gat(const float* __restrict__ bias) {
  const float* t   = (H == 8) ? g_t1  : g_t2;
  const float* asv = (H == 8) ? g_as1 : g_as2;
  const float* adv = (H == 8) ? g_ad1 : g_ad2;
  float* out       = (H == 8) ? g_skip : g_out2;

  int lane = threadIdx.x & 31, warp = threadIdx.x >> 5;
  int node = blockIdx.x * 8 + warp;
  if (node >= NN) return;
  int beg = g_rs[node];
  int cnt = g_deg[node];
  int myh = (H == 8) ? (lane >> 2) : 0;

  __shared__ float salpha[8][H * 33];

  float ad[H];
  load_as<H>(ad, adv, node);

  float m[H], den[H];
#pragma unroll
  for (int h = 0; h < H; h++) { m[h] = -1e30f; den[h] = 0.f; }
  float4 acc = make_float4(0.f, 0.f, 0.f, 0.f);

  for (int base = 0; base < cnt; base += 32) {
    int c = min(32, cnt - base);

    int s = 0;
    float e[H];
    if (lane < c) {
      s = __ldg(&g_sby[beg + base + lane]);
      float av[H];
      load_as<H>(av, asv, s);
#pragma unroll
      for (int h = 0; h < H; h++) e[h] = lrelu(av[h] + ad[h]);
    } else {
#pragma unroll
      for (int h = 0; h < H; h++) e[h] = -1e30f;
    }

    float cm[H];
#pragma unroll
    for (int h = 0; h < H; h++) {
      cm[h] = e[h];
#pragma unroll
      for (int o = 16; o; o >>= 1) cm[h] = fmaxf(cm[h], __shfl_xor_sync(0xffffffffu, cm[h], o));
    }

    float a_[H];
#pragma unroll
    for (int h = 0; h < H; h++) {
      float mn = fmaxf(m[h], cm[h]);
      float f = __expf(m[h] - mn);
      m[h] = mn;
      den[h] *= f;
      if (h == myh) { acc.x *= f; acc.y *= f; acc.z *= f; acc.w *= f; }
      a_[h] = (lane < c) ? __expf(e[h] - mn) : 0.f;
      salpha[warp][h * 33 + lane] = a_[h];
    }

#pragma unroll
    for (int h = 0; h < H; h++) {
      float sum = a_[h];
#pragma unroll
      for (int o = 16; o; o >>= 1) sum += __shfl_xor_sync(0xffffffffu, sum, o);
      den[h] += sum;
    }
    __syncwarp();

    const float* sa = &salpha[warp][myh * 33];
#pragma unroll 4
    for (int j = 0; j < c; j++) {
      int sj = __shfl_sync(0xffffffffu, s, j);
      float w = sa[j];
      float4 tv = __ldg((const float4*)(t + (size_t)sj * 128 + lane * 4));
      acc.x = fmaf(w, tv.x, acc.x);
      acc.y = fmaf(w, tv.y, acc.y);
      acc.z = fmaf(w, tv.z, acc.z);
      acc.w = fmaf(w, tv.w, acc.w);
    }
    __syncwarp();
  }

  float inv = 1.f / fmaxf(den[myh], 1e-16f);
  float4 bv = *(const float4*)(bias + lane * 4);
  float4 v;
  v.x = acc.x * inv + bv.x;
  v.y = acc.y * inv + bv.y;
  v.z = acc.z * inv + bv.z;
  v.w = acc.w * inv + bv.w;
  if (LK) { v.x = lrelu(v.x); v.y = lrelu(v.y); v.z = lrelu(v.z); v.w = lrelu(v.w); }
  if (CVT) v = tf32r4(v);
  *(float4*)(out + (size_t)node * 128 + lane * 4) = v;
}

// ---------------- final: BN2 affine + L2 row normalize (2 nodes/block) ----------------
__global__ __launch_bounds__(256) void k_final(float* __restrict__ out) {
  int node = blockIdx.x * 2 + (threadIdx.x >> 7);
  int tid = threadIdx.x & 127;
  if (node >= NN) return;
  float v = out[(size_t)node * 128 + tid] * g_sc2[tid] + g_sh2[tid];
  float q = v * v;
#pragma unroll
  for (int o = 16; o; o >>= 1) q += __shfl_xor_sync(0xffffffffu, q, o);
  __shared__ float sq[2][4];
  int half = threadIdx.x >> 7;
  if ((tid & 31) == 0) sq[half][tid >> 5] = q;
  __syncthreads();
  float tot = sq[half][0] + sq[half][1] + sq[half][2] + sq[half][3];
  float r = 1.f / fmaxf(sqrtf(tot), 1e-12f);
  out[(size_t)node * 128 + tid] = v * r;
}

}  // namespace

extern "C" void kernel_launch(void* const* d_in, const int* in_sizes, int n_in,
                              void* d_out, int out_size) {
  const float* x        = (const float*)d_in[0];
  const float* W_in     = (const float*)d_in[1];
  const float* b_in     = (const float*)d_in[2];
  const float* gamma1   = (const float*)d_in[3];
  const float* beta1    = (const float*)d_in[4];
  const float* W1       = (const float*)d_in[5];
  const float* att_src1 = (const float*)d_in[6];
  const float* att_dst1 = (const float*)d_in[7];
  const float* bias1    = (const float*)d_in[8];
  const float* W2       = (const float*)d_in[9];
  const float* att_src2 = (const float*)d_in[10];
  const float* att_dst2 = (const float*)d_in[11];
  const float* bias2    = (const float*)d_in[12];
  const float* W_skip   = (const float*)d_in[13];
  const float* b_skip   = (const float*)d_in[14];
  const float* gamma2   = (const float*)d_in[15];
  const float* beta2    = (const float*)d_in[16];
  const void*  eidx     = d_in[17];
  float* out = (float*)d_out;

  cudaFuncSetAttribute(k_gemm_tc<128, M_TB | M_ATT8, 1, true>,
                       cudaFuncAttributeMaxDynamicSharedMemorySize, GEMM_SMEM_2);
  cudaFuncSetAttribute(k_gemm_tc<128, M_ATT1, 2, true>,
                       cudaFuncAttributeMaxDynamicSharedMemorySize, GEMM_SMEM_2);
  cudaFuncSetAttribute(k_gemm_tc<128, M_BIAS | M_ADDC | M_ST2, 3, true>,
                       cudaFuncAttributeMaxDynamicSharedMemorySize, GEMM_SMEM_2);

  const int GB = (NN + 127) / 128;   // 391
  const int AB = (NN + 7) / 8;       // 6250

  k_zero<<<(NN + 255) / 256, 256>>>(eidx);                                     // 0
  k_edges<<<(NE + 255) / 256, 256>>>(eidx);                                    // 1
  k_scan<<<NB, 1024>>>();                                                      // 2
  // GEMM1: h1 = leaky(x@W_in+b_in), stats1 fused   (profiled at idx 3)
  k_gemm_tc<KIN, M_BIAS | M_LEAKY | M_CVT | M_ST1, 0, false>
      <<<GB, 256, GEMM_SMEM_1>>>(b_in, nullptr, nullptr, x, W_in, nullptr);    // 3
  k_scatter<<<(NE + 255) / 256, 256>>>();                                      // 4
  k_roundw<<<16, 256>>>(W2, W_skip);                                           // 5
  k_bnprep<<<1, 128>>>(gamma1, beta1, W1);                                     // 6
  // GEMM2: t1 = BN1(h1)@W1 (+t1bias), att1 fused
  k_gemm_tc<128, M_TB | M_ATT8, 1, true>
      <<<GB, 256, GEMM_SMEM_2>>>(nullptr, att_src1, att_dst1, nullptr, nullptr, nullptr);
  k_gat<8, true, true><<<AB, 256>>>(bias1);
  // GEMM3: t2 = skip@W2, att2 fused
  k_gemm_tc<128, M_ATT1, 2, true>
      <<<GB, 256, GEMM_SMEM_2>>>(nullptr, att_src2, att_dst2, nullptr, nullptr, nullptr);
  k_gat<1, false, false><<<AB, 256>>>(bias2);
  // GEMM4: out = skip@W_skip + b_skip + out2, stats2 fused
  k_gemm_tc<128, M_BIAS | M_ADDC | M_ST2, 3, true>
      <<<GB, 256, GEMM_SMEM_2>>>(b_skip, nullptr, nullptr, nullptr, nullptr, out);
  k_bnfin2<<<1, 128>>>(gamma2, beta2);
  k_final<<<(NN + 1) / 2, 256>>>(out);
}

// round 12
// speedup vs baseline: 1.0597x; 1.0576x over previous
#include <cuda_runtime.h>

namespace {

constexpr int NN  = 50000;   // nodes
constexpr int NE  = 800000;  // edges
constexpr int KIN = 256;     // in_dim
constexpr int NB  = (NN + 1023) / 1024;  // scan blocks = 49

// ---------------- scratch (static device memory; no allocations) ----------------
__device__ float g_win[256 * 128];   // tf32-rounded W_in
__device__ float g_w1p[128 * 128];   // tf32-rounded diag(sc1)*W1
__device__ float g_w2[128 * 128];    // tf32-rounded W2
__device__ float g_wskip[128 * 128]; // tf32-rounded W_skip
__device__ float g_t1bias[128];      // sh1^T @ W1
__device__ float g_h1[NN * 128];     // leaky(x@W_in+b_in), tf32-rounded
__device__ float g_t1[NN * 128];     // BN1(h1) @ W1
__device__ float g_skip[NN * 128];   // leaky(gat1 + bias1), tf32-rounded
__device__ float g_t2[NN * 128];     // skip @ W2
__device__ float g_out2[NN * 128];   // gat2 + bias2
__device__ float g_as1[NN * 8];
__device__ float g_ad1[NN * 8];
__device__ float g_as2[NN];
__device__ float g_ad2[NN];
__device__ int   g_src[NE];
__device__ int   g_dst[NE];
__device__ int   g_sby[NE];          // src ids sorted by dst (CSR order)
__device__ int   g_deg[NN];
__device__ int   g_cur[NN];
__device__ int   g_rs[NN + 1];       // CSR row starts (disjoint regions)
__device__ int   g_ctr;
__device__ float g_stats1[256];
__device__ float g_stats2[256];
__device__ float g_sc2[128], g_sh2[128];
__device__ int   g_is64;

__device__ __forceinline__ float lrelu(float v) { return v >= 0.f ? v : 0.2f * v; }

__device__ __forceinline__ float tf32r(float f) {
  unsigned u;
  asm("cvt.rna.tf32.f32 %0, %1;" : "=r"(u) : "f"(f));
  return __uint_as_float(u);
}
__device__ __forceinline__ float4 tf32r4(float4 v) {
  return make_float4(tf32r(v.x), tf32r(v.y), tf32r(v.z), tf32r(v.w));
}

// ---------------- setup: zero + dtype detect ----------------
__global__ void k_zero(const void* __restrict__ ei) {
  int i = blockIdx.x * 256 + threadIdx.x;
  if (i < NN) { g_deg[i] = 0; g_cur[i] = 0; g_as2[i] = 0.f; g_ad2[i] = 0.f; }
  if (i < 256) { g_stats1[i] = 0.f; g_stats2[i] = 0.f; }
  if (blockIdx.x == 0 && threadIdx.x == 0) {
    g_ctr = 0;
    const long long* p = (const long long*)ei;
    int ok = 1;
    for (int j = 0; j < 64; j++) {
      long long v = p[j];
      if (v < 0 || v >= NN) { ok = 0; break; }
    }
    g_is64 = ok;
  }
}

__global__ void k_edges(const void* __restrict__ ei) {
  int i = blockIdx.x * 256 + threadIdx.x;
  if (i < NE) {
    int s, d;
    if (g_is64) {
      const long long* p = (const long long*)ei;
      s = (int)p[i];
      d = (int)p[NE + i];
    } else {
      const int* p = (const int*)ei;
      s = p[i];
      d = p[NE + i];
    }
    if ((unsigned)s >= NN) s = 0;
    if ((unsigned)d >= NN) d = 0;
    g_src[i] = s;
    g_dst[i] = d;
    atomicAdd(&g_deg[d], 1);
  }
}

__global__ void k_scan() {
  int t = threadIdx.x;
  int i = blockIdx.x * 1024 + t;
  int v = (i < NN) ? g_deg[i] : 0;
  __shared__ int sb[1024];
  __shared__ int sbase;
  sb[t] = v;
  __syncthreads();
  for (int o = 1; o < 1024; o <<= 1) {
    int x = (t >= o) ? sb[t - o] : 0;
    __syncthreads();
    sb[t] += x;
    __syncthreads();
  }
  if (t == 1023) sbase = atomicAdd(&g_ctr, sb[1023]);
  __syncthreads();
  if (i < NN) g_rs[i] = sbase + sb[t] - v;
}

__global__ void k_scatter() {
  int i = blockIdx.x * 256 + threadIdx.x;
  if (i < NE) {
    int d = g_dst[i];
    int p = atomicAdd(&g_cur[d], 1);
    g_sby[g_rs[d] + p] = g_src[i];
  }
}

// ---------------- round W_in / W2 / W_skip to tf32 (tiny) ----------------
__global__ __launch_bounds__(256) void k_roundw(const float* __restrict__ Win,
                                                const float* __restrict__ W2,
                                                const float* __restrict__ Wsk) {
  int i = blockIdx.x * 256 + threadIdx.x;   // float4 index
  if (i < 8192)
    *(float4*)(g_win + i * 4) = tf32r4(*(const float4*)(Win + i * 4));
  if (i < 4096) {
    *(float4*)(g_w2 + i * 4)    = tf32r4(*(const float4*)(W2 + i * 4));
    *(float4*)(g_wskip + i * 4) = tf32r4(*(const float4*)(Wsk + i * 4));
  }
}

// ---------------- TF32 tensor-core GEMM ----------------
constexpr int M_LEAKY = 2, M_ADDC = 4, M_BIAS = 16, M_CVT = 32, M_TB = 64;
constexpr int M_ST1 = 128, M_ST2 = 256, M_ATT8 = 512, M_ATT1 = 1024;
constexpr int ASZ = 128 * 36;
constexpr int WSZ = 32 * 136;
constexpr int TSZ = ASZ + WSZ;            // 8448 floats per stage
constexpr int GEMM_SMEM = TSZ * 2 * 4;    // 67584 B (2 stages)

__device__ __forceinline__ void mma_tf32(float4& c, const unsigned a[4], const unsigned b[2]) {
  asm volatile(
      "mma.sync.aligned.m16n8k8.row.col.f32.tf32.tf32.f32 "
      "{%0,%1,%2,%3}, {%4,%5,%6,%7}, {%8,%9}, {%0,%1,%2,%3};"
      : "+f"(c.x), "+f"(c.y), "+f"(c.z), "+f"(c.w)
      : "r"(a[0]), "r"(a[1]), "r"(a[2]), "r"(a[3]), "r"(b[0]), "r"(b[1]));
}

// SEL: 0 -> A=Araw (x, K=256, reg-prefetch+cvt), W=g_win (cp.async), out=g_h1
//      1 -> A=g_h1,  W=g_w1p,  out=g_t1     (full cp.async)
//      2 -> A=g_skip,W=g_w2,   out=g_t2     (full cp.async)
//      3 -> A=g_skip,W=g_wskip,out=outp     (full cp.async)
template <int K, int MODE, int SEL>
__global__ __launch_bounds__(256, 2) void k_gemm_tc(const float* __restrict__ bias,
                                                    const float* __restrict__ atts,
                                                    const float* __restrict__ attd,
                                                    const float* __restrict__ Araw,
                                                    float* __restrict__ outp) {
  extern __shared__ float sm[];
  __shared__ float satt[256];
  __shared__ float sstat[256];

  const float* A  = (SEL == 0) ? Araw : (SEL == 1) ? g_h1 : g_skip;
  const float* Wm = (SEL == 0) ? g_win : (SEL == 1) ? g_w1p : (SEL == 2) ? g_w2 : g_wskip;
  float* out      = (SEL == 0) ? g_h1 : (SEL == 1) ? g_t1 : (SEL == 2) ? g_t2 : outp;

  int tid = threadIdx.x;
  int lane = tid & 31, wid = tid >> 5;
  int gr = lane >> 2, gc = lane & 3;
  int warp_m = wid & 3, warp_n = wid >> 2;
  int row0 = blockIdx.x * 128;

  if (MODE & (M_ATT8 | M_ATT1)) {
    if (tid < 128) { satt[tid] = __ldg(atts + tid); satt[128 + tid] = __ldg(attd + tid); }
  }
  if (MODE & (M_ST1 | M_ST2)) sstat[tid] = 0.f;

  float4 acc[2][8];
#pragma unroll
  for (int mt = 0; mt < 2; mt++)
#pragma unroll
    for (int nt = 0; nt < 8; nt++) acc[mt][nt] = make_float4(0.f, 0.f, 0.f, 0.f);

  // W tile via cp.async (always; W operands are pre-rounded)
  auto issueW = [&](int kc, int buf) {
    float* Ws = sm + buf * TSZ + ASZ;
#pragma unroll
    for (int i = 0; i < 4; i++) {
      int idx = tid * 4 + i * 1024;
      int k = idx >> 7, n = idx & 127;
      const float* src = Wm + (size_t)(kc + k) * 128 + n;
      unsigned dst = (unsigned)__cvta_generic_to_shared(Ws + k * 136 + n);
      asm volatile("cp.async.cg.shared.global [%0], [%1], 16;" :: "r"(dst), "l"(src));
    }
  };
  // A tile via cp.async (SEL>0: already tf32-rounded in memory)
  auto issueA = [&](int kc, int buf) {
    float* As = sm + buf * TSZ;
#pragma unroll
    for (int i = 0; i < 4; i++) {
      int idx = tid * 4 + i * 1024;
      int r = idx >> 5, c = idx & 31;
      int grow = row0 + r;
      int ok = (grow < NN);
      const float* src = A + (size_t)(ok ? grow : 0) * K + kc + c;
      unsigned dst = (unsigned)__cvta_generic_to_shared(As + r * 36 + c);
      int sz = ok ? 16 : 0;
      asm volatile("cp.async.cg.shared.global [%0], [%1], 16, %2;"
                   :: "r"(dst), "l"(src), "r"(sz));
    }
  };
  // A tile via registers (SEL==0: raw x, cvt at STS)
  float4 rA[4];
  auto ldgA = [&](int kc) {
#pragma unroll
    for (int i = 0; i < 4; i++) {
      int idx = tid * 4 + i * 1024;
      int r = idx >> 5, c = idx & 31;
      int grow = row0 + r;
      rA[i] = (grow < NN) ? *(const float4*)(A + (size_t)grow * K + kc + c)
                          : make_float4(0.f, 0.f, 0.f, 0.f);
    }
  };
  auto stsA = [&](int buf) {
    float* As = sm + buf * TSZ;
#pragma unroll
    for (int i = 0; i < 4; i++) {
      int idx = tid * 4 + i * 1024;
      int r = idx >> 5, c = idx & 31;
      float* p = &As[r * 36 + c];
      p[0] = tf32r(rA[i].x); p[1] = tf32r(rA[i].y);
      p[2] = tf32r(rA[i].z); p[3] = tf32r(rA[i].w);
    }
  };

  constexpr int NCH = K / 32;
  if (SEL == 0) {
    issueW(0, 0);
    asm volatile("cp.async.commit_group;");
    ldgA(0);
  } else {
    issueA(0, 0);
    issueW(0, 0);
    asm volatile("cp.async.commit_group;");
  }

  for (int ch = 0; ch < NCH; ch++) {
    if (SEL == 0) stsA(ch & 1);
    asm volatile("cp.async.wait_group 0;" ::: "memory");
    __syncthreads();
    if (ch + 1 < NCH) {
      if (SEL == 0) {
        issueW((ch + 1) * 32, (ch + 1) & 1);
        asm volatile("cp.async.commit_group;");
        ldgA((ch + 1) * 32);
      } else {
        issueA((ch + 1) * 32, (ch + 1) & 1);
        issueW((ch + 1) * 32, (ch + 1) & 1);
        asm volatile("cp.async.commit_group;");
      }
    }

    const float* As = sm + (ch & 1) * TSZ;
    const float* Ws = As + ASZ;
#pragma unroll
    for (int kk = 0; kk < 32; kk += 8) {
      unsigned a[2][4];
#pragma unroll
      for (int mt = 0; mt < 2; mt++) {
        int rb = warp_m * 32 + mt * 16;
        a[mt][0] = __float_as_uint(As[(rb + gr)     * 36 + kk + gc]);
        a[mt][1] = __float_as_uint(As[(rb + gr + 8) * 36 + kk + gc]);
        a[mt][2] = __float_as_uint(As[(rb + gr)     * 36 + kk + gc + 4]);
        a[mt][3] = __float_as_uint(As[(rb + gr + 8) * 36 + kk + gc + 4]);
      }
      unsigned b[8][2];
#pragma unroll
      for (int nt = 0; nt < 8; nt++) {
        int n = warp_n * 64 + nt * 8 + gr;
        b[nt][0] = __float_as_uint(Ws[(kk + gc)     * 136 + n]);
        b[nt][1] = __float_as_uint(Ws[(kk + gc + 4) * 136 + n]);
      }
#pragma unroll
      for (int mt = 0; mt < 2; mt++)
#pragma unroll
        for (int nt = 0; nt < 8; nt++) mma_tf32(acc[mt][nt], a[mt], b[nt]);
    }
    __syncthreads();
  }

  // ---------------- fused epilogue: store + bias/addC/leaky/cvt + stats + att ----------------
  float pa_s[2][2] = {{0.f, 0.f}, {0.f, 0.f}};
  float pa_d[2][2] = {{0.f, 0.f}, {0.f, 0.f}};

#pragma unroll
  for (int nt = 0; nt < 8; nt++) {
    int col = warp_n * 64 + nt * 8 + gc * 2;
    float2 bv = make_float2(0.f, 0.f);
    if (MODE & M_BIAS) bv = *(const float2*)(bias + col);
    if (MODE & M_TB)   bv = *(const float2*)(g_t1bias + col);
    float2 av_s = make_float2(0.f, 0.f), av_d = make_float2(0.f, 0.f);
    if (MODE & (M_ATT8 | M_ATT1)) {
      av_s = *(const float2*)&satt[col];
      av_d = *(const float2*)&satt[128 + col];
    }
    float2 csum = make_float2(0.f, 0.f), csq = make_float2(0.f, 0.f);

#pragma unroll
    for (int mt = 0; mt < 2; mt++) {
#pragma unroll
      for (int hh = 0; hh < 2; hh++) {
        int r = row0 + warp_m * 32 + mt * 16 + gr + hh * 8;
        if (r < NN) {
          float2 v = hh ? make_float2(acc[mt][nt].z, acc[mt][nt].w)
                        : make_float2(acc[mt][nt].x, acc[mt][nt].y);
          if (MODE & (M_BIAS | M_TB)) { v.x += bv.x; v.y += bv.y; }
          if (MODE & M_ADDC) {
            float2 cv = *(const float2*)(g_out2 + (size_t)r * 128 + col);
            v.x += cv.x; v.y += cv.y;
          }
          if (MODE & M_LEAKY) { v.x = lrelu(v.x); v.y = lrelu(v.y); }
          if (MODE & M_CVT)   { v.x = tf32r(v.x); v.y = tf32r(v.y); }
          *(float2*)(out + (size_t)r * 128 + col) = v;
          if (MODE & (M_ST1 | M_ST2)) {
            csum.x += v.x; csum.y += v.y;
            csq.x += v.x * v.x; csq.y += v.y * v.y;
          }
          if (MODE & (M_ATT8 | M_ATT1)) {
            pa_s[mt][hh] = fmaf(v.x, av_s.x, fmaf(v.y, av_s.y, pa_s[mt][hh]));
            pa_d[mt][hh] = fmaf(v.x, av_d.x, fmaf(v.y, av_d.y, pa_d[mt][hh]));
          }
        }
      }
    }

    if (MODE & (M_ST1 | M_ST2)) {
      atomicAdd(&sstat[col], csum.x);
      atomicAdd(&sstat[col + 1], csum.y);
      atomicAdd(&sstat[128 + col], csq.x);
      atomicAdd(&sstat[128 + col + 1], csq.y);
    }

    if ((MODE & M_ATT8) && (nt & 1)) {
      int head = warp_n * 4 + (nt >> 1);
#pragma unroll
      for (int mt = 0; mt < 2; mt++) {
#pragma unroll
        for (int hh = 0; hh < 2; hh++) {
          float ps = pa_s[mt][hh], pd = pa_d[mt][hh];
          ps += __shfl_xor_sync(0xffffffffu, ps, 1);
          ps += __shfl_xor_sync(0xffffffffu, ps, 2);
          pd += __shfl_xor_sync(0xffffffffu, pd, 1);
          pd += __shfl_xor_sync(0xffffffffu, pd, 2);
          int r = row0 + warp_m * 32 + mt * 16 + gr + hh * 8;
          if (gc == 0 && r < NN) {
            g_as1[(size_t)r * 8 + head] = ps;
            g_ad1[(size_t)r * 8 + head] = pd;
          }
          pa_s[mt][hh] = 0.f;
          pa_d[mt][hh] = 0.f;
        }
      }
    }
  }

  if (MODE & M_ATT1) {
#pragma unroll
    for (int mt = 0; mt < 2; mt++) {
#pragma unroll
      for (int hh = 0; hh < 2; hh++) {
        float ps = pa_s[mt][hh], pd = pa_d[mt][hh];
        ps += __shfl_xor_sync(0xffffffffu, ps, 1);
        ps += __shfl_xor_sync(0xffffffffu, ps, 2);
        pd += __shfl_xor_sync(0xffffffffu, pd, 1);
        pd += __shfl_xor_sync(0xffffffffu, pd, 2);
        int r = row0 + warp_m * 32 + mt * 16 + gr + hh * 8;
        if (gc == 0 && r < NN) {
          atomicAdd(&g_as2[r], ps);
          atomicAdd(&g_ad2[r], pd);
        }
      }
    }
  }

  if (MODE & (M_ST1 | M_ST2)) {
    __syncthreads();
    float* gst = (MODE & M_ST1) ? g_stats1 : g_stats2;
    atomicAdd(&gst[tid], sstat[tid]);
  }
}

// ---------------- BN1 finalize + fold into W1 ----------------
__global__ __launch_bounds__(128) void k_bnprep(const float* __restrict__ gamma,
                                                const float* __restrict__ beta,
                                                const float* __restrict__ W1) {
  __shared__ float ssc[128], ssh[128];
  int t = threadIdx.x;
  float mean = g_stats1[t] * (1.f / NN);
  float var = g_stats1[128 + t] * (1.f / NN) - mean * mean;
  float sc = rsqrtf(var + 1e-5f) * gamma[t];
  float sh = beta[t] - mean * sc;
  ssc[t] = sc; ssh[t] = sh;
  __syncthreads();
  float tb = 0.f;
  for (int k = 0; k < 128; k++) {
    float w = W1[k * 128 + t];
    g_w1p[k * 128 + t] = tf32r(ssc[k] * w);
    tb = fmaf(ssh[k], w, tb);
  }
  g_t1bias[t] = tb;
}

// ---------------- BN2 finalize ----------------
__global__ void k_bnfin2(const float* __restrict__ gamma, const float* __restrict__ beta) {
  int i = threadIdx.x;
  float mean = g_stats2[i] * (1.f / NN);
  float var = g_stats2[128 + i] * (1.f / NN) - mean * mean;
  float sc = rsqrtf(var + 1e-5f) * gamma[i];
  g_sc2[i] = sc;
  g_sh2[i] = beta[i] - mean * sc;
}

template <int H>
__device__ __forceinline__ void load_as(float* dst, const float* __restrict__ p, int s) {
  if constexpr (H == 8) {
    float4 a = __ldg((const float4*)(p + (size_t)s * 8));
    float4 b = __ldg((const float4*)(p + (size_t)s * 8 + 4));
    dst[0] = a.x; dst[1] = a.y; dst[2] = a.z; dst[3] = a.w;
    dst[4] = b.x; dst[5] = b.y; dst[6] = b.z; dst[7] = b.w;
  } else {
    dst[0] = __ldg(p + s);
  }
}

// ---------------- GAT aggregation: WARP per node, online softmax ----------------
template <int H, bool LK, bool CVT>
__global__ __launch_bounds__(256) void k_gat(const float* __restrict__ bias) {
  const float* t   = (H == 8) ? g_t1  : g_t2;
  const float* asv = (H == 8) ? g_as1 : g_as2;
  const float* adv = (H == 8) ? g_ad1 : g_ad2;
  float* out       = (H == 8) ? g_skip : g_out2;

  int lane = threadIdx.x & 31, warp = threadIdx.x >> 5;
  int node = blockIdx.x * 8 + warp;
  if (node >= NN) return;
  int beg = g_rs[node];
  int cnt = g_deg[node];
  int myh = (H == 8) ? (lane >> 2) : 0;

  __shared__ float salpha[8][H * 33];

  float ad[H];
  load_as<H>(ad, adv, node);

  float m[H], den[H];
#pragma unroll
  for (int h = 0; h < H; h++) { m[h] = -1e30f; den[h] = 0.f; }
  float4 acc = make_float4(0.f, 0.f, 0.f, 0.f);

  for (int base = 0; base < cnt; base += 32) {
    int c = min(32, cnt - base);

    int s = 0;
    float e[H];
    if (lane < c) {
      s = __ldg(&g_sby[beg + base + lane]);
      float av[H];
      load_as<H>(av, asv, s);
#pragma unroll
      for (int h = 0; h < H; h++) e[h] = lrelu(av[h] + ad[h]);
    } else {
#pragma unroll
      for (int h = 0; h < H; h++) e[h] = -1e30f;
    }

    float cm[H];
#pragma unroll
    for (int h = 0; h < H; h++) {
      cm[h] = e[h];
#pragma unroll
      for (int o = 16; o; o >>= 1) cm[h] = fmaxf(cm[h], __shfl_xor_sync(0xffffffffu, cm[h], o));
    }

    float a_[H];
#pragma unroll
    for (int h = 0; h < H; h++) {
      float mn = fmaxf(m[h], cm[h]);
      float f = __expf(m[h] - mn);
      m[h] = mn;
      den[h] *= f;
      if (h == myh) { acc.x *= f; acc.y *= f; acc.z *= f; acc.w *= f; }
      a_[h] = (lane < c) ? __expf(e[h] - mn) : 0.f;
      salpha[warp][h * 33 + lane] = a_[h];
    }

#pragma unroll
    for (int h = 0; h < H; h++) {
      float sum = a_[h];
#pragma unroll
      for (int o = 16; o; o >>= 1) sum += __shfl_xor_sync(0xffffffffu, sum, o);
      den[h] += sum;
    }
    __syncwarp();

    const float* sa = &salpha[warp][myh * 33];
#pragma unroll 4
    for (int j = 0; j < c; j++) {
      int sj = __shfl_sync(0xffffffffu, s, j);
      float w = sa[j];
      float4 tv = __ldg((const float4*)(t + (size_t)sj * 128 + lane * 4));
      acc.x = fmaf(w, tv.x, acc.x);
      acc.y = fmaf(w, tv.y, acc.y);
      acc.z = fmaf(w, tv.z, acc.z);
      acc.w = fmaf(w, tv.w, acc.w);
    }
    __syncwarp();
  }

  float inv = 1.f / fmaxf(den[myh], 1e-16f);
  float4 bv = *(const float4*)(bias + lane * 4);
  float4 v;
  v.x = acc.x * inv + bv.x;
  v.y = acc.y * inv + bv.y;
  v.z = acc.z * inv + bv.z;
  v.w = acc.w * inv + bv.w;
  if (LK) { v.x = lrelu(v.x); v.y = lrelu(v.y); v.z = lrelu(v.z); v.w = lrelu(v.w); }
  if (CVT) v = tf32r4(v);
  *(float4*)(out + (size_t)node * 128 + lane * 4) = v;
}

// ---------------- final: BN2 affine + L2 row normalize (2 nodes/block) ----------------
__global__ __launch_bounds__(256) void k_final(float* __restrict__ out) {
  int node = blockIdx.x * 2 + (threadIdx.x >> 7);
  int tid = threadIdx.x & 127;
  if (node >= NN) return;
  float v = out[(size_t)node * 128 + tid] * g_sc2[tid] + g_sh2[tid];
  float q = v * v;
#pragma unroll
  for (int o = 16; o; o >>= 1) q += __shfl_xor_sync(0xffffffffu, q, o);
  __shared__ float sq[2][4];
  int half = threadIdx.x >> 7;
  if ((tid & 31) == 0) sq[half][tid >> 5] = q;
  __syncthreads();
  float tot = sq[half][0] + sq[half][1] + sq[half][2] + sq[half][3];
  float r = 1.f / fmaxf(sqrtf(tot), 1e-12f);
  out[(size_t)node * 128 + tid] = v * r;
}

}  // namespace

extern "C" void kernel_launch(void* const* d_in, const int* in_sizes, int n_in,
                              void* d_out, int out_size) {
  const float* x        = (const float*)d_in[0];
  const float* W_in     = (const float*)d_in[1];
  const float* b_in     = (const float*)d_in[2];
  const float* gamma1   = (const float*)d_in[3];
  const float* beta1    = (const float*)d_in[4];
  const float* W1       = (const float*)d_in[5];
  const float* att_src1 = (const float*)d_in[6];
  const float* att_dst1 = (const float*)d_in[7];
  const float* bias1    = (const float*)d_in[8];
  const float* W2       = (const float*)d_in[9];
  const float* att_src2 = (const float*)d_in[10];
  const float* att_dst2 = (const float*)d_in[11];
  const float* bias2    = (const float*)d_in[12];
  const float* W_skip   = (const float*)d_in[13];
  const float* b_skip   = (const float*)d_in[14];
  const float* gamma2   = (const float*)d_in[15];
  const float* beta2    = (const float*)d_in[16];
  const void*  eidx     = d_in[17];
  float* out = (float*)d_out;

  cudaFuncSetAttribute(k_gemm_tc<KIN, M_BIAS | M_LEAKY | M_CVT | M_ST1, 0>,
                       cudaFuncAttributeMaxDynamicSharedMemorySize, GEMM_SMEM);
  cudaFuncSetAttribute(k_gemm_tc<128, M_TB | M_ATT8, 1>,
                       cudaFuncAttributeMaxDynamicSharedMemorySize, GEMM_SMEM);
  cudaFuncSetAttribute(k_gemm_tc<128, M_ATT1, 2>,
                       cudaFuncAttributeMaxDynamicSharedMemorySize, GEMM_SMEM);
  cudaFuncSetAttribute(k_gemm_tc<128, M_BIAS | M_ADDC | M_ST2, 3>,
                       cudaFuncAttributeMaxDynamicSharedMemorySize, GEMM_SMEM);

  const int GB = (NN + 127) / 128;   // 391
  const int AB = (NN + 7) / 8;       // 6250

  k_zero<<<(NN + 255) / 256, 256>>>(eidx);                                     // 0
  k_roundw<<<32, 256>>>(W_in, W2, W_skip);                                     // 1
  k_edges<<<(NE + 255) / 256, 256>>>(eidx);                                    // 2
  // GEMM1: h1 = leaky(x@W_in+b_in), stats1 fused   (profiled at idx 3)
  k_gemm_tc<KIN, M_BIAS | M_LEAKY | M_CVT | M_ST1, 0>
      <<<GB, 256, GEMM_SMEM>>>(b_in, nullptr, nullptr, x, nullptr);            // 3
  k_scan<<<NB, 1024>>>();                                                      // 4
  k_scatter<<<(NE + 255) / 256, 256>>>();                                      // 5
  k_bnprep<<<1, 128>>>(gamma1, beta1, W1);                                     // 6
  // GEMM2: t1 = BN1(h1)@W1 (+t1bias), att1 fused
  k_gemm_tc<128, M_TB | M_ATT8, 1>
      <<<GB, 256, GEMM_SMEM>>>(nullptr, att_src1, att_dst1, nullptr, nullptr);
  k_gat<8, true, true><<<AB, 256>>>(bias1);
  // GEMM3: t2 = skip@W2, att2 fused
  k_gemm_tc<128, M_ATT1, 2>
      <<<GB, 256, GEMM_SMEM>>>(nullptr, att_src2, att_dst2, nullptr, nullptr);
  k_gat<1, false, false><<<AB, 256>>>(bias2);
  // GEMM4: out = skip@W_skip + b_skip + out2, stats2 fused
  k_gemm_tc<128, M_BIAS | M_ADDC | M_ST2, 3>
      <<<GB, 256, GEMM_SMEM>>>(b_skip, nullptr, nullptr, nullptr, out);
  k_bnfin2<<<1, 128>>>(gamma2, beta2);
  k_final<<<(NN + 1) / 2, 256>>>(out);
}

// round 13
// speedup vs baseline: 1.0682x; 1.0081x over previous
#include <cuda_runtime.h>

namespace {

constexpr int NN  = 50000;   // nodes
constexpr int NE  = 800000;  // edges
constexpr int KIN = 256;     // in_dim
constexpr int NB  = (NN + 1023) / 1024;  // scan blocks = 49

// ---------------- scratch (static device memory; no allocations) ----------------
__device__ float g_win[256 * 128];   // tf32-rounded W_in
__device__ float g_w1p[128 * 128];   // tf32-rounded diag(sc1)*W1
__device__ float g_w2[128 * 128];    // tf32-rounded W2
__device__ float g_wskip[128 * 128]; // tf32-rounded W_skip
__device__ float g_t1bias[128];      // sh1^T @ W1
__device__ float g_h1[NN * 128];     // leaky(x@W_in+b_in), tf32-rounded
__device__ float g_t1[NN * 128];     // BN1(h1) @ W1
__device__ float g_skip[NN * 128];   // leaky(gat1 + bias1), tf32-rounded
__device__ float g_t2[NN * 128];     // skip @ W2
__device__ float g_out2[NN * 128];   // gat2 + bias2
__device__ float g_as1[NN * 8];
__device__ float g_ad1[NN * 8];
__device__ float g_as2[NN];
__device__ float g_ad2[NN];
__device__ int   g_src[NE];
__device__ int   g_dst[NE];
__device__ int   g_sby[NE];          // src ids sorted by dst (CSR order)
__device__ int   g_deg[NN];
__device__ int   g_cur[NN];
__device__ int   g_rs[NN + 1];       // CSR row starts (disjoint regions)
__device__ int   g_ctr;
__device__ float g_stats1[256];
__device__ float g_stats2[256];
__device__ float g_sc2[128], g_sh2[128];
__device__ int   g_is64;

__device__ __forceinline__ float lrelu(float v) { return v >= 0.f ? v : 0.2f * v; }

__device__ __forceinline__ float tf32r(float f) {
  unsigned u;
  asm("cvt.rna.tf32.f32 %0, %1;" : "=r"(u) : "f"(f));
  return __uint_as_float(u);
}
__device__ __forceinline__ float4 tf32r4(float4 v) {
  return make_float4(tf32r(v.x), tf32r(v.y), tf32r(v.z), tf32r(v.w));
}

// ---------------- setup: zero + dtype detect ----------------
__global__ void k_zero(const void* __restrict__ ei) {
  int i = blockIdx.x * 256 + threadIdx.x;
  if (i < NN) { g_deg[i] = 0; g_cur[i] = 0; g_as2[i] = 0.f; g_ad2[i] = 0.f; }
  if (i < 256) { g_stats1[i] = 0.f; g_stats2[i] = 0.f; }
  if (blockIdx.x == 0 && threadIdx.x == 0) {
    g_ctr = 0;
    const long long* p = (const long long*)ei;
    int ok = 1;
    for (int j = 0; j < 64; j++) {
      long long v = p[j];
      if (v < 0 || v >= NN) { ok = 0; break; }
    }
    g_is64 = ok;
  }
}

__global__ void k_edges(const void* __restrict__ ei) {
  int i = blockIdx.x * 256 + threadIdx.x;
  if (i < NE) {
    int s, d;
    if (g_is64) {
      const long long* p = (const long long*)ei;
      s = (int)p[i];
      d = (int)p[NE + i];
    } else {
      const int* p = (const int*)ei;
      s = p[i];
      d = p[NE + i];
    }
    if ((unsigned)s >= NN) s = 0;
    if ((unsigned)d >= NN) d = 0;
    g_src[i] = s;
    g_dst[i] = d;
    atomicAdd(&g_deg[d], 1);
  }
}

__global__ void k_scan() {
  int t = threadIdx.x;
  int i = blockIdx.x * 1024 + t;
  int v = (i < NN) ? g_deg[i] : 0;
  __shared__ int sb[1024];
  __shared__ int sbase;
  sb[t] = v;
  __syncthreads();
  for (int o = 1; o < 1024; o <<= 1) {
    int x = (t >= o) ? sb[t - o] : 0;
    __syncthreads();
    sb[t] += x;
    __syncthreads();
  }
  if (t == 1023) sbase = atomicAdd(&g_ctr, sb[1023]);
  __syncthreads();
  if (i < NN) g_rs[i] = sbase + sb[t] - v;
}

__global__ void k_scatter() {
  int i = blockIdx.x * 256 + threadIdx.x;
  if (i < NE) {
    int d = g_dst[i];
    int p = atomicAdd(&g_cur[d], 1);
    g_sby[g_rs[d] + p] = g_src[i];
  }
}

// ---------------- round W_in / W2 / W_skip to tf32 (tiny) ----------------
__global__ __launch_bounds__(256) void k_roundw(const float* __restrict__ Win,
                                                const float* __restrict__ W2,
                                                const float* __restrict__ Wsk) {
  int i = blockIdx.x * 256 + threadIdx.x;   // float4 index
  if (i < 8192)
    *(float4*)(g_win + i * 4) = tf32r4(*(const float4*)(Win + i * 4));
  if (i < 4096) {
    *(float4*)(g_w2 + i * 4)    = tf32r4(*(const float4*)(W2 + i * 4));
    *(float4*)(g_wskip + i * 4) = tf32r4(*(const float4*)(Wsk + i * 4));
  }
}

// ---------------- TF32 tensor-core GEMM, 3-stage cp.async pipeline ----------------
constexpr int M_LEAKY = 2, M_ADDC = 4, M_BIAS = 16, M_CVT = 32, M_TB = 64;
constexpr int M_ST1 = 128, M_ST2 = 256, M_ATT8 = 512, M_ATT1 = 1024;
constexpr int ASZ = 128 * 36;
constexpr int WSZ = 32 * 136;
constexpr int TSZ = ASZ + WSZ;            // 8448 floats per stage
constexpr int NSTG = 3;
constexpr int GEMM_SMEM = TSZ * NSTG * 4; // 101376 B

__device__ __forceinline__ void mma_tf32(float4& c, const unsigned a[4], const unsigned b[2]) {
  asm volatile(
      "mma.sync.aligned.m16n8k8.row.col.f32.tf32.tf32.f32 "
      "{%0,%1,%2,%3}, {%4,%5,%6,%7}, {%8,%9}, {%0,%1,%2,%3};"
      : "+f"(c.x), "+f"(c.y), "+f"(c.z), "+f"(c.w)
      : "r"(a[0]), "r"(a[1]), "r"(a[2]), "r"(a[3]), "r"(b[0]), "r"(b[1]));
}

// SEL: 0 -> A=Araw (x, K=256, cvt at frag read), W=g_win,  out=g_h1
//      1 -> A=g_h1,  W=g_w1p,  out=g_t1
//      2 -> A=g_skip,W=g_w2,   out=g_t2
//      3 -> A=g_skip,W=g_wskip,out=outp
template <int K, int MODE, int SEL>
__global__ __launch_bounds__(256, 2) void k_gemm_tc(const float* __restrict__ bias,
                                                    const float* __restrict__ atts,
                                                    const float* __restrict__ attd,
                                                    const float* __restrict__ Araw,
                                                    float* __restrict__ outp) {
  extern __shared__ float sm[];
  __shared__ float satt[256];
  __shared__ float sstat[256];

  const float* A  = (SEL == 0) ? Araw : (SEL == 1) ? g_h1 : g_skip;
  const float* Wm = (SEL == 0) ? g_win : (SEL == 1) ? g_w1p : (SEL == 2) ? g_w2 : g_wskip;
  float* out      = (SEL == 0) ? g_h1 : (SEL == 1) ? g_t1 : (SEL == 2) ? g_t2 : outp;

  int tid = threadIdx.x;
  int lane = tid & 31, wid = tid >> 5;
  int gr = lane >> 2, gc = lane & 3;
  int warp_m = wid & 3, warp_n = wid >> 2;
  int row0 = blockIdx.x * 128;

  if (MODE & (M_ATT8 | M_ATT1)) {
    if (tid < 128) { satt[tid] = __ldg(atts + tid); satt[128 + tid] = __ldg(attd + tid); }
  }
  if (MODE & (M_ST1 | M_ST2)) sstat[tid] = 0.f;

  float4 acc[2][8];
#pragma unroll
  for (int mt = 0; mt < 2; mt++)
#pragma unroll
    for (int nt = 0; nt < 8; nt++) acc[mt][nt] = make_float4(0.f, 0.f, 0.f, 0.f);

  // issue one chunk (A + W tiles) into stage buf
  auto issue = [&](int kc, int buf) {
    float* As = sm + buf * TSZ;
    float* Ws = As + ASZ;
#pragma unroll
    for (int i = 0; i < 4; i++) {
      int idx = tid * 4 + i * 1024;
      int r = idx >> 5, c = idx & 31;
      int grow = row0 + r;
      int ok = (grow < NN);
      const float* src = A + (size_t)(ok ? grow : 0) * K + kc + c;
      unsigned dst = (unsigned)__cvta_generic_to_shared(As + r * 36 + c);
      int sz = ok ? 16 : 0;
      asm volatile("cp.async.cg.shared.global [%0], [%1], 16, %2;"
                   :: "r"(dst), "l"(src), "r"(sz));
    }
#pragma unroll
    for (int i = 0; i < 4; i++) {
      int idx = tid * 4 + i * 1024;
      int k = idx >> 7, n = idx & 127;
      const float* src = Wm + (size_t)(kc + k) * 128 + n;
      unsigned dst = (unsigned)__cvta_generic_to_shared(Ws + k * 136 + n);
      asm volatile("cp.async.cg.shared.global [%0], [%1], 16;" :: "r"(dst), "l"(src));
    }
    asm volatile("cp.async.commit_group;");
  };

  constexpr int NCH = K / 32;
  issue(0, 0);
  if (NCH > 1) issue(32, 1);

  for (int ch = 0; ch < NCH; ch++) {
    if (ch == NCH - 1) asm volatile("cp.async.wait_group 0;" ::: "memory");
    else               asm volatile("cp.async.wait_group 1;" ::: "memory");
    __syncthreads();
    if (ch + 2 < NCH) issue((ch + 2) * 32, (ch + 2) % NSTG);

    const float* As = sm + (ch % NSTG) * TSZ;
    const float* Ws = As + ASZ;
#pragma unroll
    for (int kk = 0; kk < 32; kk += 8) {
      unsigned a[2][4];
#pragma unroll
      for (int mt = 0; mt < 2; mt++) {
        int rb = warp_m * 32 + mt * 16;
        if (SEL == 0) {
          // raw fp32 in smem: round to tf32 at fragment read (same value enters MMA)
          a[mt][0] = __float_as_uint(tf32r(As[(rb + gr)     * 36 + kk + gc]));
          a[mt][1] = __float_as_uint(tf32r(As[(rb + gr + 8) * 36 + kk + gc]));
          a[mt][2] = __float_as_uint(tf32r(As[(rb + gr)     * 36 + kk + gc + 4]));
          a[mt][3] = __float_as_uint(tf32r(As[(rb + gr + 8) * 36 + kk + gc + 4]));
        } else {
          a[mt][0] = __float_as_uint(As[(rb + gr)     * 36 + kk + gc]);
          a[mt][1] = __float_as_uint(As[(rb + gr + 8) * 36 + kk + gc]);
          a[mt][2] = __float_as_uint(As[(rb + gr)     * 36 + kk + gc + 4]);
          a[mt][3] = __float_as_uint(As[(rb + gr + 8) * 36 + kk + gc + 4]);
        }
      }
      unsigned b[8][2];
#pragma unroll
      for (int nt = 0; nt < 8; nt++) {
        int n = warp_n * 64 + nt * 8 + gr;
        b[nt][0] = __float_as_uint(Ws[(kk + gc)     * 136 + n]);
        b[nt][1] = __float_as_uint(Ws[(kk + gc + 4) * 136 + n]);
      }
#pragma unroll
      for (int mt = 0; mt < 2; mt++)
#pragma unroll
        for (int nt = 0; nt < 8; nt++) mma_tf32(acc[mt][nt], a[mt], b[nt]);
    }
  }

  __syncthreads();  // protect sstat/satt reuse below vs main loop (none) & ensure all MMA done per-thread anyway

  // ---------------- fused epilogue: store + bias/addC/leaky/cvt + stats + att ----------------
  float pa_s[2][2] = {{0.f, 0.f}, {0.f, 0.f}};
  float pa_d[2][2] = {{0.f, 0.f}, {0.f, 0.f}};

#pragma unroll
  for (int nt = 0; nt < 8; nt++) {
    int col = warp_n * 64 + nt * 8 + gc * 2;
    float2 bv = make_float2(0.f, 0.f);
    if (MODE & M_BIAS) bv = *(const float2*)(bias + col);
    if (MODE & M_TB)   bv = *(const float2*)(g_t1bias + col);
    float2 av_s = make_float2(0.f, 0.f), av_d = make_float2(0.f, 0.f);
    if (MODE & (M_ATT8 | M_ATT1)) {
      av_s = *(const float2*)&satt[col];
      av_d = *(const float2*)&satt[128 + col];
    }
    float2 csum = make_float2(0.f, 0.f), csq = make_float2(0.f, 0.f);

#pragma unroll
    for (int mt = 0; mt < 2; mt++) {
#pragma unroll
      for (int hh = 0; hh < 2; hh++) {
        int r = row0 + warp_m * 32 + mt * 16 + gr + hh * 8;
        if (r < NN) {
          float2 v = hh ? make_float2(acc[mt][nt].z, acc[mt][nt].w)
                        : make_float2(acc[mt][nt].x, acc[mt][nt].y);
          if (MODE & (M_BIAS | M_TB)) { v.x += bv.x; v.y += bv.y; }
          if (MODE & M_ADDC) {
            float2 cv = *(const float2*)(g_out2 + (size_t)r * 128 + col);
            v.x += cv.x; v.y += cv.y;
          }
          if (MODE & M_LEAKY) { v.x = lrelu(v.x); v.y = lrelu(v.y); }
          if (MODE & M_CVT)   { v.x = tf32r(v.x); v.y = tf32r(v.y); }
          *(float2*)(out + (size_t)r * 128 + col) = v;
          if (MODE & (M_ST1 | M_ST2)) {
            csum.x += v.x; csum.y += v.y;
            csq.x += v.x * v.x; csq.y += v.y * v.y;
          }
          if (MODE & (M_ATT8 | M_ATT1)) {
            pa_s[mt][hh] = fmaf(v.x, av_s.x, fmaf(v.y, av_s.y, pa_s[mt][hh]));
            pa_d[mt][hh] = fmaf(v.x, av_d.x, fmaf(v.y, av_d.y, pa_d[mt][hh]));
          }
        }
      }
    }

    if (MODE & (M_ST1 | M_ST2)) {
      atomicAdd(&sstat[col], csum.x);
      atomicAdd(&sstat[col + 1], csum.y);
      atomicAdd(&sstat[128 + col], csq.x);
      atomicAdd(&sstat[128 + col + 1], csq.y);
    }

    if ((MODE & M_ATT8) && (nt & 1)) {
      int head = warp_n * 4 + (nt >> 1);
#pragma unroll
      for (int mt = 0; mt < 2; mt++) {
#pragma unroll
        for (int hh = 0; hh < 2; hh++) {
          float ps = pa_s[mt][hh], pd = pa_d[mt][hh];
          ps += __shfl_xor_sync(0xffffffffu, ps, 1);
          ps += __shfl_xor_sync(0xffffffffu, ps, 2);
          pd += __shfl_xor_sync(0xffffffffu, pd, 1);
          pd += __shfl_xor_sync(0xffffffffu, pd, 2);
          int r = row0 + warp_m * 32 + mt * 16 + gr + hh * 8;
          if (gc == 0 && r < NN) {
            g_as1[(size_t)r * 8 + head] = ps;
            g_ad1[(size_t)r * 8 + head] = pd;
          }
          pa_s[mt][hh] = 0.f;
          pa_d[mt][hh] = 0.f;
        }
      }
    }
  }

  if (MODE & M_ATT1) {
#pragma unroll
    for (int mt = 0; mt < 2; mt++) {
#pragma unroll
      for (int hh = 0; hh < 2; hh++) {
        float ps = pa_s[mt][hh], pd = pa_d[mt][hh];
        ps += __shfl_xor_sync(0xffffffffu, ps, 1);
        ps += __shfl_xor_sync(0xffffffffu, ps, 2);
        pd += __shfl_xor_sync(0xffffffffu, pd, 1);
        pd += __shfl_xor_sync(0xffffffffu, pd, 2);
        int r = row0 + warp_m * 32 + mt * 16 + gr + hh * 8;
        if (gc == 0 && r < NN) {
          atomicAdd(&g_as2[r], ps);
          atomicAdd(&g_ad2[r], pd);
        }
      }
    }
  }

  if (MODE & (M_ST1 | M_ST2)) {
    __syncthreads();
    float* gst = (MODE & M_ST1) ? g_stats1 : g_stats2;
    atomicAdd(&gst[tid], sstat[tid]);
  }
}

// ---------------- BN1 finalize + fold into W1 ----------------
__global__ __launch_bounds__(128) void k_bnprep(const float* __restrict__ gamma,
                                                const float* __restrict__ beta,
                                                const float* __restrict__ W1) {
  __shared__ float ssc[128], ssh[128];
  int t = threadIdx.x;
  float mean = g_stats1[t] * (1.f / NN);
  float var = g_stats1[128 + t] * (1.f / NN) - mean * mean;
  float sc = rsqrtf(var + 1e-5f) * gamma[t];
  float sh = beta[t] - mean * sc;
  ssc[t] = sc; ssh[t] = sh;
  __syncthreads();
  float tb = 0.f;
  for (int k = 0; k < 128; k++) {
    float w = W1[k * 128 + t];
    g_w1p[k * 128 + t] = tf32r(ssc[k] * w);
    tb = fmaf(ssh[k], w, tb);
  }
  g_t1bias[t] = tb;
}

// ---------------- BN2 finalize ----------------
__global__ void k_bnfin2(const float* __restrict__ gamma, const float* __restrict__ beta) {
  int i = threadIdx.x;
  float mean = g_stats2[i] * (1.f / NN);
  float var = g_stats2[128 + i] * (1.f / NN) - mean * mean;
  float sc = rsqrtf(var + 1e-5f) * gamma[i];
  g_sc2[i] = sc;
  g_sh2[i] = beta[i] - mean * sc;
}

template <int H>
__device__ __forceinline__ void load_as(float* dst, const float* __restrict__ p, int s) {
  if constexpr (H == 8) {
    float4 a = __ldg((const float4*)(p + (size_t)s * 8));
    float4 b = __ldg((const float4*)(p + (size_t)s * 8 + 4));
    dst[0] = a.x; dst[1] = a.y; dst[2] = a.z; dst[3] = a.w;
    dst[4] = b.x; dst[5] = b.y; dst[6] = b.z; dst[7] = b.w;
  } else {
    dst[0] = __ldg(p + s);
  }
}

// ---------------- GAT aggregation: WARP per node, online softmax ----------------
template <int H, bool LK, bool CVT>
__global__ __launch_bounds__(256) void k_gat(const float* __restrict__ bias) {
  const float* t   = (H == 8) ? g_t1  : g_t2;
  const float* asv = (H == 8) ? g_as1 : g_as2;
  const float* adv = (H == 8) ? g_ad1 : g_ad2;
  float* out       = (H == 8) ? g_skip : g_out2;

  int lane = threadIdx.x & 31, warp = threadIdx.x >> 5;
  int node = blockIdx.x * 8 + warp;
  if (node >= NN) return;
  int beg = g_rs[node];
  int cnt = g_deg[node];
  int myh = (H == 8) ? (lane >> 2) : 0;

  __shared__ float salpha[8][H * 33];

  float ad[H];
  load_as<H>(ad, adv, node);

  float m[H], den[H];
#pragma unroll
  for (int h = 0; h < H; h++) { m[h] = -1e30f; den[h] = 0.f; }
  float4 acc = make_float4(0.f, 0.f, 0.f, 0.f);

  for (int base = 0; base < cnt; base += 32) {
    int c = min(32, cnt - base);

    int s = 0;
    float e[H];
    if (lane < c) {
      s = __ldg(&g_sby[beg + base + lane]);
      float av[H];
      load_as<H>(av, asv, s);
#pragma unroll
      for (int h = 0; h < H; h++) e[h] = lrelu(av[h] + ad[h]);
    } else {
#pragma unroll
      for (int h = 0; h < H; h++) e[h] = -1e30f;
    }

    float cm[H];
#pragma unroll
    for (int h = 0; h < H; h++) {
      cm[h] = e[h];
#pragma unroll
      for (int o = 16; o; o >>= 1) cm[h] = fmaxf(cm[h], __shfl_xor_sync(0xffffffffu, cm[h], o));
    }

    float a_[H];
#pragma unroll
    for (int h = 0; h < H; h++) {
      float mn = fmaxf(m[h], cm[h]);
      float f = __expf(m[h] - mn);
      m[h] = mn;
      den[h] *= f;
      if (h == myh) { acc.x *= f; acc.y *= f; acc.z *= f; acc.w *= f; }
      a_[h] = (lane < c) ? __expf(e[h] - mn) : 0.f;
      salpha[warp][h * 33 + lane] = a_[h];
    }

#pragma unroll
    for (int h = 0; h < H; h++) {
      float sum = a_[h];
#pragma unroll
      for (int o = 16; o; o >>= 1) sum += __shfl_xor_sync(0xffffffffu, sum, o);
      den[h] += sum;
    }
    __syncwarp();

    const float* sa = &salpha[warp][myh * 33];
#pragma unroll 4
    for (int j = 0; j < c; j++) {
      int sj = __shfl_sync(0xffffffffu, s, j);
      float w = sa[j];
      float4 tv = __ldg((const float4*)(t + (size_t)sj * 128 + lane * 4));
      acc.x = fmaf(w, tv.x, acc.x);
      acc.y = fmaf(w, tv.y, acc.y);
      acc.z = fmaf(w, tv.z, acc.z);
      acc.w = fmaf(w, tv.w, acc.w);
    }
    __syncwarp();
  }

  float inv = 1.f / fmaxf(den[myh], 1e-16f);
  float4 bv = *(const float4*)(bias + lane * 4);
  float4 v;
  v.x = acc.x * inv + bv.x;
  v.y = acc.y * inv + bv.y;
  v.z = acc.z * inv + bv.z;
  v.w = acc.w * inv + bv.w;
  if (LK) { v.x = lrelu(v.x); v.y = lrelu(v.y); v.z = lrelu(v.z); v.w = lrelu(v.w); }
  if (CVT) v = tf32r4(v);
  *(float4*)(out + (size_t)node * 128 + lane * 4) = v;
}

// ---------------- final: BN2 affine + L2 row normalize (2 nodes/block) ----------------
__global__ __launch_bounds__(256) void k_final(float* __restrict__ out) {
  int node = blockIdx.x * 2 + (threadIdx.x >> 7);
  int tid = threadIdx.x & 127;
  if (node >= NN) return;
  float v = out[(size_t)node * 128 + tid] * g_sc2[tid] + g_sh2[tid];
  float q = v * v;
#pragma unroll
  for (int o = 16; o; o >>= 1) q += __shfl_xor_sync(0xffffffffu, q, o);
  __shared__ float sq[2][4];
  int half = threadIdx.x >> 7;
  if ((tid & 31) == 0) sq[half][tid >> 5] = q;
  __syncthreads();
  float tot = sq[half][0] + sq[half][1] + sq[half][2] + sq[half][3];
  float r = 1.f / fmaxf(sqrtf(tot), 1e-12f);
  out[(size_t)node * 128 + tid] = v * r;
}

}  // namespace

extern "C" void kernel_launch(void* const* d_in, const int* in_sizes, int n_in,
                              void* d_out, int out_size) {
  const float* x        = (const float*)d_in[0];
  const float* W_in     = (const float*)d_in[1];
  const float* b_in     = (const float*)d_in[2];
  const float* gamma1   = (const float*)d_in[3];
  const float* beta1    = (const float*)d_in[4];
  const float* W1       = (const float*)d_in[5];
  const float* att_src1 = (const float*)d_in[6];
  const float* att_dst1 = (const float*)d_in[7];
  const float* bias1    = (const float*)d_in[8];
  const float* W2       = (const float*)d_in[9];
  const float* att_src2 = (const float*)d_in[10];
  const float* att_dst2 = (const float*)d_in[11];
  const float* bias2    = (const float*)d_in[12];
  const float* W_skip   = (const float*)d_in[13];
  const float* b_skip   = (const float*)d_in[14];
  const float* gamma2   = (const float*)d_in[15];
  const float* beta2    = (const float*)d_in[16];
  const void*  eidx     = d_in[17];
  float* out = (float*)d_out;

  cudaFuncSetAttribute(k_gemm_tc<KIN, M_BIAS | M_LEAKY | M_CVT | M_ST1, 0>,
                       cudaFuncAttributeMaxDynamicSharedMemorySize, GEMM_SMEM);
  cudaFuncSetAttribute(k_gemm_tc<128, M_TB | M_ATT8, 1>,
                       cudaFuncAttributeMaxDynamicSharedMemorySize, GEMM_SMEM);
  cudaFuncSetAttribute(k_gemm_tc<128, M_ATT1, 2>,
                       cudaFuncAttributeMaxDynamicSharedMemorySize, GEMM_SMEM);
  cudaFuncSetAttribute(k_gemm_tc<128, M_BIAS | M_ADDC | M_ST2, 3>,
                       cudaFuncAttributeMaxDynamicSharedMemorySize, GEMM_SMEM);

  const int GB = (NN + 127) / 128;   // 391
  const int AB = (NN + 7) / 8;       // 6250

  k_zero<<<(NN + 255) / 256, 256>>>(eidx);                                     // 0
  k_roundw<<<32, 256>>>(W_in, W2, W_skip);                                     // 1
  k_edges<<<(NE + 255) / 256, 256>>>(eidx);                                    // 2
  // GEMM1: h1 = leaky(x@W_in+b_in), stats1 fused   (profiled at idx 3)
  k_gemm_tc<KIN, M_BIAS | M_LEAKY | M_CVT | M_ST1, 0>
      <<<GB, 256, GEMM_SMEM>>>(b_in, nullptr, nullptr, x, nullptr);            // 3
  k_scan<<<NB, 1024>>>();                                                      // 4
  k_scatter<<<(NE + 255) / 256, 256>>>();                                      // 5
  k_bnprep<<<1, 128>>>(gamma1, beta1, W1);                                     // 6
  // GEMM2: t1 = BN1(h1)@W1 (+t1bias), att1 fused
  k_gemm_tc<128, M_TB | M_ATT8, 1>
      <<<GB, 256, GEMM_SMEM>>>(nullptr, att_src1, att_dst1, nullptr, nullptr);
  k_gat<8, true, true><<<AB, 256>>>(bias1);
  // GEMM3: t2 = skip@W2, att2 fused
  k_gemm_tc<128, M_ATT1, 2>
      <<<GB, 256, GEMM_SMEM>>>(nullptr, att_src2, att_dst2, nullptr, nullptr);
  k_gat<1, false, false><<<AB, 256>>>(bias2);
  // GEMM4: out = skip@W_skip + b_skip + out2, stats2 fused
  k_gemm_tc<128, M_BIAS | M_ADDC | M_ST2, 3>
      <<<GB, 256, GEMM_SMEM>>>(b_skip, nullptr, nullptr, nullptr, out);
  k_bnfin2<<<1, 128>>>(gamma2, beta2);
  k_final<<<(NN + 1) / 2, 256>>>(out);
}

// round 14
// speedup vs baseline: 1.1262x; 1.0543x over previous
#include <cuda_runtime.h>

namespace {

constexpr int NN  = 50000;   // nodes
constexpr int NE  = 800000;  // edges
constexpr int KIN = 256;     // in_dim
constexpr int NB  = (NN + 1023) / 1024;  // scan blocks = 49

// ---------------- scratch (static device memory; no allocations) ----------------
__device__ float g_win[256 * 128];   // tf32-rounded W_in
__device__ float g_w1p[128 * 128];   // tf32-rounded diag(sc1)*W1
__device__ float g_w2[128 * 128];    // tf32-rounded W2
__device__ float g_wskip[128 * 128]; // tf32-rounded W_skip
__device__ float g_t1bias[128];      // sh1^T @ W1
__device__ float g_h1[NN * 128];     // leaky(x@W_in+b_in), tf32-rounded
__device__ float g_t1[NN * 128];     // BN1(h1) @ W1
__device__ float g_skip[NN * 128];   // leaky(gat1 + bias1), tf32-rounded
__device__ float g_t2[NN * 128];     // skip @ W2
__device__ float g_out2[NN * 128];   // gat2 + bias2
__device__ float g_as1[NN * 8];
__device__ float g_ad1[NN * 8];
__device__ float g_as2[NN];
__device__ float g_ad2[NN];
__device__ int   g_src[NE];
__device__ int   g_dst[NE];
__device__ int   g_sby[NE];          // src ids sorted by dst (CSR order)
__device__ int   g_deg[NN];
__device__ int   g_cur[NN];
__device__ int   g_rs[NN + 1];       // CSR row starts (disjoint regions)
__device__ int   g_ctr;
__device__ float g_stats1[256];
__device__ float g_stats2[256];
__device__ float g_sc2[128], g_sh2[128];
__device__ int   g_is64;

__device__ __forceinline__ float lrelu(float v) { return v >= 0.f ? v : 0.2f * v; }

__device__ __forceinline__ float tf32r(float f) {
  unsigned u;
  asm("cvt.rna.tf32.f32 %0, %1;" : "=r"(u) : "f"(f));
  return __uint_as_float(u);
}
__device__ __forceinline__ float4 tf32r4(float4 v) {
  return make_float4(tf32r(v.x), tf32r(v.y), tf32r(v.z), tf32r(v.w));
}

// ---------------- setup: zero + dtype detect ----------------
__global__ void k_zero(const void* __restrict__ ei) {
  int i = blockIdx.x * 256 + threadIdx.x;
  if (i < NN) { g_deg[i] = 0; g_cur[i] = 0; g_as2[i] = 0.f; g_ad2[i] = 0.f; }
  if (i < 256) { g_stats1[i] = 0.f; g_stats2[i] = 0.f; }
  if (blockIdx.x == 0 && threadIdx.x == 0) {
    g_ctr = 0;
    const long long* p = (const long long*)ei;
    int ok = 1;
    for (int j = 0; j < 64; j++) {
      long long v = p[j];
      if (v < 0 || v >= NN) { ok = 0; break; }
    }
    g_is64 = ok;
  }
}

__global__ void k_edges(const void* __restrict__ ei) {
  int i = blockIdx.x * 256 + threadIdx.x;
  if (i < NE) {
    int s, d;
    if (g_is64) {
      const long long* p = (const long long*)ei;
      s = (int)p[i];
      d = (int)p[NE + i];
    } else {
      const int* p = (const int*)ei;
      s = p[i];
      d = p[NE + i];
    }
    if ((unsigned)s >= NN) s = 0;
    if ((unsigned)d >= NN) d = 0;
    g_src[i] = s;
    g_dst[i] = d;
    atomicAdd(&g_deg[d], 1);
  }
}

__global__ void k_scan() {
  int t = threadIdx.x;
  int i = blockIdx.x * 1024 + t;
  int v = (i < NN) ? g_deg[i] : 0;
  __shared__ int sb[1024];
  __shared__ int sbase;
  sb[t] = v;
  __syncthreads();
  for (int o = 1; o < 1024; o <<= 1) {
    int x = (t >= o) ? sb[t - o] : 0;
    __syncthreads();
    sb[t] += x;
    __syncthreads();
  }
  if (t == 1023) sbase = atomicAdd(&g_ctr, sb[1023]);
  __syncthreads();
  if (i < NN) g_rs[i] = sbase + sb[t] - v;
}

__global__ void k_scatter() {
  int i = blockIdx.x * 256 + threadIdx.x;
  if (i < NE) {
    int d = g_dst[i];
    int p = atomicAdd(&g_cur[d], 1);
    g_sby[g_rs[d] + p] = g_src[i];
  }
}

// ---------------- round W_in / W2 / W_skip to tf32 (tiny) ----------------
__global__ __launch_bounds__(256) void k_roundw(const float* __restrict__ Win,
                                                const float* __restrict__ W2,
                                                const float* __restrict__ Wsk) {
  int i = blockIdx.x * 256 + threadIdx.x;   // float4 index
  if (i < 8192)
    *(float4*)(g_win + i * 4) = tf32r4(*(const float4*)(Win + i * 4));
  if (i < 4096) {
    *(float4*)(g_w2 + i * 4)    = tf32r4(*(const float4*)(W2 + i * 4));
    *(float4*)(g_wskip + i * 4) = tf32r4(*(const float4*)(Wsk + i * 4));
  }
}

// ---------------- TF32 tensor-core GEMM: block 128x64, BK=16, 4-stage pipeline ----------------
constexpr int M_LEAKY = 2, M_ADDC = 4, M_BIAS = 16, M_CVT = 32, M_TB = 64;
constexpr int M_ST1 = 128, M_ST2 = 256, M_ATT8 = 512, M_ATT1 = 1024;
constexpr int ASZ = 128 * 20;             // A stage: 128 rows x 16 k (pad 20)
constexpr int WSZ = 16 * 72;              // W stage: 16 k x 64 n (pad 72)
constexpr int TSZ = ASZ + WSZ;            // 3712 floats per stage
constexpr int NSTG = 4;
constexpr int GEMM_SMEM = TSZ * NSTG * 4; // 59392 B

__device__ __forceinline__ void mma_tf32(float4& c, const unsigned a[4], const unsigned b[2]) {
  asm volatile(
      "mma.sync.aligned.m16n8k8.row.col.f32.tf32.tf32.f32 "
      "{%0,%1,%2,%3}, {%4,%5,%6,%7}, {%8,%9}, {%0,%1,%2,%3};"
      : "+f"(c.x), "+f"(c.y), "+f"(c.z), "+f"(c.w)
      : "r"(a[0]), "r"(a[1]), "r"(a[2]), "r"(a[3]), "r"(b[0]), "r"(b[1]));
}

// SEL: 0 -> A=Araw (x, K=256, cvt at frag read), W=g_win,  out=g_h1
//      1 -> A=g_h1,  W=g_w1p,  out=g_t1
//      2 -> A=g_skip,W=g_w2,   out=g_t2
//      3 -> A=g_skip,W=g_wskip,out=outp
// grid: 2 blocks per 128-row tile; bx&1 selects the 64-col half.
template <int K, int MODE, int SEL>
__global__ __launch_bounds__(256, 3) void k_gemm_tc(const float* __restrict__ bias,
                                                    const float* __restrict__ atts,
                                                    const float* __restrict__ attd,
                                                    const float* __restrict__ Araw,
                                                    float* __restrict__ outp) {
  extern __shared__ float sm[];
  __shared__ float satt[256];
  __shared__ float sstat[256];

  const float* A  = (SEL == 0) ? Araw : (SEL == 1) ? g_h1 : g_skip;
  const float* Wm = (SEL == 0) ? g_win : (SEL == 1) ? g_w1p : (SEL == 2) ? g_w2 : g_wskip;
  float* out      = (SEL == 0) ? g_h1 : (SEL == 1) ? g_t1 : (SEL == 2) ? g_t2 : outp;

  int tid = threadIdx.x;
  int lane = tid & 31, wid = tid >> 5;
  int gr = lane >> 2, gc = lane & 3;
  int warp_m = wid & 3, warp_n = wid >> 2;   // 4 m-warps x 2 n-warps
  int row0 = (blockIdx.x >> 1) * 128;
  int ncol0 = (blockIdx.x & 1) * 64;

  if (MODE & (M_ATT8 | M_ATT1)) {
    if (tid < 128) { satt[tid] = __ldg(atts + tid); satt[128 + tid] = __ldg(attd + tid); }
  }
  if (MODE & (M_ST1 | M_ST2)) sstat[tid] = 0.f;

  float4 acc[2][4];
#pragma unroll
  for (int mt = 0; mt < 2; mt++)
#pragma unroll
    for (int nt = 0; nt < 4; nt++) acc[mt][nt] = make_float4(0.f, 0.f, 0.f, 0.f);

  // issue one BK=16 chunk (A + W tiles) into stage buf
  auto issue = [&](int kc, int buf) {
    float* As = sm + buf * TSZ;
    float* Ws = As + ASZ;
#pragma unroll
    for (int i = 0; i < 2; i++) {
      int fidx = i * 256 + tid;              // 0..511 float4s
      int r = fidx >> 2, c4 = fidx & 3;
      int grow = row0 + r;
      int ok = (grow < NN);
      const float* src = A + (size_t)(ok ? grow : 0) * K + kc + c4 * 4;
      unsigned dst = (unsigned)__cvta_generic_to_shared(As + r * 20 + c4 * 4);
      int sz = ok ? 16 : 0;
      asm volatile("cp.async.cg.shared.global [%0], [%1], 16, %2;"
                   :: "r"(dst), "l"(src), "r"(sz));
    }
    {
      int k = tid >> 4, n4 = tid & 15;       // 256 float4s = 16k x 64n
      const float* src = Wm + (size_t)(kc + k) * 128 + ncol0 + n4 * 4;
      unsigned dst = (unsigned)__cvta_generic_to_shared(Ws + k * 72 + n4 * 4);
      asm volatile("cp.async.cg.shared.global [%0], [%1], 16;" :: "r"(dst), "l"(src));
    }
    asm volatile("cp.async.commit_group;");
  };

  constexpr int NCH = K / 16;
  issue(0, 0);
  issue(16, 1);
  issue(32, 2);

  for (int ch = 0; ch < NCH; ch++) {
    int rem = NCH - ch - 1;
    if (rem >= 2)      asm volatile("cp.async.wait_group 2;" ::: "memory");
    else if (rem == 1) asm volatile("cp.async.wait_group 1;" ::: "memory");
    else               asm volatile("cp.async.wait_group 0;" ::: "memory");
    __syncthreads();
    if (ch + 3 < NCH) issue((ch + 3) * 16, (ch + 3) % NSTG);

    const float* As = sm + (ch % NSTG) * TSZ;
    const float* Ws = As + ASZ;
#pragma unroll
    for (int kk = 0; kk < 16; kk += 8) {
      unsigned a[2][4];
#pragma unroll
      for (int mt = 0; mt < 2; mt++) {
        int rb = warp_m * 32 + mt * 16;
        if (SEL == 0) {
          a[mt][0] = __float_as_uint(tf32r(As[(rb + gr)     * 20 + kk + gc]));
          a[mt][1] = __float_as_uint(tf32r(As[(rb + gr + 8) * 20 + kk + gc]));
          a[mt][2] = __float_as_uint(tf32r(As[(rb + gr)     * 20 + kk + gc + 4]));
          a[mt][3] = __float_as_uint(tf32r(As[(rb + gr + 8) * 20 + kk + gc + 4]));
        } else {
          a[mt][0] = __float_as_uint(As[(rb + gr)     * 20 + kk + gc]);
          a[mt][1] = __float_as_uint(As[(rb + gr + 8) * 20 + kk + gc]);
          a[mt][2] = __float_as_uint(As[(rb + gr)     * 20 + kk + gc + 4]);
          a[mt][3] = __float_as_uint(As[(rb + gr + 8) * 20 + kk + gc + 4]);
        }
      }
      unsigned b[4][2];
#pragma unroll
      for (int nt = 0; nt < 4; nt++) {
        int n = warp_n * 32 + nt * 8 + gr;
        b[nt][0] = __float_as_uint(Ws[(kk + gc)     * 72 + n]);
        b[nt][1] = __float_as_uint(Ws[(kk + gc + 4) * 72 + n]);
      }
#pragma unroll
      for (int mt = 0; mt < 2; mt++)
#pragma unroll
        for (int nt = 0; nt < 4; nt++) mma_tf32(acc[mt][nt], a[mt], b[nt]);
    }
  }

  __syncthreads();

  // ---------------- fused epilogue ----------------
  float pa_s[2][2] = {{0.f, 0.f}, {0.f, 0.f}};
  float pa_d[2][2] = {{0.f, 0.f}, {0.f, 0.f}};

#pragma unroll
  for (int nt = 0; nt < 4; nt++) {
    int col = ncol0 + warp_n * 32 + nt * 8 + gc * 2;   // global col in [0,128)
    float2 bv = make_float2(0.f, 0.f);
    if (MODE & M_BIAS) bv = *(const float2*)(bias + col);
    if (MODE & M_TB)   bv = *(const float2*)(g_t1bias + col);
    float2 av_s = make_float2(0.f, 0.f), av_d = make_float2(0.f, 0.f);
    if (MODE & (M_ATT8 | M_ATT1)) {
      av_s = *(const float2*)&satt[col];
      av_d = *(const float2*)&satt[128 + col];
    }
    float2 csum = make_float2(0.f, 0.f), csq = make_float2(0.f, 0.f);

#pragma unroll
    for (int mt = 0; mt < 2; mt++) {
#pragma unroll
      for (int hh = 0; hh < 2; hh++) {
        int r = row0 + warp_m * 32 + mt * 16 + gr + hh * 8;
        if (r < NN) {
          float2 v = hh ? make_float2(acc[mt][nt].z, acc[mt][nt].w)
                        : make_float2(acc[mt][nt].x, acc[mt][nt].y);
          if (MODE & (M_BIAS | M_TB)) { v.x += bv.x; v.y += bv.y; }
          if (MODE & M_ADDC) {
            float2 cv = *(const float2*)(g_out2 + (size_t)r * 128 + col);
            v.x += cv.x; v.y += cv.y;
          }
          if (MODE & M_LEAKY) { v.x = lrelu(v.x); v.y = lrelu(v.y); }
          if (MODE & M_CVT)   { v.x = tf32r(v.x); v.y = tf32r(v.y); }
          *(float2*)(out + (size_t)r * 128 + col) = v;
          if (MODE & (M_ST1 | M_ST2)) {
            csum.x += v.x; csum.y += v.y;
            csq.x += v.x * v.x; csq.y += v.y * v.y;
          }
          if (MODE & (M_ATT8 | M_ATT1)) {
            pa_s[mt][hh] = fmaf(v.x, av_s.x, fmaf(v.y, av_s.y, pa_s[mt][hh]));
            pa_d[mt][hh] = fmaf(v.x, av_d.x, fmaf(v.y, av_d.y, pa_d[mt][hh]));
          }
        }
      }
    }

    if (MODE & (M_ST1 | M_ST2)) {
      atomicAdd(&sstat[col], csum.x);
      atomicAdd(&sstat[col + 1], csum.y);
      atomicAdd(&sstat[128 + col], csq.x);
      atomicAdd(&sstat[128 + col + 1], csq.y);
    }

    if ((MODE & M_ATT8) && (nt & 1)) {
      int head = (ncol0 >> 4) + warp_n * 2 + (nt >> 1);
#pragma unroll
      for (int mt = 0; mt < 2; mt++) {
#pragma unroll
        for (int hh = 0; hh < 2; hh++) {
          float ps = pa_s[mt][hh], pd = pa_d[mt][hh];
          ps += __shfl_xor_sync(0xffffffffu, ps, 1);
          ps += __shfl_xor_sync(0xffffffffu, ps, 2);
          pd += __shfl_xor_sync(0xffffffffu, pd, 1);
          pd += __shfl_xor_sync(0xffffffffu, pd, 2);
          int r = row0 + warp_m * 32 + mt * 16 + gr + hh * 8;
          if (gc == 0 && r < NN) {
            g_as1[(size_t)r * 8 + head] = ps;
            g_ad1[(size_t)r * 8 + head] = pd;
          }
          pa_s[mt][hh] = 0.f;
          pa_d[mt][hh] = 0.f;
        }
      }
    }
  }

  if (MODE & M_ATT1) {
#pragma unroll
    for (int mt = 0; mt < 2; mt++) {
#pragma unroll
      for (int hh = 0; hh < 2; hh++) {
        float ps = pa_s[mt][hh], pd = pa_d[mt][hh];
        ps += __shfl_xor_sync(0xffffffffu, ps, 1);
        ps += __shfl_xor_sync(0xffffffffu, ps, 2);
        pd += __shfl_xor_sync(0xffffffffu, pd, 1);
        pd += __shfl_xor_sync(0xffffffffu, pd, 2);
        int r = row0 + warp_m * 32 + mt * 16 + gr + hh * 8;
        if (gc == 0 && r < NN) {
          atomicAdd(&g_as2[r], ps);
          atomicAdd(&g_ad2[r], pd);
        }
      }
    }
  }

  if (MODE & (M_ST1 | M_ST2)) {
    __syncthreads();
    float* gst = (MODE & M_ST1) ? g_stats1 : g_stats2;
    atomicAdd(&gst[tid], sstat[tid]);
  }
}

// ---------------- BN1 finalize + fold into W1 ----------------
__global__ __launch_bounds__(128) void k_bnprep(const float* __restrict__ gamma,
                                                const float* __restrict__ beta,
                                                const float* __restrict__ W1) {
  __shared__ float ssc[128], ssh[128];
  int t = threadIdx.x;
  float mean = g_stats1[t] * (1.f / NN);
  float var = g_stats1[128 + t] * (1.f / NN) - mean * mean;
  float sc = rsqrtf(var + 1e-5f) * gamma[t];
  float sh = beta[t] - mean * sc;
  ssc[t] = sc; ssh[t] = sh;
  __syncthreads();
  float tb = 0.f;
  for (int k = 0; k < 128; k++) {
    float w = W1[k * 128 + t];
    g_w1p[k * 128 + t] = tf32r(ssc[k] * w);
    tb = fmaf(ssh[k], w, tb);
  }
  g_t1bias[t] = tb;
}

// ---------------- BN2 finalize ----------------
__global__ void k_bnfin2(const float* __restrict__ gamma, const float* __restrict__ beta) {
  int i = threadIdx.x;
  float mean = g_stats2[i] * (1.f / NN);
  float var = g_stats2[128 + i] * (1.f / NN) - mean * mean;
  float sc = rsqrtf(var + 1e-5f) * gamma[i];
  g_sc2[i] = sc;
  g_sh2[i] = beta[i] - mean * sc;
}

template <int H>
__device__ __forceinline__ void load_as(float* dst, const float* __restrict__ p, int s) {
  if constexpr (H == 8) {
    float4 a = __ldg((const float4*)(p + (size_t)s * 8));
    float4 b = __ldg((const float4*)(p + (size_t)s * 8 + 4));
    dst[0] = a.x; dst[1] = a.y; dst[2] = a.z; dst[3] = a.w;
    dst[4] = b.x; dst[5] = b.y; dst[6] = b.z; dst[7] = b.w;
  } else {
    dst[0] = __ldg(p + s);
  }
}

// ---------------- GAT aggregation: WARP per node, online softmax ----------------
template <int H, bool LK, bool CVT>
__global__ __launch_bounds__(256) void k_gat(const float* __restrict__ bias) {
  const float* t   = (H == 8) ? g_t1  : g_t2;
  const float* asv = (H == 8) ? g_as1 : g_as2;
  const float* adv = (H == 8) ? g_ad1 : g_ad2;
  float* out       = (H == 8) ? g_skip : g_out2;

  int lane = threadIdx.x & 31, warp = threadIdx.x >> 5;
  int node = blockIdx.x * 8 + warp;
  if (node >= NN) return;
  int beg = g_rs[node];
  int cnt = g_deg[node];
  int myh = (H == 8) ? (lane >> 2) : 0;

  __shared__ float salpha[8][H * 33];

  float ad[H];
  load_as<H>(ad, adv, node);

  float m[H], den[H];
#pragma unroll
  for (int h = 0; h < H; h++) { m[h] = -1e30f; den[h] = 0.f; }
  float4 acc = make_float4(0.f, 0.f, 0.f, 0.f);

  for (int base = 0; base < cnt; base += 32) {
    int c = min(32, cnt - base);

    int s = 0;
    float e[H];
    if (lane < c) {
      s = __ldg(&g_sby[beg + base + lane]);
      float av[H];
      load_as<H>(av, asv, s);
#pragma unroll
      for (int h = 0; h < H; h++) e[h] = lrelu(av[h] + ad[h]);
    } else {
#pragma unroll
      for (int h = 0; h < H; h++) e[h] = -1e30f;
    }

    float cm[H];
#pragma unroll
    for (int h = 0; h < H; h++) {
      cm[h] = e[h];
#pragma unroll
      for (int o = 16; o; o >>= 1) cm[h] = fmaxf(cm[h], __shfl_xor_sync(0xffffffffu, cm[h], o));
    }

    float a_[H];
#pragma unroll
    for (int h = 0; h < H; h++) {
      float mn = fmaxf(m[h], cm[h]);
      float f = __expf(m[h] - mn);
      m[h] = mn;
      den[h] *= f;
      if (h == myh) { acc.x *= f; acc.y *= f; acc.z *= f; acc.w *= f; }
      a_[h] = (lane < c) ? __expf(e[h] - mn) : 0.f;
      salpha[warp][h * 33 + lane] = a_[h];
    }

#pragma unroll
    for (int h = 0; h < H; h++) {
      float sum = a_[h];
#pragma unroll
      for (int o = 16; o; o >>= 1) sum += __shfl_xor_sync(0xffffffffu, sum, o);
      den[h] += sum;
    }
    __syncwarp();

    const float* sa = &salpha[warp][myh * 33];
#pragma unroll 4
    for (int j = 0; j < c; j++) {
      int sj = __shfl_sync(0xffffffffu, s, j);
      float w = sa[j];
      float4 tv = __ldg((const float4*)(t + (size_t)sj * 128 + lane * 4));
      acc.x = fmaf(w, tv.x, acc.x);
      acc.y = fmaf(w, tv.y, acc.y);
      acc.z = fmaf(w, tv.z, acc.z);
      acc.w = fmaf(w, tv.w, acc.w);
    }
    __syncwarp();
  }

  float inv = 1.f / fmaxf(den[myh], 1e-16f);
  float4 bv = *(const float4*)(bias + lane * 4);
  float4 v;
  v.x = acc.x * inv + bv.x;
  v.y = acc.y * inv + bv.y;
  v.z = acc.z * inv + bv.z;
  v.w = acc.w * inv + bv.w;
  if (LK) { v.x = lrelu(v.x); v.y = lrelu(v.y); v.z = lrelu(v.z); v.w = lrelu(v.w); }
  if (CVT) v = tf32r4(v);
  *(float4*)(out + (size_t)node * 128 + lane * 4) = v;
}

// ---------------- final: BN2 affine + L2 row normalize (2 nodes/block) ----------------
__global__ __launch_bounds__(256) void k_final(float* __restrict__ out) {
  int node = blockIdx.x * 2 + (threadIdx.x >> 7);
  int tid = threadIdx.x & 127;
  if (node >= NN) return;
  float v = out[(size_t)node * 128 + tid] * g_sc2[tid] + g_sh2[tid];
  float q = v * v;
#pragma unroll
  for (int o = 16; o; o >>= 1) q += __shfl_xor_sync(0xffffffffu, q, o);
  __shared__ float sq[2][4];
  int half = threadIdx.x >> 7;
  if ((tid & 31) == 0) sq[half][tid >> 5] = q;
  __syncthreads();
  float tot = sq[half][0] + sq[half][1] + sq[half][2] + sq[half][3];
  float r = 1.f / fmaxf(sqrtf(tot), 1e-12f);
  out[(size_t)node * 128 + tid] = v * r;
}

}  // namespace

extern "C" void kernel_launch(void* const* d_in, const int* in_sizes, int n_in,
                              void* d_out, int out_size) {
  const float* x        = (const float*)d_in[0];
  const float* W_in     = (const float*)d_in[1];
  const float* b_in     = (const float*)d_in[2];
  const float* gamma1   = (const float*)d_in[3];
  const float* beta1    = (const float*)d_in[4];
  const float* W1       = (const float*)d_in[5];
  const float* att_src1 = (const float*)d_in[6];
  const float* att_dst1 = (const float*)d_in[7];
  const float* bias1    = (const float*)d_in[8];
  const float* W2       = (const float*)d_in[9];
  const float* att_src2 = (const float*)d_in[10];
  const float* att_dst2 = (const float*)d_in[11];
  const float* bias2    = (const float*)d_in[12];
  const float* W_skip   = (const float*)d_in[13];
  const float* b_skip   = (const float*)d_in[14];
  const float* gamma2   = (const float*)d_in[15];
  const float* beta2    = (const float*)d_in[16];
  const void*  eidx     = d_in[17];
  float* out = (float*)d_out;

  cudaFuncSetAttribute(k_gemm_tc<KIN, M_BIAS | M_LEAKY | M_CVT | M_ST1, 0>,
                       cudaFuncAttributeMaxDynamicSharedMemorySize, GEMM_SMEM);
  cudaFuncSetAttribute(k_gemm_tc<128, M_TB | M_ATT8, 1>,
                       cudaFuncAttributeMaxDynamicSharedMemorySize, GEMM_SMEM);
  cudaFuncSetAttribute(k_gemm_tc<128, M_ATT1, 2>,
                       cudaFuncAttributeMaxDynamicSharedMemorySize, GEMM_SMEM);
  cudaFuncSetAttribute(k_gemm_tc<128, M_BIAS | M_ADDC | M_ST2, 3>,
                       cudaFuncAttributeMaxDynamicSharedMemorySize, GEMM_SMEM);

  const int GB2 = ((NN + 127) / 128) * 2;  // 782 (128-row x 64-col tiles)
  const int AB = (NN + 7) / 8;             // 6250

  k_zero<<<(NN + 255) / 256, 256>>>(eidx);                                     // 0
  k_roundw<<<32, 256>>>(W_in, W2, W_skip);                                     // 1
  k_edges<<<(NE + 255) / 256, 256>>>(eidx);                                    // 2
  // GEMM1: h1 = leaky(x@W_in+b_in), stats1 fused   (profiled at idx 3)
  k_gemm_tc<KIN, M_BIAS | M_LEAKY | M_CVT | M_ST1, 0>
      <<<GB2, 256, GEMM_SMEM>>>(b_in, nullptr, nullptr, x, nullptr);           // 3
  k_scan<<<NB, 1024>>>();                                                      // 4
  k_scatter<<<(NE + 255) / 256, 256>>>();                                      // 5
  k_bnprep<<<1, 128>>>(gamma1, beta1, W1);                                     // 6
  // GEMM2: t1 = BN1(h1)@W1 (+t1bias), att1 fused
  k_gemm_tc<128, M_TB | M_ATT8, 1>
      <<<GB2, 256, GEMM_SMEM>>>(nullptr, att_src1, att_dst1, nullptr, nullptr);
  k_gat<8, true, true><<<AB, 256>>>(bias1);
  // GEMM3: t2 = skip@W2, att2 fused
  k_gemm_tc<128, M_ATT1, 2>
      <<<GB2, 256, GEMM_SMEM>>>(nullptr, att_src2, att_dst2, nullptr, nullptr);
  k_gat<1, false, false><<<AB, 256>>>(bias2);
  // GEMM4: out = skip@W_skip + b_skip + out2, stats2 fused
  k_gemm_tc<128, M_BIAS | M_ADDC | M_ST2, 3>
      <<<GB2, 256, GEMM_SMEM>>>(b_skip, nullptr, nullptr, nullptr, out);
  k_bnfin2<<<1, 128>>>(gamma2, beta2);
  k_final<<<(NN + 1) / 2, 256>>>(out);
}

// round 15
// speedup vs baseline: 1.1819x; 1.0495x over previous
#include <cuda_runtime.h>

namespace {

constexpr int NN  = 50000;   // nodes
constexpr int NE  = 800000;  // edges
constexpr int KIN = 256;     // in_dim
constexpr int NB  = (NN + 1023) / 1024;  // scan blocks = 49

// ---------------- scratch (static device memory; no allocations) ----------------
__device__ float g_win[256 * 128];   // tf32-rounded W_in
__device__ float g_w1r[128 * 128];   // tf32-rounded W1
__device__ float g_w2[128 * 128];    // tf32-rounded W2
__device__ float g_wskip[128 * 128]; // tf32-rounded W_skip
__device__ float g_h1[NN * 128];     // leaky(x@W_in+b_in), tf32-rounded
__device__ float g_t1[NN * 128];     // BN1(h1) @ W1
__device__ float g_skip[NN * 128];   // leaky(gat1 + bias1), tf32-rounded
__device__ float g_t2[NN * 128];     // skip @ W2
__device__ float g_out2[NN * 128];   // gat2 + bias2
__device__ float g_as1[NN * 8];
__device__ float g_ad1[NN * 8];
__device__ float g_as2[NN];
__device__ float g_ad2[NN];
__device__ int   g_src[NE];
__device__ int   g_dst[NE];
__device__ int   g_sby[NE];          // src ids sorted by dst (CSR order)
__device__ int   g_deg[NN];
__device__ int   g_cur[NN];
__device__ int   g_rs[NN + 1];       // CSR row starts (disjoint regions)
__device__ int   g_ctr;
__device__ float g_stats1[256];
__device__ float g_stats2[256];
__device__ float g_sc2[128], g_sh2[128];
__device__ int   g_is64;

__device__ __forceinline__ float lrelu(float v) { return v >= 0.f ? v : 0.2f * v; }

__device__ __forceinline__ float tf32r(float f) {
  unsigned u;
  asm("cvt.rna.tf32.f32 %0, %1;" : "=r"(u) : "f"(f));
  return __uint_as_float(u);
}
__device__ __forceinline__ float4 tf32r4(float4 v) {
  return make_float4(tf32r(v.x), tf32r(v.y), tf32r(v.z), tf32r(v.w));
}

// ---------------- init: zero + dtype detect + round all weights ----------------
__global__ void k_zerow(const void* __restrict__ ei,
                        const float* __restrict__ Win, const float* __restrict__ W1,
                        const float* __restrict__ W2,  const float* __restrict__ Wsk) {
  int i = blockIdx.x * 256 + threadIdx.x;
  if (i < NN) { g_deg[i] = 0; g_cur[i] = 0; g_as2[i] = 0.f; g_ad2[i] = 0.f; }
  if (i < 256) { g_stats1[i] = 0.f; g_stats2[i] = 0.f; }
  if (i < 8192)
    *(float4*)(g_win + i * 4) = tf32r4(*(const float4*)(Win + i * 4));
  if (i < 4096) {
    *(float4*)(g_w1r + i * 4)   = tf32r4(*(const float4*)(W1 + i * 4));
    *(float4*)(g_w2 + i * 4)    = tf32r4(*(const float4*)(W2 + i * 4));
    *(float4*)(g_wskip + i * 4) = tf32r4(*(const float4*)(Wsk + i * 4));
  }
  if (blockIdx.x == 0 && threadIdx.x == 0) {
    g_ctr = 0;
    const long long* p = (const long long*)ei;
    int ok = 1;
    for (int j = 0; j < 64; j++) {
      long long v = p[j];
      if (v < 0 || v >= NN) { ok = 0; break; }
    }
    g_is64 = ok;
  }
}

__global__ void k_edges(const void* __restrict__ ei) {
  int i = blockIdx.x * 256 + threadIdx.x;
  if (i < NE) {
    int s, d;
    if (g_is64) {
      const long long* p = (const long long*)ei;
      s = (int)p[i];
      d = (int)p[NE + i];
    } else {
      const int* p = (const int*)ei;
      s = p[i];
      d = p[NE + i];
    }
    if ((unsigned)s >= NN) s = 0;
    if ((unsigned)d >= NN) d = 0;
    g_src[i] = s;
    g_dst[i] = d;
    atomicAdd(&g_deg[d], 1);
  }
}

__global__ void k_scan() {
  int t = threadIdx.x;
  int i = blockIdx.x * 1024 + t;
  int v = (i < NN) ? g_deg[i] : 0;
  __shared__ int sb[1024];
  __shared__ int sbase;
  sb[t] = v;
  __syncthreads();
  for (int o = 1; o < 1024; o <<= 1) {
    int x = (t >= o) ? sb[t - o] : 0;
    __syncthreads();
    sb[t] += x;
    __syncthreads();
  }
  if (t == 1023) sbase = atomicAdd(&g_ctr, sb[1023]);
  __syncthreads();
  if (i < NN) g_rs[i] = sbase + sb[t] - v;
}

__global__ void k_scatter() {
  int i = blockIdx.x * 256 + threadIdx.x;
  if (i < NE) {
    int d = g_dst[i];
    int p = atomicAdd(&g_cur[d], 1);
    g_sby[g_rs[d] + p] = g_src[i];
  }
}

// ---------------- TF32 tensor-core GEMM: block 128x64, BK=16, 3-stage pipeline ----------------
constexpr int M_LEAKY = 2, M_ADDC = 4, M_BIAS = 16, M_CVT = 32, M_BNA = 64;
constexpr int M_ST1 = 128, M_ST2 = 256, M_ATT8 = 512, M_ATT1 = 1024;
constexpr int ASZ = 128 * 20;             // A stage: 128 rows x 16 k (pad 20)
constexpr int WSZ = 16 * 72;              // W stage: 16 k x 64 n (pad 72)
constexpr int TSZ = ASZ + WSZ;            // 3712 floats per stage
constexpr int NSTG = 3;
constexpr int GEMM_SMEM = TSZ * NSTG * 4; // 44544 B

__device__ __forceinline__ void mma_tf32(float4& c, const unsigned a[4], const unsigned b[2]) {
  asm volatile(
      "mma.sync.aligned.m16n8k8.row.col.f32.tf32.tf32.f32 "
      "{%0,%1,%2,%3}, {%4,%5,%6,%7}, {%8,%9}, {%0,%1,%2,%3};"
      : "+f"(c.x), "+f"(c.y), "+f"(c.z), "+f"(c.w)
      : "r"(a[0]), "r"(a[1]), "r"(a[2]), "r"(a[3]), "r"(b[0]), "r"(b[1]));
}

// SEL: 0 -> A=Araw (x, K=256, cvt at frag read), W=g_win,  out=g_h1
//      1 -> A=g_h1 (BN affine at frag read),     W=g_w1r,  out=g_t1
//      2 -> A=g_skip,                            W=g_w2,   out=g_t2
//      3 -> A=g_skip,                            W=g_wskip,out=outp
template <int K, int MODE, int SEL>
__global__ __launch_bounds__(256, 4) void k_gemm_tc(const float* __restrict__ bias,
                                                    const float* __restrict__ atts,
                                                    const float* __restrict__ attd,
                                                    const float* __restrict__ gam,
                                                    const float* __restrict__ bet,
                                                    const float* __restrict__ Araw,
                                                    float* __restrict__ outp) {
  extern __shared__ float sm[];
  __shared__ float satt[256];
  __shared__ float sstat[256];
  __shared__ float sbn[256];     // [0:128) sc1, [128:256) sh1

  const float* A  = (SEL == 0) ? Araw : (SEL == 1) ? g_h1 : g_skip;
  const float* Wm = (SEL == 0) ? g_win : (SEL == 1) ? g_w1r : (SEL == 2) ? g_w2 : g_wskip;
  float* out      = (SEL == 0) ? g_h1 : (SEL == 1) ? g_t1 : (SEL == 2) ? g_t2 : outp;

  int tid = threadIdx.x;
  int lane = tid & 31, wid = tid >> 5;
  int gr = lane >> 2, gc = lane & 3;
  int warp_m = wid & 3, warp_n = wid >> 2;   // 4 m-warps x 2 n-warps
  int row0 = (blockIdx.x >> 1) * 128;
  int ncol0 = (blockIdx.x & 1) * 64;

  if (MODE & (M_ATT8 | M_ATT1)) {
    if (tid < 128) { satt[tid] = __ldg(atts + tid); satt[128 + tid] = __ldg(attd + tid); }
  }
  if (MODE & (M_ST1 | M_ST2)) sstat[tid] = 0.f;
  if (MODE & M_BNA) {
    if (tid < 128) {
      float mean = g_stats1[tid] * (1.f / NN);
      float var = g_stats1[128 + tid] * (1.f / NN) - mean * mean;
      float sc = rsqrtf(var + 1e-5f) * __ldg(gam + tid);
      sbn[tid] = sc;
      sbn[128 + tid] = __ldg(bet + tid) - mean * sc;
    }
  }

  float4 acc[2][4];
#pragma unroll
  for (int mt = 0; mt < 2; mt++)
#pragma unroll
    for (int nt = 0; nt < 4; nt++) acc[mt][nt] = make_float4(0.f, 0.f, 0.f, 0.f);

  auto issue = [&](int kc, int buf) {
    float* As = sm + buf * TSZ;
    float* Ws = As + ASZ;
#pragma unroll
    for (int i = 0; i < 2; i++) {
      int fidx = i * 256 + tid;              // 0..511 float4s
      int r = fidx >> 2, c4 = fidx & 3;
      int grow = row0 + r;
      int ok = (grow < NN);
      const float* src = A + (size_t)(ok ? grow : 0) * K + kc + c4 * 4;
      unsigned dst = (unsigned)__cvta_generic_to_shared(As + r * 20 + c4 * 4);
      int sz = ok ? 16 : 0;
      asm volatile("cp.async.cg.shared.global [%0], [%1], 16, %2;"
                   :: "r"(dst), "l"(src), "r"(sz));
    }
    {
      int k = tid >> 4, n4 = tid & 15;       // 256 float4s = 16k x 64n
      const float* src = Wm + (size_t)(kc + k) * 128 + ncol0 + n4 * 4;
      unsigned dst = (unsigned)__cvta_generic_to_shared(Ws + k * 72 + n4 * 4);
      asm volatile("cp.async.cg.shared.global [%0], [%1], 16;" :: "r"(dst), "l"(src));
    }
    asm volatile("cp.async.commit_group;");
  };

  constexpr int NCH = K / 16;
  issue(0, 0);
  issue(16, 1);

  for (int ch = 0; ch < NCH; ch++) {
    if (ch < NCH - 1) asm volatile("cp.async.wait_group 1;" ::: "memory");
    else              asm volatile("cp.async.wait_group 0;" ::: "memory");
    __syncthreads();
    if (ch + 2 < NCH) issue((ch + 2) * 16, (ch + 2) % NSTG);

    const float* As = sm + (ch % NSTG) * TSZ;
    const float* Ws = As + ASZ;
    int kb = ch * 16;
#pragma unroll
    for (int kk = 0; kk < 16; kk += 8) {
      unsigned a[2][4];
      if (MODE & M_BNA) {
        float sc0 = sbn[kb + kk + gc],       sh0 = sbn[128 + kb + kk + gc];
        float sc1 = sbn[kb + kk + gc + 4],   sh1 = sbn[128 + kb + kk + gc + 4];
#pragma unroll
        for (int mt = 0; mt < 2; mt++) {
          int rb = warp_m * 32 + mt * 16;
          a[mt][0] = __float_as_uint(tf32r(fmaf(As[(rb + gr)     * 20 + kk + gc], sc0, sh0)));
          a[mt][1] = __float_as_uint(tf32r(fmaf(As[(rb + gr + 8) * 20 + kk + gc], sc0, sh0)));
          a[mt][2] = __float_as_uint(tf32r(fmaf(As[(rb + gr)     * 20 + kk + gc + 4], sc1, sh1)));
          a[mt][3] = __float_as_uint(tf32r(fmaf(As[(rb + gr + 8) * 20 + kk + gc + 4], sc1, sh1)));
        }
      } else {
#pragma unroll
        for (int mt = 0; mt < 2; mt++) {
          int rb = warp_m * 32 + mt * 16;
          if (SEL == 0) {
            a[mt][0] = __float_as_uint(tf32r(As[(rb + gr)     * 20 + kk + gc]));
            a[mt][1] = __float_as_uint(tf32r(As[(rb + gr + 8) * 20 + kk + gc]));
            a[mt][2] = __float_as_uint(tf32r(As[(rb + gr)     * 20 + kk + gc + 4]));
            a[mt][3] = __float_as_uint(tf32r(As[(rb + gr + 8) * 20 + kk + gc + 4]));
          } else {
            a[mt][0] = __float_as_uint(As[(rb + gr)     * 20 + kk + gc]);
            a[mt][1] = __float_as_uint(As[(rb + gr + 8) * 20 + kk + gc]);
            a[mt][2] = __float_as_uint(As[(rb + gr)     * 20 + kk + gc + 4]);
            a[mt][3] = __float_as_uint(As[(rb + gr + 8) * 20 + kk + gc + 4]);
          }
        }
      }
      unsigned b[4][2];
#pragma unroll
      for (int nt = 0; nt < 4; nt++) {
        int n = warp_n * 32 + nt * 8 + gr;
        b[nt][0] = __float_as_uint(Ws[(kk + gc)     * 72 + n]);
        b[nt][1] = __float_as_uint(Ws[(kk + gc + 4) * 72 + n]);
      }
#pragma unroll
      for (int mt = 0; mt < 2; mt++)
#pragma unroll
        for (int nt = 0; nt < 4; nt++) mma_tf32(acc[mt][nt], a[mt], b[nt]);
    }
  }

  __syncthreads();

  // ---------------- fused epilogue ----------------
  float pa_s[2][2] = {{0.f, 0.f}, {0.f, 0.f}};
  float pa_d[2][2] = {{0.f, 0.f}, {0.f, 0.f}};

#pragma unroll
  for (int nt = 0; nt < 4; nt++) {
    int col = ncol0 + warp_n * 32 + nt * 8 + gc * 2;   // global col in [0,128)
    float2 bv = make_float2(0.f, 0.f);
    if (MODE & M_BIAS) bv = *(const float2*)(bias + col);
    float2 av_s = make_float2(0.f, 0.f), av_d = make_float2(0.f, 0.f);
    if (MODE & (M_ATT8 | M_ATT1)) {
      av_s = *(const float2*)&satt[col];
      av_d = *(const float2*)&satt[128 + col];
    }
    float2 csum = make_float2(0.f, 0.f), csq = make_float2(0.f, 0.f);

#pragma unroll
    for (int mt = 0; mt < 2; mt++) {
#pragma unroll
      for (int hh = 0; hh < 2; hh++) {
        int r = row0 + warp_m * 32 + mt * 16 + gr + hh * 8;
        if (r < NN) {
          float2 v = hh ? make_float2(acc[mt][nt].z, acc[mt][nt].w)
                        : make_float2(acc[mt][nt].x, acc[mt][nt].y);
          if (MODE & M_BIAS) { v.x += bv.x; v.y += bv.y; }
          if (MODE & M_ADDC) {
            float2 cv = *(const float2*)(g_out2 + (size_t)r * 128 + col);
            v.x += cv.x; v.y += cv.y;
          }
          if (MODE & M_LEAKY) { v.x = lrelu(v.x); v.y = lrelu(v.y); }
          if (MODE & M_CVT)   { v.x = tf32r(v.x); v.y = tf32r(v.y); }
          *(float2*)(out + (size_t)r * 128 + col) = v;
          if (MODE & (M_ST1 | M_ST2)) {
            csum.x += v.x; csum.y += v.y;
            csq.x += v.x * v.x; csq.y += v.y * v.y;
          }
          if (MODE & (M_ATT8 | M_ATT1)) {
            pa_s[mt][hh] = fmaf(v.x, av_s.x, fmaf(v.y, av_s.y, pa_s[mt][hh]));
            pa_d[mt][hh] = fmaf(v.x, av_d.x, fmaf(v.y, av_d.y, pa_d[mt][hh]));
          }
        }
      }
    }

    if (MODE & (M_ST1 | M_ST2)) {
      atomicAdd(&sstat[col], csum.x);
      atomicAdd(&sstat[col + 1], csum.y);
      atomicAdd(&sstat[128 + col], csq.x);
      atomicAdd(&sstat[128 + col + 1], csq.y);
    }

    if ((MODE & M_ATT8) && (nt & 1)) {
      int head = (ncol0 >> 4) + warp_n * 2 + (nt >> 1);
#pragma unroll
      for (int mt = 0; mt < 2; mt++) {
#pragma unroll
        for (int hh = 0; hh < 2; hh++) {
          float ps = pa_s[mt][hh], pd = pa_d[mt][hh];
          ps += __shfl_xor_sync(0xffffffffu, ps, 1);
          ps += __shfl_xor_sync(0xffffffffu, ps, 2);
          pd += __shfl_xor_sync(0xffffffffu, pd, 1);
          pd += __shfl_xor_sync(0xffffffffu, pd, 2);
          int r = row0 + warp_m * 32 + mt * 16 + gr + hh * 8;
          if (gc == 0 && r < NN) {
            g_as1[(size_t)r * 8 + head] = ps;
            g_ad1[(size_t)r * 8 + head] = pd;
          }
          pa_s[mt][hh] = 0.f;
          pa_d[mt][hh] = 0.f;
        }
      }
    }
  }

  if (MODE & M_ATT1) {
#pragma unroll
    for (int mt = 0; mt < 2; mt++) {
#pragma unroll
      for (int hh = 0; hh < 2; hh++) {
        float ps = pa_s[mt][hh], pd = pa_d[mt][hh];
        ps += __shfl_xor_sync(0xffffffffu, ps, 1);
        ps += __shfl_xor_sync(0xffffffffu, ps, 2);
        pd += __shfl_xor_sync(0xffffffffu, pd, 1);
        pd += __shfl_xor_sync(0xffffffffu, pd, 2);
        int r = row0 + warp_m * 32 + mt * 16 + gr + hh * 8;
        if (gc == 0 && r < NN) {
          atomicAdd(&g_as2[r], ps);
          atomicAdd(&g_ad2[r], pd);
        }
      }
    }
  }

  if (MODE & (M_ST1 | M_ST2)) {
    __syncthreads();
    float* gst = (MODE & M_ST1) ? g_stats1 : g_stats2;
    atomicAdd(&gst[tid], sstat[tid]);
  }
}

// ---------------- BN2 finalize ----------------
__global__ void k_bnfin2(const float* __restrict__ gamma, const float* __restrict__ beta) {
  int i = threadIdx.x;
  float mean = g_stats2[i] * (1.f / NN);
  float var = g_stats2[128 + i] * (1.f / NN) - mean * mean;
  float sc = rsqrtf(var + 1e-5f) * gamma[i];
  g_sc2[i] = sc;
  g_sh2[i] = beta[i] - mean * sc;
}

template <int H>
__device__ __forceinline__ void load_as(float* dst, const float* __restrict__ p, int s) {
  if constexpr (H == 8) {
    float4 a = __ldg((const float4*)(p + (size_t)s * 8));
    float4 b = __ldg((const float4*)(p + (size_t)s * 8 + 4));
    dst[0] = a.x; dst[1] = a.y; dst[2] = a.z; dst[3] = a.w;
    dst[4] = b.x; dst[5] = b.y; dst[6] = b.z; dst[7] = b.w;
  } else {
    dst[0] = __ldg(p + s);
  }
}

// ---------------- GAT aggregation: WARP per node, online softmax ----------------
template <int H, bool LK, bool CVT>
__global__ __launch_bounds__(256) void k_gat(const float* __restrict__ bias) {
  const float* t   = (H == 8) ? g_t1  : g_t2;
  const float* asv = (H == 8) ? g_as1 : g_as2;
  const float* adv = (H == 8) ? g_ad1 : g_ad2;
  float* out       = (H == 8) ? g_skip : g_out2;

  int lane = threadIdx.x & 31, warp = threadIdx.x >> 5;
  int node = blockIdx.x * 8 + warp;
  if (node >= NN) return;
  int beg = g_rs[node];
  int cnt = g_deg[node];
  int myh = (H == 8) ? (lane >> 2) : 0;

  __shared__ float salpha[8][H * 33];

  float ad[H];
  load_as<H>(ad, adv, node);

  float m[H], den[H];
#pragma unroll
  for (int h = 0; h < H; h++) { m[h] = -1e30f; den[h] = 0.f; }
  float4 acc = make_float4(0.f, 0.f, 0.f, 0.f);

  for (int base = 0; base < cnt; base += 32) {
    int c = min(32, cnt - base);

    int s = 0;
    float e[H];
    if (lane < c) {
      s = __ldg(&g_sby[beg + base + lane]);
      float av[H];
      load_as<H>(av, asv, s);
#pragma unroll
      for (int h = 0; h < H; h++) e[h] = lrelu(av[h] + ad[h]);
    } else {
#pragma unroll
      for (int h = 0; h < H; h++) e[h] = -1e30f;
    }

    float cm[H];
#pragma unroll
    for (int h = 0; h < H; h++) {
      cm[h] = e[h];
#pragma unroll
      for (int o = 16; o; o >>= 1) cm[h] = fmaxf(cm[h], __shfl_xor_sync(0xffffffffu, cm[h], o));
    }

    float a_[H];
#pragma unroll
    for (int h = 0; h < H; h++) {
      float mn = fmaxf(m[h], cm[h]);
      float f = __expf(m[h] - mn);
      m[h] = mn;
      den[h] *= f;
      if (h == myh) { acc.x *= f; acc.y *= f; acc.z *= f; acc.w *= f; }
      a_[h] = (lane < c) ? __expf(e[h] - mn) : 0.f;
      salpha[warp][h * 33 + lane] = a_[h];
    }

#pragma unroll
    for (int h = 0; h < H; h++) {
      float sum = a_[h];
#pragma unroll
      for (int o = 16; o; o >>= 1) sum += __shfl_xor_sync(0xffffffffu, sum, o);
      den[h] += sum;
    }
    __syncwarp();

    const float* sa = &salpha[warp][myh * 33];
#pragma unroll 4
    for (int j = 0; j < c; j++) {
      int sj = __shfl_sync(0xffffffffu, s, j);
      float w = sa[j];
      float4 tv = __ldg((const float4*)(t + (size_t)sj * 128 + lane * 4));
      acc.x = fmaf(w, tv.x, acc.x);
      acc.y = fmaf(w, tv.y, acc.y);
      acc.z = fmaf(w, tv.z, acc.z);
      acc.w = fmaf(w, tv.w, acc.w);
    }
    __syncwarp();
  }

  float inv = 1.f / fmaxf(den[myh], 1e-16f);
  float4 bv = *(const float4*)(bias + lane * 4);
  float4 v;
  v.x = acc.x * inv + bv.x;
  v.y = acc.y * inv + bv.y;
  v.z = acc.z * inv + bv.z;
  v.w = acc.w * inv + bv.w;
  if (LK) { v.x = lrelu(v.x); v.y = lrelu(v.y); v.z = lrelu(v.z); v.w = lrelu(v.w); }
  if (CVT) v = tf32r4(v);
  *(float4*)(out + (size_t)node * 128 + lane * 4) = v;
}

// ---------------- final: BN2 affine + L2 row normalize (2 nodes/block) ----------------
__global__ __launch_bounds__(256) void k_final(float* __restrict__ out) {
  int node = blockIdx.x * 2 + (threadIdx.x >> 7);
  int tid = threadIdx.x & 127;
  if (node >= NN) return;
  float v = out[(size_t)node * 128 + tid] * g_sc2[tid] + g_sh2[tid];
  float q = v * v;
#pragma unroll
  for (int o = 16; o; o >>= 1) q += __shfl_xor_sync(0xffffffffu, q, o);
  __shared__ float sq[2][4];
  int half = threadIdx.x >> 7;
  if ((tid & 31) == 0) sq[half][tid >> 5] = q;
  __syncthreads();
  float tot = sq[half][0] + sq[half][1] + sq[half][2] + sq[half][3];
  float r = 1.f / fmaxf(sqrtf(tot), 1e-12f);
  out[(size_t)node * 128 + tid] = v * r;
}

}  // namespace

extern "C" void kernel_launch(void* const* d_in, const int* in_sizes, int n_in,
                              void* d_out, int out_size) {
  const float* x        = (const float*)d_in[0];
  const float* W_in     = (const float*)d_in[1];
  const float* b_in     = (const float*)d_in[2];
  const float* gamma1   = (const float*)d_in[3];
  const float* beta1    = (const float*)d_in[4];
  const float* W1       = (const float*)d_in[5];
  const float* att_src1 = (const float*)d_in[6];
  const float* att_dst1 = (const float*)d_in[7];
  const float* bias1    = (const float*)d_in[8];
  const float* W2       = (const float*)d_in[9];
  const float* att_src2 = (const float*)d_in[10];
  const float* att_dst2 = (const float*)d_in[11];
  const float* bias2    = (const float*)d_in[12];
  const float* W_skip   = (const float*)d_in[13];
  const float* b_skip   = (const float*)d_in[14];
  const float* gamma2   = (const float*)d_in[15];
  const float* beta2    = (const float*)d_in[16];
  const void*  eidx     = d_in[17];
  float* out = (float*)d_out;

  cudaFuncSetAttribute(k_gemm_tc<KIN, M_BIAS | M_LEAKY | M_CVT | M_ST1, 0>,
                       cudaFuncAttributeMaxDynamicSharedMemorySize, GEMM_SMEM);
  cudaFuncSetAttribute(k_gemm_tc<128, M_BNA | M_ATT8, 1>,
                       cudaFuncAttributeMaxDynamicSharedMemorySize, GEMM_SMEM);
  cudaFuncSetAttribute(k_gemm_tc<128, M_ATT1, 2>,
                       cudaFuncAttributeMaxDynamicSharedMemorySize, GEMM_SMEM);
  cudaFuncSetAttribute(k_gemm_tc<128, M_BIAS | M_ADDC | M_ST2, 3>,
                       cudaFuncAttributeMaxDynamicSharedMemorySize, GEMM_SMEM);

  const int GB2 = ((NN + 127) / 128) * 2;  // 782 (128-row x 64-col tiles)
  const int AB = (NN + 7) / 8;             // 6250

  // init (zero + weight rounding + dtype detect)
  k_zerow<<<(NN + 255) / 256, 256>>>(eidx, W_in, W1, W2, W_skip);              // 0
  // GEMM1: h1 = leaky(x@W_in+b_in), stats1 fused
  k_gemm_tc<KIN, M_BIAS | M_LEAKY | M_CVT | M_ST1, 0>
      <<<GB2, 256, GEMM_SMEM>>>(b_in, nullptr, nullptr, nullptr, nullptr, x, nullptr); // 1
  k_edges<<<(NE + 255) / 256, 256>>>(eidx);                                    // 2
  // GEMM2: t1 = BN1(h1)@W1 (BN folded in), att1 fused   (profiled at idx 3)
  k_gemm_tc<128, M_BNA | M_ATT8, 1>
      <<<GB2, 256, GEMM_SMEM>>>(nullptr, att_src1, att_dst1, gamma1, beta1, nullptr, nullptr); // 3
  k_scan<<<NB, 1024>>>();                                                      // 4
  k_scatter<<<(NE + 255) / 256, 256>>>();                                      // 5
  k_gat<8, true, true><<<AB, 256>>>(bias1);
  // GEMM3: t2 = skip@W2, att2 fused
  k_gemm_tc<128, M_ATT1, 2>
      <<<GB2, 256, GEMM_SMEM>>>(nullptr, att_src2, att_dst2, nullptr, nullptr, nullptr, nullptr);
  k_gat<1, false, false><<<AB, 256>>>(bias2);
  // GEMM4: out = skip@W_skip + b_skip + out2, stats2 fused
  k_gemm_tc<128, M_BIAS | M_ADDC | M_ST2, 3>
      <<<GB2, 256, GEMM_SMEM>>>(b_skip, nullptr, nullptr, nullptr, nullptr, nullptr, out);
  k_bnfin2<<<1, 128>>>(gamma2, beta2);
  k_final<<<(NN + 1) / 2, 256>>>(out);
}

// round 16
// speedup vs baseline: 1.1875x; 1.0047x over previous
#include <cuda_runtime.h>

namespace {

constexpr int NN  = 50000;   // nodes
constexpr int NE  = 800000;  // edges
constexpr int KIN = 256;     // in_dim
constexpr int NB  = (NN + 1023) / 1024;  // scan blocks = 49

// ---------------- scratch (static device memory; no allocations) ----------------
__device__ float g_win[256 * 128];   // tf32-rounded W_in
__device__ float g_w1r[128 * 128];   // tf32-rounded W1
__device__ float g_w2[128 * 128];    // tf32-rounded W2
__device__ float g_wskip[128 * 128]; // tf32-rounded W_skip
__device__ float g_h1[NN * 128];     // leaky(x@W_in+b_in), tf32-rounded
__device__ float g_t1[NN * 128];     // BN1(h1)@W1; later reused as skip@W_skip+b_skip
__device__ float g_skip[NN * 128];   // leaky(gat1 + bias1), tf32-rounded
__device__ float g_t2[NN * 128];     // skip @ W2
__device__ float g_out2[NN * 128];   // gat2 + bias2
__device__ float g_as1[NN * 8];
__device__ float g_ad1[NN * 8];
__device__ float g_as2[NN];
__device__ float g_ad2[NN];
__device__ int   g_src[NE];
__device__ int   g_dst[NE];
__device__ int   g_sby[NE];          // src ids sorted by dst (CSR order)
__device__ int   g_deg[NN];
__device__ int   g_cur[NN];
__device__ int   g_rs[NN + 1];       // CSR row starts (disjoint regions)
__device__ int   g_ctr;
__device__ float g_stats1[256];
__device__ float g_stats2[256];
__device__ float g_sc2[128], g_sh2[128];
__device__ int   g_is64;

__device__ __forceinline__ float lrelu(float v) { return v >= 0.f ? v : 0.2f * v; }

__device__ __forceinline__ float tf32r(float f) {
  unsigned u;
  asm("cvt.rna.tf32.f32 %0, %1;" : "=r"(u) : "f"(f));
  return __uint_as_float(u);
}
__device__ __forceinline__ float4 tf32r4(float4 v) {
  return make_float4(tf32r(v.x), tf32r(v.y), tf32r(v.z), tf32r(v.w));
}

// ---------------- init: zero + dtype detect + round all weights ----------------
__global__ void k_zerow(const void* __restrict__ ei,
                        const float* __restrict__ Win, const float* __restrict__ W1,
                        const float* __restrict__ W2,  const float* __restrict__ Wsk) {
  int i = blockIdx.x * 256 + threadIdx.x;
  if (i < NN) { g_deg[i] = 0; g_cur[i] = 0; g_as2[i] = 0.f; g_ad2[i] = 0.f; }
  if (i < 256) { g_stats1[i] = 0.f; g_stats2[i] = 0.f; }
  if (i < 8192)
    *(float4*)(g_win + i * 4) = tf32r4(*(const float4*)(Win + i * 4));
  if (i < 4096) {
    *(float4*)(g_w1r + i * 4)   = tf32r4(*(const float4*)(W1 + i * 4));
    *(float4*)(g_w2 + i * 4)    = tf32r4(*(const float4*)(W2 + i * 4));
    *(float4*)(g_wskip + i * 4) = tf32r4(*(const float4*)(Wsk + i * 4));
  }
  if (blockIdx.x == 0 && threadIdx.x == 0) {
    g_ctr = 0;
    const long long* p = (const long long*)ei;
    int ok = 1;
    for (int j = 0; j < 64; j++) {
      long long v = p[j];
      if (v < 0 || v >= NN) { ok = 0; break; }
    }
    g_is64 = ok;
  }
}

__global__ void k_edges(const void* __restrict__ ei) {
  int i = blockIdx.x * 256 + threadIdx.x;
  if (i < NE) {
    int s, d;
    if (g_is64) {
      const long long* p = (const long long*)ei;
      s = (int)p[i];
      d = (int)p[NE + i];
    } else {
      const int* p = (const int*)ei;
      s = p[i];
      d = p[NE + i];
    }
    if ((unsigned)s >= NN) s = 0;
    if ((unsigned)d >= NN) d = 0;
    g_src[i] = s;
    g_dst[i] = d;
    atomicAdd(&g_deg[d], 1);
  }
}

__global__ void k_scan() {
  int t = threadIdx.x;
  int i = blockIdx.x * 1024 + t;
  int v = (i < NN) ? g_deg[i] : 0;
  __shared__ int sb[1024];
  __shared__ int sbase;
  sb[t] = v;
  __syncthreads();
  for (int o = 1; o < 1024; o <<= 1) {
    int x = (t >= o) ? sb[t - o] : 0;
    __syncthreads();
    sb[t] += x;
    __syncthreads();
  }
  if (t == 1023) sbase = atomicAdd(&g_ctr, sb[1023]);
  __syncthreads();
  if (i < NN) g_rs[i] = sbase + sb[t] - v;
}

__global__ void k_scatter() {
  int i = blockIdx.x * 256 + threadIdx.x;
  if (i < NE) {
    int d = g_dst[i];
    int p = atomicAdd(&g_cur[d], 1);
    g_sby[g_rs[d] + p] = g_src[i];
  }
}

// ---------------- TF32 tensor-core GEMM: block 128x64, BK=16, 3-stage pipeline ----------------
constexpr int M_LEAKY = 2, M_BIAS = 16, M_CVT = 32, M_BNA = 64;
constexpr int M_ST1 = 128, M_ATT8 = 512, M_ATT1 = 1024;
constexpr int ASZ = 128 * 20;             // A stage: 128 rows x 16 k (pad 20)
constexpr int WSZ = 16 * 72;              // W stage: 16 k x 64 n (pad 72)
constexpr int TSZ = ASZ + WSZ;            // 3712 floats per stage
constexpr int NSTG = 3;
constexpr int GEMM_SMEM = TSZ * NSTG * 4; // 44544 B

__device__ __forceinline__ void mma_tf32(float4& c, const unsigned a[4], const unsigned b[2]) {
  asm volatile(
      "mma.sync.aligned.m16n8k8.row.col.f32.tf32.tf32.f32 "
      "{%0,%1,%2,%3}, {%4,%5,%6,%7}, {%8,%9}, {%0,%1,%2,%3};"
      : "+f"(c.x), "+f"(c.y), "+f"(c.z), "+f"(c.w)
      : "r"(a[0]), "r"(a[1]), "r"(a[2]), "r"(a[3]), "r"(b[0]), "r"(b[1]));
}

// SEL: 0 -> A=Araw (x, K=256, cvt at frag read), W=g_win,  out=g_h1
//      1 -> A=g_h1 (BN affine at frag read),     W=g_w1r,  out=g_t1
//      2 -> A=g_skip,                            W=g_w2,   out=g_t2
//      3 -> A=g_skip,                            W=g_wskip,out=g_t1 (skip@W_skip+b_skip)
template <int K, int MODE, int SEL>
__global__ __launch_bounds__(256, 4) void k_gemm_tc(const float* __restrict__ bias,
                                                    const float* __restrict__ atts,
                                                    const float* __restrict__ attd,
                                                    const float* __restrict__ gam,
                                                    const float* __restrict__ bet,
                                                    const float* __restrict__ Araw) {
  extern __shared__ float sm[];
  __shared__ float satt[256];
  __shared__ float sstat[256];
  __shared__ float sbn[256];     // [0:128) sc1, [128:256) sh1

  const float* A  = (SEL == 0) ? Araw : (SEL == 1) ? g_h1 : g_skip;
  const float* Wm = (SEL == 0) ? g_win : (SEL == 1) ? g_w1r : (SEL == 2) ? g_w2 : g_wskip;
  float* out      = (SEL == 0) ? g_h1 : (SEL == 1) ? g_t1 : (SEL == 2) ? g_t2 : g_t1;

  int tid = threadIdx.x;
  int lane = tid & 31, wid = tid >> 5;
  int gr = lane >> 2, gc = lane & 3;
  int warp_m = wid & 3, warp_n = wid >> 2;   // 4 m-warps x 2 n-warps
  int row0 = (blockIdx.x >> 1) * 128;
  int ncol0 = (blockIdx.x & 1) * 64;

  if (MODE & (M_ATT8 | M_ATT1)) {
    if (tid < 128) { satt[tid] = __ldg(atts + tid); satt[128 + tid] = __ldg(attd + tid); }
  }
  if (MODE & M_ST1) sstat[tid] = 0.f;
  if (MODE & M_BNA) {
    if (tid < 128) {
      float mean = g_stats1[tid] * (1.f / NN);
      float var = g_stats1[128 + tid] * (1.f / NN) - mean * mean;
      float sc = rsqrtf(var + 1e-5f) * __ldg(gam + tid);
      sbn[tid] = sc;
      sbn[128 + tid] = __ldg(bet + tid) - mean * sc;
    }
  }

  float4 acc[2][4];
#pragma unroll
  for (int mt = 0; mt < 2; mt++)
#pragma unroll
    for (int nt = 0; nt < 4; nt++) acc[mt][nt] = make_float4(0.f, 0.f, 0.f, 0.f);

  auto issue = [&](int kc, int buf) {
    float* As = sm + buf * TSZ;
    float* Ws = As + ASZ;
#pragma unroll
    for (int i = 0; i < 2; i++) {
      int fidx = i * 256 + tid;              // 0..511 float4s
      int r = fidx >> 2, c4 = fidx & 3;
      int grow = row0 + r;
      int ok = (grow < NN);
      const float* src = A + (size_t)(ok ? grow : 0) * K + kc + c4 * 4;
      unsigned dst = (unsigned)__cvta_generic_to_shared(As + r * 20 + c4 * 4);
      int sz = ok ? 16 : 0;
      asm volatile("cp.async.cg.shared.global [%0], [%1], 16, %2;"
                   :: "r"(dst), "l"(src), "r"(sz));
    }
    {
      int k = tid >> 4, n4 = tid & 15;       // 256 float4s = 16k x 64n
      const float* src = Wm + (size_t)(kc + k) * 128 + ncol0 + n4 * 4;
      unsigned dst = (unsigned)__cvta_generic_to_shared(Ws + k * 72 + n4 * 4);
      asm volatile("cp.async.cg.shared.global [%0], [%1], 16;" :: "r"(dst), "l"(src));
    }
    asm volatile("cp.async.commit_group;");
  };

  constexpr int NCH = K / 16;
  issue(0, 0);
  issue(16, 1);

  for (int ch = 0; ch < NCH; ch++) {
    if (ch < NCH - 1) asm volatile("cp.async.wait_group 1;" ::: "memory");
    else              asm volatile("cp.async.wait_group 0;" ::: "memory");
    __syncthreads();
    if (ch + 2 < NCH) issue((ch + 2) * 16, (ch + 2) % NSTG);

    const float* As = sm + (ch % NSTG) * TSZ;
    const float* Ws = As + ASZ;
    int kb = ch * 16;
#pragma unroll
    for (int kk = 0; kk < 16; kk += 8) {
      unsigned a[2][4];
      if (MODE & M_BNA) {
        float sc0 = sbn[kb + kk + gc],       sh0 = sbn[128 + kb + kk + gc];
        float sc1 = sbn[kb + kk + gc + 4],   sh1 = sbn[128 + kb + kk + gc + 4];
#pragma unroll
        for (int mt = 0; mt < 2; mt++) {
          int rb = warp_m * 32 + mt * 16;
          a[mt][0] = __float_as_uint(tf32r(fmaf(As[(rb + gr)     * 20 + kk + gc], sc0, sh0)));
          a[mt][1] = __float_as_uint(tf32r(fmaf(As[(rb + gr + 8) * 20 + kk + gc], sc0, sh0)));
          a[mt][2] = __float_as_uint(tf32r(fmaf(As[(rb + gr)     * 20 + kk + gc + 4], sc1, sh1)));
          a[mt][3] = __float_as_uint(tf32r(fmaf(As[(rb + gr + 8) * 20 + kk + gc + 4], sc1, sh1)));
        }
      } else {
#pragma unroll
        for (int mt = 0; mt < 2; mt++) {
          int rb = warp_m * 32 + mt * 16;
          if (SEL == 0) {
            a[mt][0] = __float_as_uint(tf32r(As[(rb + gr)     * 20 + kk + gc]));
            a[mt][1] = __float_as_uint(tf32r(As[(rb + gr + 8) * 20 + kk + gc]));
            a[mt][2] = __float_as_uint(tf32r(As[(rb + gr)     * 20 + kk + gc + 4]));
            a[mt][3] = __float_as_uint(tf32r(As[(rb + gr + 8) * 20 + kk + gc + 4]));
          } else {
            a[mt][0] = __float_as_uint(As[(rb + gr)     * 20 + kk + gc]);
            a[mt][1] = __float_as_uint(As[(rb + gr + 8) * 20 + kk + gc]);
            a[mt][2] = __float_as_uint(As[(rb + gr)     * 20 + kk + gc + 4]);
            a[mt][3] = __float_as_uint(As[(rb + gr + 8) * 20 + kk + gc + 4]);
          }
        }
      }
      unsigned b[4][2];
#pragma unroll
      for (int nt = 0; nt < 4; nt++) {
        int n = warp_n * 32 + nt * 8 + gr;
        b[nt][0] = __float_as_uint(Ws[(kk + gc)     * 72 + n]);
        b[nt][1] = __float_as_uint(Ws[(kk + gc + 4) * 72 + n]);
      }
#pragma unroll
      for (int mt = 0; mt < 2; mt++)
#pragma unroll
        for (int nt = 0; nt < 4; nt++) mma_tf32(acc[mt][nt], a[mt], b[nt]);
    }
  }

  __syncthreads();

  // ---------------- fused epilogue ----------------
  float pa_s[2][2] = {{0.f, 0.f}, {0.f, 0.f}};
  float pa_d[2][2] = {{0.f, 0.f}, {0.f, 0.f}};

#pragma unroll
  for (int nt = 0; nt < 4; nt++) {
    int col = ncol0 + warp_n * 32 + nt * 8 + gc * 2;   // global col in [0,128)
    float2 bv = make_float2(0.f, 0.f);
    if (MODE & M_BIAS) bv = *(const float2*)(bias + col);
    float2 av_s = make_float2(0.f, 0.f), av_d = make_float2(0.f, 0.f);
    if (MODE & (M_ATT8 | M_ATT1)) {
      av_s = *(const float2*)&satt[col];
      av_d = *(const float2*)&satt[128 + col];
    }
    float2 csum = make_float2(0.f, 0.f), csq = make_float2(0.f, 0.f);

#pragma unroll
    for (int mt = 0; mt < 2; mt++) {
#pragma unroll
      for (int hh = 0; hh < 2; hh++) {
        int r = row0 + warp_m * 32 + mt * 16 + gr + hh * 8;
        if (r < NN) {
          float2 v = hh ? make_float2(acc[mt][nt].z, acc[mt][nt].w)
                        : make_float2(acc[mt][nt].x, acc[mt][nt].y);
          if (MODE & M_BIAS) { v.x += bv.x; v.y += bv.y; }
          if (MODE & M_LEAKY) { v.x = lrelu(v.x); v.y = lrelu(v.y); }
          if (MODE & M_CVT)   { v.x = tf32r(v.x); v.y = tf32r(v.y); }
          *(float2*)(out + (size_t)r * 128 + col) = v;
          if (MODE & M_ST1) {
            csum.x += v.x; csum.y += v.y;
            csq.x += v.x * v.x; csq.y += v.y * v.y;
          }
          if (MODE & (M_ATT8 | M_ATT1)) {
            pa_s[mt][hh] = fmaf(v.x, av_s.x, fmaf(v.y, av_s.y, pa_s[mt][hh]));
            pa_d[mt][hh] = fmaf(v.x, av_d.x, fmaf(v.y, av_d.y, pa_d[mt][hh]));
          }
        }
      }
    }

    if (MODE & M_ST1) {
      atomicAdd(&sstat[col], csum.x);
      atomicAdd(&sstat[col + 1], csum.y);
      atomicAdd(&sstat[128 + col], csq.x);
      atomicAdd(&sstat[128 + col + 1], csq.y);
    }

    if ((MODE & M_ATT8) && (nt & 1)) {
      int head = (ncol0 >> 4) + warp_n * 2 + (nt >> 1);
#pragma unroll
      for (int mt = 0; mt < 2; mt++) {
#pragma unroll
        for (int hh = 0; hh < 2; hh++) {
          float ps = pa_s[mt][hh], pd = pa_d[mt][hh];
          ps += __shfl_xor_sync(0xffffffffu, ps, 1);
          ps += __shfl_xor_sync(0xffffffffu, ps, 2);
          pd += __shfl_xor_sync(0xffffffffu, pd, 1);
          pd += __shfl_xor_sync(0xffffffffu, pd, 2);
          int r = row0 + warp_m * 32 + mt * 16 + gr + hh * 8;
          if (gc == 0 && r < NN) {
            g_as1[(size_t)r * 8 + head] = ps;
            g_ad1[(size_t)r * 8 + head] = pd;
          }
          pa_s[mt][hh] = 0.f;
          pa_d[mt][hh] = 0.f;
        }
      }
    }
  }

  if (MODE & M_ATT1) {
#pragma unroll
    for (int mt = 0; mt < 2; mt++) {
#pragma unroll
      for (int hh = 0; hh < 2; hh++) {
        float ps = pa_s[mt][hh], pd = pa_d[mt][hh];
        ps += __shfl_xor_sync(0xffffffffu, ps, 1);
        ps += __shfl_xor_sync(0xffffffffu, ps, 2);
        pd += __shfl_xor_sync(0xffffffffu, pd, 1);
        pd += __shfl_xor_sync(0xffffffffu, pd, 2);
        int r = row0 + warp_m * 32 + mt * 16 + gr + hh * 8;
        if (gc == 0 && r < NN) {
          atomicAdd(&g_as2[r], ps);
          atomicAdd(&g_ad2[r], pd);
        }
      }
    }
  }

  if (MODE & M_ST1) {
    __syncthreads();
    atomicAdd(&g_stats1[tid], sstat[tid]);
  }
}

// ---------------- merge: out = g_t1(skip@W_skip+b) + g_out2, BN2 stats ----------------
__global__ __launch_bounds__(256) void k_merge(float* __restrict__ out) {
  int col = threadIdx.x & 127;
  int half = threadIdx.x >> 7;
  float s = 0.f, q = 0.f;
  for (int i = 0; i < 64; i++) {
    int r = blockIdx.x * 128 + i * 2 + half;
    if (r < NN) {
      float v = g_t1[(size_t)r * 128 + col] + g_out2[(size_t)r * 128 + col];
      out[(size_t)r * 128 + col] = v;
      s += v;
      q += v * v;
    }
  }
  __shared__ float red[512];
  red[threadIdx.x] = s;
  red[256 + threadIdx.x] = q;
  __syncthreads();
  if (threadIdx.x < 128) {
    atomicAdd(&g_stats2[threadIdx.x], red[threadIdx.x] + red[threadIdx.x + 128]);
    atomicAdd(&g_stats2[128 + threadIdx.x], red[256 + threadIdx.x] + red[384 + threadIdx.x]);
  }
}

// ---------------- BN2 finalize ----------------
__global__ void k_bnfin2(const float* __restrict__ gamma, const float* __restrict__ beta) {
  int i = threadIdx.x;
  float mean = g_stats2[i] * (1.f / NN);
  float var = g_stats2[128 + i] * (1.f / NN) - mean * mean;
  float sc = rsqrtf(var + 1e-5f) * gamma[i];
  g_sc2[i] = sc;
  g_sh2[i] = beta[i] - mean * sc;
}

template <int H>
__device__ __forceinline__ void load_as(float* dst, const float* __restrict__ p, int s) {
  if constexpr (H == 8) {
    float4 a = __ldg((const float4*)(p + (size_t)s * 8));
    float4 b = __ldg((const float4*)(p + (size_t)s * 8 + 4));
    dst[0] = a.x; dst[1] = a.y; dst[2] = a.z; dst[3] = a.w;
    dst[4] = b.x; dst[5] = b.y; dst[6] = b.z; dst[7] = b.w;
  } else {
    dst[0] = __ldg(p + s);
  }
}

// ---------------- GAT aggregation: WARP per node, online softmax ----------------
template <int H, bool LK, bool CVT>
__global__ __launch_bounds__(256) void k_gat(const float* __restrict__ bias) {
  const float* t   = (H == 8) ? g_t1  : g_t2;
  const float* asv = (H == 8) ? g_as1 : g_as2;
  const float* adv = (H == 8) ? g_ad1 : g_ad2;
  float* out       = (H == 8) ? g_skip : g_out2;

  int lane = threadIdx.x & 31, warp = threadIdx.x >> 5;
  int node = blockIdx.x * 8 + warp;
  if (node >= NN) return;
  int beg = g_rs[node];
  int cnt = g_deg[node];
  int myh = (H == 8) ? (lane >> 2) : 0;

  __shared__ float salpha[8][H * 33];

  float ad[H];
  load_as<H>(ad, adv, node);

  float m[H], den[H];
#pragma unroll
  for (int h = 0; h < H; h++) { m[h] = -1e30f; den[h] = 0.f; }
  float4 acc = make_float4(0.f, 0.f, 0.f, 0.f);

  for (int base = 0; base < cnt; base += 32) {
    int c = min(32, cnt - base);

    int s = 0;
    float e[H];
    if (lane < c) {
      s = __ldg(&g_sby[beg + base + lane]);
      float av[H];
      load_as<H>(av, asv, s);
#pragma unroll
      for (int h = 0; h < H; h++) e[h] = lrelu(av[h] + ad[h]);
    } else {
#pragma unroll
      for (int h = 0; h < H; h++) e[h] = -1e30f;
    }

    float cm[H];
#pragma unroll
    for (int h = 0; h < H; h++) {
      cm[h] = e[h];
#pragma unroll
      for (int o = 16; o; o >>= 1) cm[h] = fmaxf(cm[h], __shfl_xor_sync(0xffffffffu, cm[h], o));
    }

    float a_[H];
#pragma unroll
    for (int h = 0; h < H; h++) {
      float mn = fmaxf(m[h], cm[h]);
      float f = __expf(m[h] - mn);
      m[h] = mn;
      den[h] *= f;
      if (h == myh) { acc.x *= f; acc.y *= f; acc.z *= f; acc.w *= f; }
      a_[h] = (lane < c) ? __expf(e[h] - mn) : 0.f;
      salpha[warp][h * 33 + lane] = a_[h];
    }

#pragma unroll
    for (int h = 0; h < H; h++) {
      float sum = a_[h];
#pragma unroll
      for (int o = 16; o; o >>= 1) sum += __shfl_xor_sync(0xffffffffu, sum, o);
      den[h] += sum;
    }
    __syncwarp();

    const float* sa = &salpha[warp][myh * 33];
#pragma unroll 4
    for (int j = 0; j < c; j++) {
      int sj = __shfl_sync(0xffffffffu, s, j);
      float w = sa[j];
      float4 tv = __ldg((const float4*)(t + (size_t)sj * 128 + lane * 4));
      acc.x = fmaf(w, tv.x, acc.x);
      acc.y = fmaf(w, tv.y, acc.y);
      acc.z = fmaf(w, tv.z, acc.z);
      acc.w = fmaf(w, tv.w, acc.w);
    }
    __syncwarp();
  }

  float inv = 1.f / fmaxf(den[myh], 1e-16f);
  float4 bv = *(const float4*)(bias + lane * 4);
  float4 v;
  v.x = acc.x * inv + bv.x;
  v.y = acc.y * inv + bv.y;
  v.z = acc.z * inv + bv.z;
  v.w = acc.w * inv + bv.w;
  if (LK) { v.x = lrelu(v.x); v.y = lrelu(v.y); v.z = lrelu(v.z); v.w = lrelu(v.w); }
  if (CVT) v = tf32r4(v);
  *(float4*)(out + (size_t)node * 128 + lane * 4) = v;
}

// ---------------- final: BN2 affine + L2 row normalize (2 nodes/block) ----------------
__global__ __launch_bounds__(256) void k_final(float* __restrict__ out) {
  int node = blockIdx.x * 2 + (threadIdx.x >> 7);
  int tid = threadIdx.x & 127;
  if (node >= NN) return;
  float v = out[(size_t)node * 128 + tid] * g_sc2[tid] + g_sh2[tid];
  float q = v * v;
#pragma unroll
  for (int o = 16; o; o >>= 1) q += __shfl_xor_sync(0xffffffffu, q, o);
  __shared__ float sq[2][4];
  int half = threadIdx.x >> 7;
  if ((tid & 31) == 0) sq[half][tid >> 5] = q;
  __syncthreads();
  float tot = sq[half][0] + sq[half][1] + sq[half][2] + sq[half][3];
  float r = 1.f / fmaxf(sqrtf(tot), 1e-12f);
  out[(size_t)node * 128 + tid] = v * r;
}

}  // namespace

extern "C" void kernel_launch(void* const* d_in, const int* in_sizes, int n_in,
                              void* d_out, int out_size) {
  const float* x        = (const float*)d_in[0];
  const float* W_in     = (const float*)d_in[1];
  const float* b_in     = (const float*)d_in[2];
  const float* gamma1   = (const float*)d_in[3];
  const float* beta1    = (const float*)d_in[4];
  const float* W1       = (const float*)d_in[5];
  const float* att_src1 = (const float*)d_in[6];
  const float* att_dst1 = (const float*)d_in[7];
  const float* bias1    = (const float*)d_in[8];
  const float* W2       = (const float*)d_in[9];
  const float* att_src2 = (const float*)d_in[10];
  const float* att_dst2 = (const float*)d_in[11];
  const float* bias2    = (const float*)d_in[12];
  const float* W_skip   = (const float*)d_in[13];
  const float* b_skip   = (const float*)d_in[14];
  const float* gamma2   = (const float*)d_in[15];
  const float* beta2    = (const float*)d_in[16];
  const void*  eidx     = d_in[17];
  float* out = (float*)d_out;

  static bool s_init = false;
  static cudaStream_t s2, s3;
  static cudaEvent_t evz, evcsr, evskip, evg4;
  if (!s_init) {
    cudaStreamCreateWithFlags(&s2, cudaStreamNonBlocking);
    cudaStreamCreateWithFlags(&s3, cudaStreamNonBlocking);
    cudaEventCreateWithFlags(&evz, cudaEventDisableTiming);
    cudaEventCreateWithFlags(&evcsr, cudaEventDisableTiming);
    cudaEventCreateWithFlags(&evskip, cudaEventDisableTiming);
    cudaEventCreateWithFlags(&evg4, cudaEventDisableTiming);
    cudaFuncSetAttribute(k_gemm_tc<KIN, M_BIAS | M_LEAKY | M_CVT | M_ST1, 0>,
                         cudaFuncAttributeMaxDynamicSharedMemorySize, GEMM_SMEM);
    cudaFuncSetAttribute(k_gemm_tc<128, M_BNA | M_ATT8, 1>,
                         cudaFuncAttributeMaxDynamicSharedMemorySize, GEMM_SMEM);
    cudaFuncSetAttribute(k_gemm_tc<128, M_ATT1, 2>,
                         cudaFuncAttributeMaxDynamicSharedMemorySize, GEMM_SMEM);
    cudaFuncSetAttribute(k_gemm_tc<128, M_BIAS, 3>,
                         cudaFuncAttributeMaxDynamicSharedMemorySize, GEMM_SMEM);
    s_init = true;
  }

  const int GB2 = ((NN + 127) / 128) * 2;  // 782 (128-row x 64-col tiles)
  const int AB = (NN + 7) / 8;             // 6250

  // init (zero + weight rounding + dtype detect) on main stream
  k_zerow<<<(NN + 255) / 256, 256>>>(eidx, W_in, W1, W2, W_skip);
  cudaEventRecord(evz, 0);

  // CSR build on s2, parallel with GEMM1+GEMM2
  cudaStreamWaitEvent(s2, evz, 0);
  k_edges<<<(NE + 255) / 256, 256, 0, s2>>>(eidx);
  k_scan<<<NB, 1024, 0, s2>>>();
  k_scatter<<<(NE + 255) / 256, 256, 0, s2>>>();
  cudaEventRecord(evcsr, s2);

  // GEMM1: h1 = leaky(x@W_in+b_in), stats1 fused
  k_gemm_tc<KIN, M_BIAS | M_LEAKY | M_CVT | M_ST1, 0>
      <<<GB2, 256, GEMM_SMEM>>>(b_in, nullptr, nullptr, nullptr, nullptr, x);
  // GEMM2: t1 = BN1(h1)@W1 (BN folded in), att1 fused
  k_gemm_tc<128, M_BNA | M_ATT8, 1>
      <<<GB2, 256, GEMM_SMEM>>>(nullptr, att_src1, att_dst1, gamma1, beta1, nullptr);

  // gat1 needs CSR + GEMM2
  cudaStreamWaitEvent(0, evcsr, 0);
  k_gat<8, true, true><<<AB, 256>>>(bias1);
  cudaEventRecord(evskip, 0);

  // GEMM4': g_t1 = skip@W_skip + b_skip  (parallel with GEMM3+gat2)
  cudaStreamWaitEvent(s3, evskip, 0);
  k_gemm_tc<128, M_BIAS, 3>
      <<<GB2, 256, GEMM_SMEM, s3>>>(b_skip, nullptr, nullptr, nullptr, nullptr, nullptr);
  cudaEventRecord(evg4, s3);

  // GEMM3: t2 = skip@W2, att2 fused
  k_gemm_tc<128, M_ATT1, 2>
      <<<GB2, 256, GEMM_SMEM>>>(nullptr, att_src2, att_dst2, nullptr, nullptr, nullptr);
  k_gat<1, false, false><<<AB, 256>>>(bias2);

  // merge + BN2 + final
  cudaStreamWaitEvent(0, evg4, 0);
  k_merge<<<(NN + 127) / 128, 256>>>(out);
  k_bnfin2<<<1, 128>>>(gamma2, beta2);
  k_final<<<(NN + 1) / 2, 256>>>(out);
}

// round 17
// speedup vs baseline: 1.2581x; 1.0595x over previous
#include <cuda_runtime.h>

namespace {

constexpr int NN  = 50000;   // nodes
constexpr int NE  = 800000;  // edges
constexpr int KIN = 256;     // in_dim
constexpr int NB  = (NN + 1023) / 1024;  // scan blocks = 49

// ---------------- scratch (static device memory; no allocations) ----------------
__device__ float g_win[256 * 128];   // tf32-rounded W_in
__device__ float g_w1r[128 * 128];   // tf32-rounded W1
__device__ float g_w2[128 * 128];    // tf32-rounded W2
__device__ float g_wskip[128 * 128]; // tf32-rounded W_skip
__device__ float g_h1[NN * 128];     // leaky(x@W_in+b_in), tf32-rounded
__device__ float g_t1[NN * 128];     // BN1(h1)@W1; later reused as skip@W_skip+b_skip
__device__ float g_skip[NN * 128];   // leaky(gat1 + bias1), tf32-rounded
__device__ float g_t2[NN * 128];     // skip @ W2
__device__ float g_out2[NN * 128];   // gat2 + bias2
__device__ float g_as1[NN * 8];
__device__ float g_ad1[NN * 8];
__device__ float g_as2[NN];
__device__ float g_ad2[NN];
__device__ int   g_src[NE];
__device__ int   g_dst[NE];
__device__ int   g_sby[NE];          // src ids sorted by dst (CSR order)
__device__ int   g_deg[NN];
__device__ int   g_cur[NN];
__device__ int   g_rs[NN + 1];       // CSR row starts (disjoint regions)
__device__ int   g_ctr;
__device__ float g_stats1[256];
__device__ float g_stats2[256];
__device__ float g_sc2[128], g_sh2[128];
__device__ int   g_is64;

__device__ __forceinline__ float lrelu(float v) { return v >= 0.f ? v : 0.2f * v; }

__device__ __forceinline__ float tf32r(float f) {
  unsigned u;
  asm("cvt.rna.tf32.f32 %0, %1;" : "=r"(u) : "f"(f));
  return __uint_as_float(u);
}
__device__ __forceinline__ float4 tf32r4(float4 v) {
  return make_float4(tf32r(v.x), tf32r(v.y), tf32r(v.z), tf32r(v.w));
}

// ---------------- init: zero + dtype detect + round all weights ----------------
__global__ void k_zerow(const void* __restrict__ ei,
                        const float* __restrict__ Win, const float* __restrict__ W1,
                        const float* __restrict__ W2,  const float* __restrict__ Wsk) {
  int i = blockIdx.x * 256 + threadIdx.x;
  if (i < NN) { g_deg[i] = 0; g_cur[i] = 0; g_as2[i] = 0.f; g_ad2[i] = 0.f; }
  if (i < 256) { g_stats1[i] = 0.f; g_stats2[i] = 0.f; }
  if (i < 8192)
    *(float4*)(g_win + i * 4) = tf32r4(*(const float4*)(Win + i * 4));
  if (i < 4096) {
    *(float4*)(g_w1r + i * 4)   = tf32r4(*(const float4*)(W1 + i * 4));
    *(float4*)(g_w2 + i * 4)    = tf32r4(*(const float4*)(W2 + i * 4));
    *(float4*)(g_wskip + i * 4) = tf32r4(*(const float4*)(Wsk + i * 4));
  }
  if (blockIdx.x == 0 && threadIdx.x == 0) {
    g_ctr = 0;
    const long long* p = (const long long*)ei;
    int ok = 1;
    for (int j = 0; j < 64; j++) {
      long long v = p[j];
      if (v < 0 || v >= NN) { ok = 0; break; }
    }
    g_is64 = ok;
  }
}

__global__ void k_edges(const void* __restrict__ ei) {
  int i = blockIdx.x * 256 + threadIdx.x;
  if (i < NE) {
    int s, d;
    if (g_is64) {
      const long long* p = (const long long*)ei;
      s = (int)p[i];
      d = (int)p[NE + i];
    } else {
      const int* p = (const int*)ei;
      s = p[i];
      d = p[NE + i];
    }
    if ((unsigned)s >= NN) s = 0;
    if ((unsigned)d >= NN) d = 0;
    g_src[i] = s;
    g_dst[i] = d;
    atomicAdd(&g_deg[d], 1);
  }
}

__global__ void k_scan() {
  int t = threadIdx.x;
  int i = blockIdx.x * 1024 + t;
  int v = (i < NN) ? g_deg[i] : 0;
  __shared__ int sb[1024];
  __shared__ int sbase;
  sb[t] = v;
  __syncthreads();
  for (int o = 1; o < 1024; o <<= 1) {
    int x = (t >= o) ? sb[t - o] : 0;
    __syncthreads();
    sb[t] += x;
    __syncthreads();
  }
  if (t == 1023) sbase = atomicAdd(&g_ctr, sb[1023]);
  __syncthreads();
  if (i < NN) g_rs[i] = sbase + sb[t] - v;
}

__global__ void k_scatter() {
  int i = blockIdx.x * 256 + threadIdx.x;
  if (i < NE) {
    int d = g_dst[i];
    int p = atomicAdd(&g_cur[d], 1);
    g_sby[g_rs[d] + p] = g_src[i];
  }
}

// ---------------- TF32 tensor-core GEMM: block 128x64, BK=16, 3-stage pipeline ----------------
constexpr int M_LEAKY = 2, M_BIAS = 16, M_CVT = 32, M_BNA = 64;
constexpr int M_ST1 = 128, M_ATT8 = 512, M_ATT1 = 1024;
constexpr int ASZ = 128 * 20;             // A stage: 128 rows x 16 k (pad 20)
constexpr int WSZ = 16 * 72;              // W stage: 16 k x 64 n (pad 72)
constexpr int TSZ = ASZ + WSZ;            // 3712 floats per stage
constexpr int NSTG = 3;
constexpr int GEMM_SMEM = TSZ * NSTG * 4; // 44544 B

__device__ __forceinline__ void mma_tf32(float4& c, const unsigned a[4], const unsigned b[2]) {
  asm volatile(
      "mma.sync.aligned.m16n8k8.row.col.f32.tf32.tf32.f32 "
      "{%0,%1,%2,%3}, {%4,%5,%6,%7}, {%8,%9}, {%0,%1,%2,%3};"
      : "+f"(c.x), "+f"(c.y), "+f"(c.z), "+f"(c.w)
      : "r"(a[0]), "r"(a[1]), "r"(a[2]), "r"(a[3]), "r"(b[0]), "r"(b[1]));
}

// SEL: 0 -> A=Araw (x, K=256, cvt at frag read), W=g_win,  out=g_h1
//      1 -> A=g_h1 (BN affine at frag read),     W=g_w1r,  out=g_t1
//      2 -> A=g_skip,                            W=g_w2,   out=g_t2
//      3 -> A=g_skip,                            W=g_wskip,out=g_t1 (skip@W_skip+b_skip)
template <int K, int MODE, int SEL>
__global__ __launch_bounds__(256, 4) void k_gemm_tc(const float* __restrict__ bias,
                                                    const float* __restrict__ atts,
                                                    const float* __restrict__ attd,
                                                    const float* __restrict__ gam,
                                                    const float* __restrict__ bet,
                                                    const float* __restrict__ Araw) {
  extern __shared__ float sm[];
  __shared__ float satt[256];
  __shared__ float sstat[256];
  __shared__ float sbn[256];     // [0:128) sc1, [128:256) sh1

  const float* A  = (SEL == 0) ? Araw : (SEL == 1) ? g_h1 : g_skip;
  const float* Wm = (SEL == 0) ? g_win : (SEL == 1) ? g_w1r : (SEL == 2) ? g_w2 : g_wskip;
  float* out      = (SEL == 0) ? g_h1 : (SEL == 1) ? g_t1 : (SEL == 2) ? g_t2 : g_t1;

  int tid = threadIdx.x;
  int lane = tid & 31, wid = tid >> 5;
  int gr = lane >> 2, gc = lane & 3;
  int warp_m = wid & 3, warp_n = wid >> 2;   // 4 m-warps x 2 n-warps
  int row0 = (blockIdx.x >> 1) * 128;
  int ncol0 = (blockIdx.x & 1) * 64;

  if (MODE & (M_ATT8 | M_ATT1)) {
    if (tid < 128) { satt[tid] = __ldg(atts + tid); satt[128 + tid] = __ldg(attd + tid); }
  }
  if (MODE & M_ST1) sstat[tid] = 0.f;
  if (MODE & M_BNA) {
    if (tid < 128) {
      float mean = g_stats1[tid] * (1.f / NN);
      float var = g_stats1[128 + tid] * (1.f / NN) - mean * mean;
      float sc = rsqrtf(var + 1e-5f) * __ldg(gam + tid);
      sbn[tid] = sc;
      sbn[128 + tid] = __ldg(bet + tid) - mean * sc;
    }
  }

  float4 acc[2][4];
#pragma unroll
  for (int mt = 0; mt < 2; mt++)
#pragma unroll
    for (int nt = 0; nt < 4; nt++) acc[mt][nt] = make_float4(0.f, 0.f, 0.f, 0.f);

  auto issue = [&](int kc, int buf) {
    float* As = sm + buf * TSZ;
    float* Ws = As + ASZ;
#pragma unroll
    for (int i = 0; i < 2; i++) {
      int fidx = i * 256 + tid;              // 0..511 float4s
      int r = fidx >> 2, c4 = fidx & 3;
      int grow = row0 + r;
      int ok = (grow < NN);
      const float* src = A + (size_t)(ok ? grow : 0) * K + kc + c4 * 4;
      unsigned dst = (unsigned)__cvta_generic_to_shared(As + r * 20 + c4 * 4);
      int sz = ok ? 16 : 0;
      asm volatile("cp.async.cg.shared.global [%0], [%1], 16, %2;"
                   :: "r"(dst), "l"(src), "r"(sz));
    }
    {
      int k = tid >> 4, n4 = tid & 15;       // 256 float4s = 16k x 64n
      const float* src = Wm + (size_t)(kc + k) * 128 + ncol0 + n4 * 4;
      unsigned dst = (unsigned)__cvta_generic_to_shared(Ws + k * 72 + n4 * 4);
      asm volatile("cp.async.cg.shared.global [%0], [%1], 16;" :: "r"(dst), "l"(src));
    }
    asm volatile("cp.async.commit_group;");
  };

  constexpr int NCH = K / 16;
  issue(0, 0);
  issue(16, 1);

  for (int ch = 0; ch < NCH; ch++) {
    if (ch < NCH - 1) asm volatile("cp.async.wait_group 1;" ::: "memory");
    else              asm volatile("cp.async.wait_group 0;" ::: "memory");
    __syncthreads();
    if (ch + 2 < NCH) issue((ch + 2) * 16, (ch + 2) % NSTG);

    const float* As = sm + (ch % NSTG) * TSZ;
    const float* Ws = As + ASZ;
    int kb = ch * 16;
#pragma unroll
    for (int kk = 0; kk < 16; kk += 8) {
      unsigned a[2][4];
      if (MODE & M_BNA) {
        float sc0 = sbn[kb + kk + gc],       sh0 = sbn[128 + kb + kk + gc];
        float sc1 = sbn[kb + kk + gc + 4],   sh1 = sbn[128 + kb + kk + gc + 4];
#pragma unroll
        for (int mt = 0; mt < 2; mt++) {
          int rb = warp_m * 32 + mt * 16;
          a[mt][0] = __float_as_uint(tf32r(fmaf(As[(rb + gr)     * 20 + kk + gc], sc0, sh0)));
          a[mt][1] = __float_as_uint(tf32r(fmaf(As[(rb + gr + 8) * 20 + kk + gc], sc0, sh0)));
          a[mt][2] = __float_as_uint(tf32r(fmaf(As[(rb + gr)     * 20 + kk + gc + 4], sc1, sh1)));
          a[mt][3] = __float_as_uint(tf32r(fmaf(As[(rb + gr + 8) * 20 + kk + gc + 4], sc1, sh1)));
        }
      } else {
#pragma unroll
        for (int mt = 0; mt < 2; mt++) {
          int rb = warp_m * 32 + mt * 16;
          if (SEL == 0) {
            a[mt][0] = __float_as_uint(tf32r(As[(rb + gr)     * 20 + kk + gc]));
            a[mt][1] = __float_as_uint(tf32r(As[(rb + gr + 8) * 20 + kk + gc]));
            a[mt][2] = __float_as_uint(tf32r(As[(rb + gr)     * 20 + kk + gc + 4]));
            a[mt][3] = __float_as_uint(tf32r(As[(rb + gr + 8) * 20 + kk + gc + 4]));
          } else {
            a[mt][0] = __float_as_uint(As[(rb + gr)     * 20 + kk + gc]);
            a[mt][1] = __float_as_uint(As[(rb + gr + 8) * 20 + kk + gc]);
            a[mt][2] = __float_as_uint(As[(rb + gr)     * 20 + kk + gc + 4]);
            a[mt][3] = __float_as_uint(As[(rb + gr + 8) * 20 + kk + gc + 4]);
          }
        }
      }
      unsigned b[4][2];
#pragma unroll
      for (int nt = 0; nt < 4; nt++) {
        int n = warp_n * 32 + nt * 8 + gr;
        b[nt][0] = __float_as_uint(Ws[(kk + gc)     * 72 + n]);
        b[nt][1] = __float_as_uint(Ws[(kk + gc + 4) * 72 + n]);
      }
#pragma unroll
      for (int mt = 0; mt < 2; mt++)
#pragma unroll
        for (int nt = 0; nt < 4; nt++) mma_tf32(acc[mt][nt], a[mt], b[nt]);
    }
  }

  __syncthreads();

  // ---------------- fused epilogue ----------------
  float pa_s[2][2] = {{0.f, 0.f}, {0.f, 0.f}};
  float pa_d[2][2] = {{0.f, 0.f}, {0.f, 0.f}};

#pragma unroll
  for (int nt = 0; nt < 4; nt++) {
    int col = ncol0 + warp_n * 32 + nt * 8 + gc * 2;   // global col in [0,128)
    float2 bv = make_float2(0.f, 0.f);
    if (MODE & M_BIAS) bv = *(const float2*)(bias + col);
    float2 av_s = make_float2(0.f, 0.f), av_d = make_float2(0.f, 0.f);
    if (MODE & (M_ATT8 | M_ATT1)) {
      av_s = *(const float2*)&satt[col];
      av_d = *(const float2*)&satt[128 + col];
    }
    float2 csum = make_float2(0.f, 0.f), csq = make_float2(0.f, 0.f);

#pragma unroll
    for (int mt = 0; mt < 2; mt++) {
#pragma unroll
      for (int hh = 0; hh < 2; hh++) {
        int r = row0 + warp_m * 32 + mt * 16 + gr + hh * 8;
        if (r < NN) {
          float2 v = hh ? make_float2(acc[mt][nt].z, acc[mt][nt].w)
                        : make_float2(acc[mt][nt].x, acc[mt][nt].y);
          if (MODE & M_BIAS) { v.x += bv.x; v.y += bv.y; }
          if (MODE & M_LEAKY) { v.x = lrelu(v.x); v.y = lrelu(v.y); }
          if (MODE & M_CVT)   { v.x = tf32r(v.x); v.y = tf32r(v.y); }
          *(float2*)(out + (size_t)r * 128 + col) = v;
          if (MODE & M_ST1) {
            csum.x += v.x; csum.y += v.y;
            csq.x += v.x * v.x; csq.y += v.y * v.y;
          }
          if (MODE & (M_ATT8 | M_ATT1)) {
            pa_s[mt][hh] = fmaf(v.x, av_s.x, fmaf(v.y, av_s.y, pa_s[mt][hh]));
            pa_d[mt][hh] = fmaf(v.x, av_d.x, fmaf(v.y, av_d.y, pa_d[mt][hh]));
          }
        }
      }
    }

    if (MODE & M_ST1) {
      atomicAdd(&sstat[col], csum.x);
      atomicAdd(&sstat[col + 1], csum.y);
      atomicAdd(&sstat[128 + col], csq.x);
      atomicAdd(&sstat[128 + col + 1], csq.y);
    }

    if ((MODE & M_ATT8) && (nt & 1)) {
      int head = (ncol0 >> 4) + warp_n * 2 + (nt >> 1);
#pragma unroll
      for (int mt = 0; mt < 2; mt++) {
#pragma unroll
        for (int hh = 0; hh < 2; hh++) {
          float ps = pa_s[mt][hh], pd = pa_d[mt][hh];
          ps += __shfl_xor_sync(0xffffffffu, ps, 1);
          ps += __shfl_xor_sync(0xffffffffu, ps, 2);
          pd += __shfl_xor_sync(0xffffffffu, pd, 1);
          pd += __shfl_xor_sync(0xffffffffu, pd, 2);
          int r = row0 + warp_m * 32 + mt * 16 + gr + hh * 8;
          if (gc == 0 && r < NN) {
            g_as1[(size_t)r * 8 + head] = ps;
            g_ad1[(size_t)r * 8 + head] = pd;
          }
          pa_s[mt][hh] = 0.f;
          pa_d[mt][hh] = 0.f;
        }
      }
    }
  }

  if (MODE & M_ATT1) {
#pragma unroll
    for (int mt = 0; mt < 2; mt++) {
#pragma unroll
      for (int hh = 0; hh < 2; hh++) {
        float ps = pa_s[mt][hh], pd = pa_d[mt][hh];
        ps += __shfl_xor_sync(0xffffffffu, ps, 1);
        ps += __shfl_xor_sync(0xffffffffu, ps, 2);
        pd += __shfl_xor_sync(0xffffffffu, pd, 1);
        pd += __shfl_xor_sync(0xffffffffu, pd, 2);
        int r = row0 + warp_m * 32 + mt * 16 + gr + hh * 8;
        if (gc == 0 && r < NN) {
          atomicAdd(&g_as2[r], ps);
          atomicAdd(&g_ad2[r], pd);
        }
      }
    }
  }

  if (MODE & M_ST1) {
    __syncthreads();
    atomicAdd(&g_stats1[tid], sstat[tid]);
  }
}

// ---------------- merge: out = g_t1(skip@W_skip+b) + g_out2, BN2 stats ----------------
__global__ __launch_bounds__(256) void k_merge(float* __restrict__ out) {
  int col = threadIdx.x & 127;
  int half = threadIdx.x >> 7;
  float s = 0.f, q = 0.f;
  for (int i = 0; i < 64; i++) {
    int r = blockIdx.x * 128 + i * 2 + half;
    if (r < NN) {
      float v = g_t1[(size_t)r * 128 + col] + g_out2[(size_t)r * 128 + col];
      out[(size_t)r * 128 + col] = v;
      s += v;
      q += v * v;
    }
  }
  __shared__ float red[512];
  red[threadIdx.x] = s;
  red[256 + threadIdx.x] = q;
  __syncthreads();
  if (threadIdx.x < 128) {
    atomicAdd(&g_stats2[threadIdx.x], red[threadIdx.x] + red[threadIdx.x + 128]);
    atomicAdd(&g_stats2[128 + threadIdx.x], red[256 + threadIdx.x] + red[384 + threadIdx.x]);
  }
}

// ---------------- BN2 finalize ----------------
__global__ void k_bnfin2(const float* __restrict__ gamma, const float* __restrict__ beta) {
  int i = threadIdx.x;
  float mean = g_stats2[i] * (1.f / NN);
  float var = g_stats2[128 + i] * (1.f / NN) - mean * mean;
  float sc = rsqrtf(var + 1e-5f) * gamma[i];
  g_sc2[i] = sc;
  g_sh2[i] = beta[i] - mean * sc;
}

template <int H>
__device__ __forceinline__ void load_as(float* dst, const float* __restrict__ p, int s) {
  if constexpr (H == 8) {
    float4 a = __ldg((const float4*)(p + (size_t)s * 8));
    float4 b = __ldg((const float4*)(p + (size_t)s * 8 + 4));
    dst[0] = a.x; dst[1] = a.y; dst[2] = a.z; dst[3] = a.w;
    dst[4] = b.x; dst[5] = b.y; dst[6] = b.z; dst[7] = b.w;
  } else {
    dst[0] = __ldg(p + s);
  }
}

// ---------------- GAT aggregation: WARP per node, plain softmax (no max-shift) ----------------
// Logits are bounded (~±6 by construction), so exp() is safe without max subtraction.
// Denominator accumulated as per-lane partials; ONE butterfly allreduce per node at the end.
template <int H, bool LK, bool CVT>
__global__ __launch_bounds__(256) void k_gat(const float* __restrict__ bias) {
  const float* t   = (H == 8) ? g_t1  : g_t2;
  const float* asv = (H == 8) ? g_as1 : g_as2;
  const float* adv = (H == 8) ? g_ad1 : g_ad2;
  float* out       = (H == 8) ? g_skip : g_out2;

  int lane = threadIdx.x & 31, warp = threadIdx.x >> 5;
  int node = blockIdx.x * 8 + warp;
  if (node >= NN) return;
  int beg = g_rs[node];
  int cnt = g_deg[node];
  int myh = (H == 8) ? (lane >> 2) : 0;

  __shared__ float salpha[8][H * 33];

  float ad[H];
  load_as<H>(ad, adv, node);

  float denp[H];
#pragma unroll
  for (int h = 0; h < H; h++) denp[h] = 0.f;
  float4 acc = make_float4(0.f, 0.f, 0.f, 0.f);

  for (int base = 0; base < cnt; base += 32) {
    int c = min(32, cnt - base);

    int s = 0;
    float a_[H];
    if (lane < c) {
      s = __ldg(&g_sby[beg + base + lane]);
      float av[H];
      load_as<H>(av, asv, s);
#pragma unroll
      for (int h = 0; h < H; h++) {
        a_[h] = __expf(lrelu(av[h] + ad[h]));
        denp[h] += a_[h];
      }
    } else {
#pragma unroll
      for (int h = 0; h < H; h++) a_[h] = 0.f;
    }
#pragma unroll
    for (int h = 0; h < H; h++) salpha[warp][h * 33 + lane] = a_[h];
    __syncwarp();

    // weighted gather: per edge, one coalesced 128B row read
    const float* sa = &salpha[warp][myh * 33];
#pragma unroll 4
    for (int j = 0; j < c; j++) {
      int sj = __shfl_sync(0xffffffffu, s, j);
      float w = sa[j];
      float4 tv = __ldg((const float4*)(t + (size_t)sj * 128 + lane * 4));
      acc.x = fmaf(w, tv.x, acc.x);
      acc.y = fmaf(w, tv.y, acc.y);
      acc.z = fmaf(w, tv.z, acc.z);
      acc.w = fmaf(w, tv.w, acc.w);
    }
    __syncwarp();
  }

  // single denominator allreduce per node
#pragma unroll
  for (int h = 0; h < H; h++) {
#pragma unroll
    for (int o = 16; o; o >>= 1) denp[h] += __shfl_xor_sync(0xffffffffu, denp[h], o);
  }

  float inv = 1.f / fmaxf(denp[myh], 1e-16f);
  float4 bv = *(const float4*)(bias + lane * 4);
  float4 v;
  v.x = acc.x * inv + bv.x;
  v.y = acc.y * inv + bv.y;
  v.z = acc.z * inv + bv.z;
  v.w = acc.w * inv + bv.w;
  if (LK) { v.x = lrelu(v.x); v.y = lrelu(v.y); v.z = lrelu(v.z); v.w = lrelu(v.w); }
  if (CVT) v = tf32r4(v);
  *(float4*)(out + (size_t)node * 128 + lane * 4) = v;
}

// ---------------- final: BN2 affine + L2 row normalize (2 nodes/block) ----------------
__global__ __launch_bounds__(256) void k_final(float* __restrict__ out) {
  int node = blockIdx.x * 2 + (threadIdx.x >> 7);
  int tid = threadIdx.x & 127;
  if (node >= NN) return;
  float v = out[(size_t)node * 128 + tid] * g_sc2[tid] + g_sh2[tid];
  float q = v * v;
#pragma unroll
  for (int o = 16; o; o >>= 1) q += __shfl_xor_sync(0xffffffffu, q, o);
  __shared__ float sq[2][4];
  int half = threadIdx.x >> 7;
  if ((tid & 31) == 0) sq[half][tid >> 5] = q;
  __syncthreads();
  float tot = sq[half][0] + sq[half][1] + sq[half][2] + sq[half][3];
  float r = 1.f / fmaxf(sqrtf(tot), 1e-12f);
  out[(size_t)node * 128 + tid] = v * r;
}

}  // namespace

extern "C" void kernel_launch(void* const* d_in, const int* in_sizes, int n_in,
                              void* d_out, int out_size) {
  const float* x        = (const float*)d_in[0];
  const float* W_in     = (const float*)d_in[1];
  const float* b_in     = (const float*)d_in[2];
  const float* gamma1   = (const float*)d_in[3];
  const float* beta1    = (const float*)d_in[4];
  const float* W1       = (const float*)d_in[5];
  const float* att_src1 = (const float*)d_in[6];
  const float* att_dst1 = (const float*)d_in[7];
  const float* bias1    = (const float*)d_in[8];
  const float* W2       = (const float*)d_in[9];
  const float* att_src2 = (const float*)d_in[10];
  const float* att_dst2 = (const float*)d_in[11];
  const float* bias2    = (const float*)d_in[12];
  const float* W_skip   = (const float*)d_in[13];
  const float* b_skip   = (const float*)d_in[14];
  const float* gamma2   = (const float*)d_in[15];
  const float* beta2    = (const float*)d_in[16];
  const void*  eidx     = d_in[17];
  float* out = (float*)d_out;

  static bool s_init = false;
  static cudaStream_t s2, s3;
  static cudaEvent_t evz, evcsr, evskip, evg4;
  if (!s_init) {
    cudaStreamCreateWithFlags(&s2, cudaStreamNonBlocking);
    cudaStreamCreateWithFlags(&s3, cudaStreamNonBlocking);
    cudaEventCreateWithFlags(&evz, cudaEventDisableTiming);
    cudaEventCreateWithFlags(&evcsr, cudaEventDisableTiming);
    cudaEventCreateWithFlags(&evskip, cudaEventDisableTiming);
    cudaEventCreateWithFlags(&evg4, cudaEventDisableTiming);
    cudaFuncSetAttribute(k_gemm_tc<KIN, M_BIAS | M_LEAKY | M_CVT | M_ST1, 0>,
                         cudaFuncAttributeMaxDynamicSharedMemorySize, GEMM_SMEM);
    cudaFuncSetAttribute(k_gemm_tc<128, M_BNA | M_ATT8, 1>,
                         cudaFuncAttributeMaxDynamicSharedMemorySize, GEMM_SMEM);
    cudaFuncSetAttribute(k_gemm_tc<128, M_ATT1, 2>,
                         cudaFuncAttributeMaxDynamicSharedMemorySize, GEMM_SMEM);
    cudaFuncSetAttribute(k_gemm_tc<128, M_BIAS, 3>,
                         cudaFuncAttributeMaxDynamicSharedMemorySize, GEMM_SMEM);
    s_init = true;
  }

  const int GB2 = ((NN + 127) / 128) * 2;  // 782 (128-row x 64-col tiles)
  const int AB = (NN + 7) / 8;             // 6250

  // init (zero + weight rounding + dtype detect) on main stream
  k_zerow<<<(NN + 255) / 256, 256>>>(eidx, W_in, W1, W2, W_skip);
  cudaEventRecord(evz, 0);

  // CSR build on s2, parallel with GEMM1+GEMM2
  cudaStreamWaitEvent(s2, evz, 0);
  k_edges<<<(NE + 255) / 256, 256, 0, s2>>>(eidx);
  k_scan<<<NB, 1024, 0, s2>>>();
  k_scatter<<<(NE + 255) / 256, 256, 0, s2>>>();
  cudaEventRecord(evcsr, s2);

  // GEMM1: h1 = leaky(x@W_in+b_in), stats1 fused
  k_gemm_tc<KIN, M_BIAS | M_LEAKY | M_CVT | M_ST1, 0>
      <<<GB2, 256, GEMM_SMEM>>>(b_in, nullptr, nullptr, nullptr, nullptr, x);
  // GEMM2: t1 = BN1(h1)@W1 (BN folded in), att1 fused
  k_gemm_tc<128, M_BNA | M_ATT8, 1>
      <<<GB2, 256, GEMM_SMEM>>>(nullptr, att_src1, att_dst1, gamma1, beta1, nullptr);

  // gat1 needs CSR + GEMM2
  cudaStreamWaitEvent(0, evcsr, 0);
  k_gat<8, true, true><<<AB, 256>>>(bias1);
  cudaEventRecord(evskip, 0);

  // GEMM4': g_t1 = skip@W_skip + b_skip  (parallel with GEMM3+gat2)
  cudaStreamWaitEvent(s3, evskip, 0);
  k_gemm_tc<128, M_BIAS, 3>
      <<<GB2, 256, GEMM_SMEM, s3>>>(b_skip, nullptr, nullptr, nullptr, nullptr, nullptr);
  cudaEventRecord(evg4, s3);

  // GEMM3: t2 = skip@W2, att2 fused
  k_gemm_tc<128, M_ATT1, 2>
      <<<GB2, 256, GEMM_SMEM>>>(nullptr, att_src2, att_dst2, nullptr, nullptr, nullptr);
  k_gat<1, false, false><<<AB, 256>>>(bias2);

  // merge + BN2 + final
  cudaStreamWaitEvent(0, evg4, 0);
  k_merge<<<(NN + 127) / 128, 256>>>(out);
  k_bnfin2<<<1, 128>>>(gamma2, beta2);
  k_final<<<(NN + 1) / 2, 256>>>(out);
}